// round 10
// baseline (speedup 1.0000x reference)
#include <cuda_runtime.h>
#include <cuda_bf16.h>
#include <cstdint>

// Problem constants: B=8, H=64, W=64, C=256, NUM_HEADS=8, KEY_DIM=32
#define M_TOT   32768
#define C_DIM   256
#define ELEMS   (M_TOT * C_DIM)   // 8388608

// ---------------- scratch (device globals; no allocation allowed) ----------
__device__ __align__(16) float g_v[ELEMS];      // v fp32 NHWC (LePE input)
__device__ __align__(16) float g_lepe[ELEMS];   // LePE output NHWC

// W-layout = [b][n][h][w][d]; H-layout = [b][n][w][h][d]
__device__ __align__(16) __nv_bfloat16 g_qwh[ELEMS];
__device__ __align__(16) __nv_bfloat16 g_qwl[ELEMS];
__device__ __align__(16) __nv_bfloat16 g_qhh[ELEMS];
__device__ __align__(16) __nv_bfloat16 g_qhl[ELEMS];
__device__ __align__(16) __nv_bfloat16 g_kwh[ELEMS];
__device__ __align__(16) __nv_bfloat16 g_kwl[ELEMS];
__device__ __align__(16) __nv_bfloat16 g_khh[ELEMS];
__device__ __align__(16) __nv_bfloat16 g_khl[ELEMS];
__device__ __align__(16) __nv_bfloat16 g_vwh[ELEMS];
__device__ __align__(16) __nv_bfloat16 g_vwl[ELEMS];
__device__ __align__(16) __nv_bfloat16 g_v1h[ELEMS];   // v1 H-layout hi
__device__ __align__(16) __nv_bfloat16 g_v1l[ELEMS];   // v1 H-layout lo
__device__ __align__(16) __nv_bfloat16 g_ahi[ELEMS];   // row-major (GEMM A)
__device__ __align__(16) __nv_bfloat16 g_alo[ELEMS];
__device__ __align__(16) __nv_bfloat16 g_whi[4 * 65536];
__device__ __align__(16) __nv_bfloat16 g_wlo[4 * 65536];

// ---------------- helpers ---------------------------------------------------
__device__ __forceinline__ uint32_t smem_u32(const void* p) {
    uint32_t a;
    asm("{ .reg .u64 t; cvta.to.shared.u64 t, %1; cvt.u32.u64 %0, t; }"
        : "=r"(a) : "l"(p));
    return a;
}

__device__ __forceinline__ void mma16816(float* c, const uint32_t* a,
                                         uint32_t b0, uint32_t b1)
{
    asm volatile(
        "mma.sync.aligned.m16n8k16.row.col.f32.bf16.bf16.f32 "
        "{%0,%1,%2,%3}, {%4,%5,%6,%7}, {%8,%9}, {%0,%1,%2,%3};"
        : "+f"(c[0]), "+f"(c[1]), "+f"(c[2]), "+f"(c[3])
        : "r"(a[0]), "r"(a[1]), "r"(a[2]), "r"(a[3]), "r"(b0), "r"(b1));
}

__device__ __forceinline__ void ldm_x4(uint32_t* r, uint32_t addr) {
    asm volatile("ldmatrix.sync.aligned.m8n8.x4.shared.b16 {%0,%1,%2,%3}, [%4];"
        : "=r"(r[0]), "=r"(r[1]), "=r"(r[2]), "=r"(r[3]) : "r"(addr));
}

__device__ __forceinline__ void ldm_x2t(uint32_t* r, uint32_t addr) {
    asm volatile("ldmatrix.sync.aligned.m8n8.x2.trans.shared.b16 {%0,%1}, [%2];"
        : "=r"(r[0]), "=r"(r[1]) : "r"(addr));
}

__device__ __forceinline__ uint32_t packsplit(float x0, float x1, uint32_t& lo) {
    __nv_bfloat16 h0 = __float2bfloat16(x0), h1 = __float2bfloat16(x1);
    float r0 = x0 - __bfloat162float(h0);
    float r1 = x1 - __bfloat162float(h1);
    __nv_bfloat16 l0 = __float2bfloat16(r0), l1 = __float2bfloat16(r1);
    lo = (uint32_t)__bfloat16_as_ushort(l0) |
         ((uint32_t)__bfloat16_as_ushort(l1) << 16);
    return (uint32_t)__bfloat16_as_ushort(h0) |
           ((uint32_t)__bfloat16_as_ushort(h1) << 16);
}

// ---------------------------------------------------------------------------
// Merged split kernel: blocks [0, 8192) split x; blocks [8192, 8448) split W.
// ---------------------------------------------------------------------------
__global__ __launch_bounds__(256)
void split_all(const float* __restrict__ x,
               const float* __restrict__ W0, const float* __restrict__ W1,
               const float* __restrict__ W2, const float* __restrict__ W3,
               __nv_bfloat16* __restrict__ xhi, __nv_bfloat16* __restrict__ xlo,
               __nv_bfloat16* __restrict__ whi, __nv_bfloat16* __restrict__ wlo)
{
    if (blockIdx.x < 8192) {
        const int i = blockIdx.x * 256 + threadIdx.x;
        float4 v = ((const float4*)x)[i];
        uint32_t l0, l1;
        uint32_t h0 = packsplit(v.x, v.y, l0);
        uint32_t h1 = packsplit(v.z, v.w, l1);
        ((uint2*)xhi)[i] = make_uint2(h0, h1);
        ((uint2*)xlo)[i] = make_uint2(l0, l1);
    } else {
        const int wblk = blockIdx.x - 8192;
        const int w = wblk >> 6;
        const float* W = (w == 0) ? W0 : (w == 1) ? W1 : (w == 2) ? W2 : W3;
        const int i = (wblk & 63) * 256 + threadIdx.x;
        float4 v = ((const float4*)W)[i];
        uint32_t l0, l1;
        uint32_t h0 = packsplit(v.x, v.y, l0);
        uint32_t h1 = packsplit(v.z, v.w, l1);
        ((uint2*)whi)[w * 16384 + i] = make_uint2(h0, h1);
        ((uint2*)wlo)[w * 16384 + i] = make_uint2(l0, l1);
    }
}

// ---------------------------------------------------------------------------
// Shared HMMA GEMM mainloop: 128x256 CTA tile, 512 thr (16 warps 4m x 4n),
// warp tile 32x64, fp32 emulation (3 products), cp.async 2-stage.
// ---------------------------------------------------------------------------
#define A_TILE_B  10240
#define B_TILE_B  20480
#define STAGE_B   (2 * A_TILE_B + 2 * B_TILE_B)
#define GEMM_SMEM (2 * STAGE_B)

__device__ __forceinline__
void gemm_main(float acc[2][8][4],
               const __nv_bfloat16* __restrict__ Ahi,
               const __nv_bfloat16* __restrict__ Alo,
               const __nv_bfloat16* __restrict__ Bhi,
               const __nv_bfloat16* __restrict__ Blo,
               int m0, uint32_t smem_base)
{
    const int tid  = threadIdx.x;
    const int lane = tid & 31;
    const int warp = tid >> 5;
    const int wm   = warp >> 2;
    const int wn   = warp & 3;

    const uint4* gAh = (const uint4*)Ahi + (size_t)m0 * 32;
    const uint4* gAl = (const uint4*)Alo + (size_t)m0 * 32;
    const uint4* gBh = (const uint4*)Bhi;
    const uint4* gBl = (const uint4*)Blo;

    auto issue = [&](int chunk, int stg) {
        const int kq4 = chunk * 4;
        const uint32_t sb = smem_base + stg * STAGE_B;
        {
            const int r = tid >> 2, q = tid & 3;
            const uint32_t off = (uint32_t)(r * 80 + q * 16);
            asm volatile("cp.async.ca.shared.global [%0], [%1], 16;"
                         :: "r"(sb + off),
                            "l"(gAh + (size_t)r * 32 + kq4 + q));
            asm volatile("cp.async.ca.shared.global [%0], [%1], 16;"
                         :: "r"(sb + A_TILE_B + off),
                            "l"(gAl + (size_t)r * 32 + kq4 + q));
        }
#pragma unroll
        for (int rep = 0; rep < 2; rep++) {
            const int li = rep * 512 + tid;
            const int r = li >> 2, q = li & 3;
            const uint32_t off = (uint32_t)(r * 80 + q * 16);
            asm volatile("cp.async.ca.shared.global [%0], [%1], 16;"
                         :: "r"(sb + 2 * A_TILE_B + off),
                            "l"(gBh + (size_t)r * 32 + kq4 + q));
            asm volatile("cp.async.ca.shared.global [%0], [%1], 16;"
                         :: "r"(sb + 2 * A_TILE_B + B_TILE_B + off),
                            "l"(gBl + (size_t)r * 32 + kq4 + q));
        }
    };

    issue(0, 0);
    asm volatile("cp.async.commit_group;" ::: "memory");

    for (int c = 0; c < 8; c++) {
        if (c + 1 < 8) issue(c + 1, (c + 1) & 1);
        asm volatile("cp.async.commit_group;" ::: "memory");
        asm volatile("cp.async.wait_group 1;" ::: "memory");
        __syncthreads();

        const uint32_t sb  = smem_base + (c & 1) * STAGE_B;
        const uint32_t sAh = sb, sAl = sb + A_TILE_B;
        const uint32_t sBh = sb + 2 * A_TILE_B;
        const uint32_t sBl = sb + 2 * A_TILE_B + B_TILE_B;

#pragma unroll
        for (int ks = 0; ks < 2; ks++) {
            const int kb = ks * 16;
            uint32_t ah[2][4], al[2][4];
            const int arow = wm * 32 + (lane & 15);
            const int acol = kb + ((lane >> 4) << 3);
#pragma unroll
            for (int i = 0; i < 2; i++) {
                const uint32_t off = (uint32_t)((arow + i * 16) * 80 + acol * 2);
                ldm_x4(ah[i], sAh + off);
                ldm_x4(al[i], sAl + off);
            }
            const int brow0 = wn * 64 + ((lane >> 4) & 1) * 8 + (lane & 7);
            const int bcol  = kb + ((lane >> 3) & 1) * 8;
#pragma unroll
            for (int jp = 0; jp < 4; jp++) {
                uint32_t bh[4], bl[4];
                const uint32_t off = (uint32_t)((brow0 + jp * 16) * 80 + bcol * 2);
                ldm_x4(bh, sBh + off);
                ldm_x4(bl, sBl + off);
#pragma unroll
                for (int jj = 0; jj < 2; jj++) {
                    const int j = jp * 2 + jj;
#pragma unroll
                    for (int i = 0; i < 2; i++) {
                        mma16816(acc[i][j], ah[i], bh[jj * 2], bh[jj * 2 + 1]);
                        mma16816(acc[i][j], al[i], bh[jj * 2], bh[jj * 2 + 1]);
                        mma16816(acc[i][j], ah[i], bl[jj * 2], bl[jj * 2 + 1]);
                    }
                }
            }
        }
        __syncthreads();
    }
}

// ---------------------------------------------------------------------------
// QKV GEMM: grid.z selects q/k/v. Epilogue writes head-blocked layouts:
// q,k -> W-layout and H-layout hi/lo; v -> W-layout hi/lo + fp32 NHWC.
// ---------------------------------------------------------------------------
__global__ __launch_bounds__(512)
void gemm_qkv(const __nv_bfloat16* __restrict__ Ahi,
              const __nv_bfloat16* __restrict__ Alo,
              const __nv_bfloat16* __restrict__ Whi,
              const __nv_bfloat16* __restrict__ Wlo,
              const float* __restrict__ bq, const float* __restrict__ bk,
              const float* __restrict__ bv,
              __nv_bfloat16* __restrict__ qwh, __nv_bfloat16* __restrict__ qwl,
              __nv_bfloat16* __restrict__ qhh, __nv_bfloat16* __restrict__ qhl,
              __nv_bfloat16* __restrict__ kwh, __nv_bfloat16* __restrict__ kwl,
              __nv_bfloat16* __restrict__ khh, __nv_bfloat16* __restrict__ khl,
              __nv_bfloat16* __restrict__ vwh, __nv_bfloat16* __restrict__ vwl,
              float* __restrict__ vf, float kscale)
{
    extern __shared__ __align__(16) char gsm[];
    const int z = blockIdx.z;
    const int m0 = blockIdx.y * 128;

    float acc[2][8][4];
#pragma unroll
    for (int i = 0; i < 2; i++)
#pragma unroll
        for (int j = 0; j < 8; j++)
#pragma unroll
            for (int t = 0; t < 4; t++) acc[i][j][t] = 0.f;

    gemm_main(acc, Ahi, Alo, Whi + z * 65536, Wlo + z * 65536,
              m0, smem_u32(gsm));

    const float* bias = (z == 0) ? bq : (z == 1) ? bk : bv;
    const float scale = (z == 1) ? kscale : 1.0f;

    __nv_bfloat16 *pwh, *pwl, *phh, *phl;
    if (z == 0)      { pwh = qwh; pwl = qwl; phh = qhh; phl = qhl; }
    else if (z == 1) { pwh = kwh; pwl = kwl; phh = khh; phl = khl; }
    else             { pwh = vwh; pwl = vwl; phh = nullptr; phl = nullptr; }

    const int lane = threadIdx.x & 31;
    const int warp = threadIdx.x >> 5;
    const int wm = warp >> 2, wn = warp & 3;
    const int gid = lane >> 2, tig = lane & 3;

#pragma unroll
    for (int i = 0; i < 2; i++) {
        const int row = m0 + wm * 32 + i * 16 + gid;
        const int b = row >> 12, h = (row >> 6) & 63, w = row & 63;
#pragma unroll
        for (int j = 0; j < 8; j++) {
            const int col = wn * 64 + j * 8 + tig * 2;
            const int n = col >> 5, d = col & 31;
            const float b0 = bias[col], b1 = bias[col + 1];
            const float x0 = (acc[i][j][0] + b0) * scale;
            const float x1 = (acc[i][j][1] + b1) * scale;
            const float y0 = (acc[i][j][2] + b0) * scale;
            const float y1 = (acc[i][j][3] + b1) * scale;

            uint32_t lo0, lo1;
            const uint32_t hi0 = packsplit(x0, x1, lo0);
            const uint32_t hi1 = packsplit(y0, y1, lo1);

            // W-layout [b][n][h][w][d]: row r -> w; r+8 -> w+8 (+256 elems)
            const size_t wl0 = ((size_t)(b * 512 + n * 64 + h) << 11)
                               + (size_t)w * 32 + d;
            *(uint32_t*)(pwh + wl0)       = hi0;
            *(uint32_t*)(pwl + wl0)       = lo0;
            *(uint32_t*)(pwh + wl0 + 256) = hi1;
            *(uint32_t*)(pwl + wl0 + 256) = lo1;

            if (z < 2) {
                // H-layout [b][n][w][h][d]: r+8 -> +8*2048
                const size_t hl0 = ((size_t)(b * 512 + n * 64 + w) << 11)
                                   + (size_t)h * 32 + d;
                *(uint32_t*)(phh + hl0)         = hi0;
                *(uint32_t*)(phl + hl0)         = lo0;
                *(uint32_t*)(phh + hl0 + 16384) = hi1;
                *(uint32_t*)(phl + hl0 + 16384) = lo1;
            } else {
                const size_t o0 = (size_t)row * 256 + col;
                *(float2*)(vf + o0)           = make_float2(x0, x1);
                *(float2*)(vf + o0 + 8 * 256) = make_float2(y0, y1);
            }
        }
    }
}

// ---------------------------------------------------------------------------
// Output projection GEMM: fp32 out, row-major.
// ---------------------------------------------------------------------------
__global__ __launch_bounds__(512)
void gemm_out(const __nv_bfloat16* __restrict__ Ahi,
              const __nv_bfloat16* __restrict__ Alo,
              const __nv_bfloat16* __restrict__ Whi,
              const __nv_bfloat16* __restrict__ Wlo,
              const float* __restrict__ bias, float* __restrict__ out)
{
    extern __shared__ __align__(16) char gsm[];
    const int m0 = blockIdx.y * 128;

    float acc[2][8][4];
#pragma unroll
    for (int i = 0; i < 2; i++)
#pragma unroll
        for (int j = 0; j < 8; j++)
#pragma unroll
            for (int t = 0; t < 4; t++) acc[i][j][t] = 0.f;

    gemm_main(acc, Ahi, Alo, Whi, Wlo, m0, smem_u32(gsm));

    const int lane = threadIdx.x & 31;
    const int warp = threadIdx.x >> 5;
    const int wm = warp >> 2, wn = warp & 3;
    const int gid = lane >> 2, tig = lane & 3;

#pragma unroll
    for (int i = 0; i < 2; i++) {
        const int row = m0 + wm * 32 + i * 16 + gid;
#pragma unroll
        for (int j = 0; j < 8; j++) {
            const int col = wn * 64 + j * 8 + tig * 2;
            const float b0 = bias[col], b1 = bias[col + 1];
            *(float2*)(out + (size_t)row * 256 + col) =
                make_float2(acc[i][j][0] + b0, acc[i][j][1] + b1);
            *(float2*)(out + (size_t)(row + 8) * 256 + col) =
                make_float2(acc[i][j][2] + b0, acc[i][j][3] + b1);
        }
    }
}

// ---------------------------------------------------------------------------
// LePE: 5x5 depthwise conv, register-blocked 4 x-outputs per thread.
// ---------------------------------------------------------------------------
__global__ __launch_bounds__(256)
void lepe_kernel(const float* __restrict__ V,
                 const float* __restrict__ Wl,
                 const float* __restrict__ bl,
                 float* __restrict__ out)
{
    const int idx = blockIdx.x * 256 + threadIdx.x;
    const int c  = idx & 255;
    const int xg = (idx >> 8) & 15;
    const int y  = (idx >> 12) & 63;
    const int b  = idx >> 18;
    const int x0 = xg * 4;

    float w[5][5];
#pragma unroll
    for (int dy = 0; dy < 5; dy++)
#pragma unroll
        for (int dx = 0; dx < 5; dx++)
            w[dy][dx] = Wl[(dy * 5 + dx) * 256 + c];

    const float bias = bl[c];
    float acc[4] = {bias, bias, bias, bias};

#pragma unroll
    for (int dy = 0; dy < 5; dy++) {
        const int yy = y + dy - 2;
        if (yy < 0 || yy > 63) continue;
        const float* vrow = V + (size_t)(((b << 6) + yy) << 6) * 256 + c;
#pragma unroll
        for (int e = 0; e < 8; e++) {
            const int xx = x0 - 2 + e;
            if (xx < 0 || xx > 63) continue;
            const float val = vrow[(size_t)xx * 256];
#pragma unroll
            for (int u = 0; u < 4; u++) {
                const int dxi = e - u;
                if (dxi >= 0 && dxi < 5) acc[u] += val * w[dy][dxi];
            }
        }
    }

    float* orow = out + (size_t)((((b << 6) + y) << 6) + x0) * 256 + c;
#pragma unroll
    for (int u = 0; u < 4; u++) orow[(size_t)u * 256] = acc[u];
}

// ---------------------------------------------------------------------------
// HMMA attention on head-blocked contiguous tiles (coalesced staging) with
// smem+ldmatrix fragment path for K and V. Q fragments direct from gmem.
// Block (b, y, n): tile base = ((b*512 + n*64 + y) << 11), 64 rows x 32 d.
// FUSE=false: width-attn; out -> v1 in H-layout.
// FUSE=true : height-attn; out -> row-major a (+LePE), for out-projection.
// ---------------------------------------------------------------------------
template <bool FUSE>
__global__ __launch_bounds__(128, 8)
void attn3(const __nv_bfloat16* __restrict__ Qhi, const __nv_bfloat16* __restrict__ Qlo,
           const __nv_bfloat16* __restrict__ Khi, const __nv_bfloat16* __restrict__ Klo,
           const __nv_bfloat16* __restrict__ Vhi, const __nv_bfloat16* __restrict__ Vlo,
           const float* __restrict__ mask,
           const float* __restrict__ lepe,
           __nv_bfloat16* __restrict__ Ohi, __nv_bfloat16* __restrict__ Olo)
{
    __shared__ __align__(16) __nv_bfloat16 sKh[64][40];
    __shared__ __align__(16) __nv_bfloat16 sKl[64][40];
    __shared__ __align__(16) __nv_bfloat16 sVh[64][40];
    __shared__ __align__(16) __nv_bfloat16 sVl[64][40];

    const int n = blockIdx.x & 7;
    const int y = (blockIdx.x >> 3) & 63;
    const int b = blockIdx.x >> 9;
    const int tid  = threadIdx.x;
    const int lane = tid & 31;
    const int w    = tid >> 5;
    const int gid  = lane >> 2;
    const int tig  = lane & 3;

    const size_t tb = ((size_t)(b * 512 + n * 64 + y)) << 11;

    // Stage K and V hi/lo: fully coalesced (each tile 4KB contiguous).
#pragma unroll
    for (int i = tid; i < 256; i += 128) {
        const int r = i >> 2, c8 = (i & 3) * 8;
        const size_t g = tb + r * 32 + c8;
        *(uint4*)&sKh[r][c8] = *(const uint4*)(Khi + g);
        *(uint4*)&sKl[r][c8] = *(const uint4*)(Klo + g);
        *(uint4*)&sVh[r][c8] = *(const uint4*)(Vhi + g);
        *(uint4*)&sVl[r][c8] = *(const uint4*)(Vlo + g);
    }

    // Q fragments direct from gmem (one-time, within a 4KB tile).
    uint32_t qh[2][4], ql[2][4];
    {
        const size_t qa = tb + (size_t)(16 * w + gid) * 32 + 2 * tig;
#pragma unroll
        for (int kc = 0; kc < 2; kc++) {
            const size_t a = qa + kc * 16;
            qh[kc][0] = *(const uint32_t*)(Qhi + a);
            qh[kc][1] = *(const uint32_t*)(Qhi + a + 256);
            qh[kc][2] = *(const uint32_t*)(Qhi + a + 8);
            qh[kc][3] = *(const uint32_t*)(Qhi + a + 264);
            ql[kc][0] = *(const uint32_t*)(Qlo + a);
            ql[kc][1] = *(const uint32_t*)(Qlo + a + 256);
            ql[kc][2] = *(const uint32_t*)(Qlo + a + 8);
            ql[kc][3] = *(const uint32_t*)(Qlo + a + 264);
        }
    }
    __syncthreads();

    // S = Q K^T via ldmatrix on staged K.
    float sacc[8][4];
#pragma unroll
    for (int j = 0; j < 8; j++)
#pragma unroll
        for (int t = 0; t < 4; t++) sacc[j][t] = 0.f;

    {
        const int krow = ((lane >> 4) & 1) * 8 + (lane & 7);
        const int kcol = ((lane >> 3) & 1) * 8;
#pragma unroll
        for (int kc = 0; kc < 2; kc++)
#pragma unroll
            for (int jp = 0; jp < 4; jp++) {
                uint32_t kh[4], kl[4];
                ldm_x4(kh, smem_u32(&sKh[16 * jp + krow][kc * 16 + kcol]));
                ldm_x4(kl, smem_u32(&sKl[16 * jp + krow][kc * 16 + kcol]));
#pragma unroll
                for (int jj = 0; jj < 2; jj++) {
                    const int j = jp * 2 + jj;
                    mma16816(sacc[j], qh[kc], kh[jj * 2], kh[jj * 2 + 1]);
                    mma16816(sacc[j], ql[kc], kh[jj * 2], kh[jj * 2 + 1]);
                    mma16816(sacc[j], qh[kc], kl[jj * 2], kl[jj * 2 + 1]);
                }
            }
    }

    // Mask add + softmax on fragments.
    const int r0 = 16 * w + gid;
    const int r1 = r0 + 8;
    const float* mbase = mask + (size_t)n * 4096;
    float mx0 = -1e30f, mx1 = -1e30f;
#pragma unroll
    for (int j = 0; j < 8; j++) {
        const float2 m0 = *(const float2*)(mbase + r0 * 64 + j * 8 + tig * 2);
        const float2 m1 = *(const float2*)(mbase + r1 * 64 + j * 8 + tig * 2);
        sacc[j][0] += m0.x; sacc[j][1] += m0.y;
        sacc[j][2] += m1.x; sacc[j][3] += m1.y;
        mx0 = fmaxf(mx0, fmaxf(sacc[j][0], sacc[j][1]));
        mx1 = fmaxf(mx1, fmaxf(sacc[j][2], sacc[j][3]));
    }
    mx0 = fmaxf(mx0, __shfl_xor_sync(0xffffffffu, mx0, 1));
    mx0 = fmaxf(mx0, __shfl_xor_sync(0xffffffffu, mx0, 2));
    mx1 = fmaxf(mx1, __shfl_xor_sync(0xffffffffu, mx1, 1));
    mx1 = fmaxf(mx1, __shfl_xor_sync(0xffffffffu, mx1, 2));

    float sum0 = 0.f, sum1 = 0.f;
#pragma unroll
    for (int j = 0; j < 8; j++) {
        sacc[j][0] = __expf(sacc[j][0] - mx0);
        sacc[j][1] = __expf(sacc[j][1] - mx0);
        sacc[j][2] = __expf(sacc[j][2] - mx1);
        sacc[j][3] = __expf(sacc[j][3] - mx1);
        sum0 += sacc[j][0] + sacc[j][1];
        sum1 += sacc[j][2] + sacc[j][3];
    }
    sum0 += __shfl_xor_sync(0xffffffffu, sum0, 1);
    sum0 += __shfl_xor_sync(0xffffffffu, sum0, 2);
    sum1 += __shfl_xor_sync(0xffffffffu, sum1, 1);
    sum1 += __shfl_xor_sync(0xffffffffu, sum1, 2);
    const float inv0 = 1.f / sum0;
    const float inv1 = 1.f / sum1;

    // Repack P (unnormalized) into A-fragments, hi/lo bf16.
    uint32_t ph[4][4], pl[4][4];
#pragma unroll
    for (int kc = 0; kc < 4; kc++) {
        const int t0 = 2 * kc, t1 = 2 * kc + 1;
        ph[kc][0] = packsplit(sacc[t0][0], sacc[t0][1], pl[kc][0]);
        ph[kc][1] = packsplit(sacc[t0][2], sacc[t0][3], pl[kc][1]);
        ph[kc][2] = packsplit(sacc[t1][0], sacc[t1][1], pl[kc][2]);
        ph[kc][3] = packsplit(sacc[t1][2], sacc[t1][3], pl[kc][3]);
    }

    // O = P V via ldmatrix.trans on staged V.
    float oacc[4][4];
#pragma unroll
    for (int jd = 0; jd < 4; jd++)
#pragma unroll
        for (int t = 0; t < 4; t++) oacc[jd][t] = 0.f;

    {
        const int vrow = lane & 15;
#pragma unroll
        for (int kc = 0; kc < 4; kc++)
#pragma unroll
            for (int jd = 0; jd < 4; jd++) {
                uint32_t vh[2], vl[2];
                ldm_x2t(vh, smem_u32(&sVh[16 * kc + vrow][jd * 8]));
                ldm_x2t(vl, smem_u32(&sVl[16 * kc + vrow][jd * 8]));
                mma16816(oacc[jd], ph[kc], vh[0], vh[1]);
                mma16816(oacc[jd], pl[kc], vh[0], vh[1]);
                mma16816(oacc[jd], ph[kc], vl[0], vl[1]);
            }
    }

    // Epilogue.
#pragma unroll
    for (int jd = 0; jd < 4; jd++) {
        float x0 = oacc[jd][0] * inv0, x1 = oacc[jd][1] * inv0;
        float y0 = oacc[jd][2] * inv1, y1 = oacc[jd][3] * inv1;
        const int d = jd * 8 + tig * 2;
        size_t o0, o1;
        if (FUSE) {
            // row-major a output, spatial (h=r, w=y)
            o0 = ((size_t)b * 4096 + (size_t)r0 * 64 + y) * 256 + n * 32 + d;
            o1 = ((size_t)b * 4096 + (size_t)r1 * 64 + y) * 256 + n * 32 + d;
            const float2 lp0 = *(const float2*)(lepe + o0);
            const float2 lp1 = *(const float2*)(lepe + o1);
            x0 += lp0.x; x1 += lp0.y;
            y0 += lp1.x; y1 += lp1.y;
        } else {
            // v1 H-layout [b][n][w=r][h=y][d]
            o0 = ((size_t)(b * 512 + n * 64 + r0) << 11) + (size_t)y * 32 + d;
            o1 = o0 + (size_t)(8 << 11);
        }
        uint32_t lo;
        uint32_t hi = packsplit(x0, x1, lo);
        *(uint32_t*)(Ohi + o0) = hi;
        *(uint32_t*)(Olo + o0) = lo;
        hi = packsplit(y0, y1, lo);
        *(uint32_t*)(Ohi + o1) = hi;
        *(uint32_t*)(Olo + o1) = lo;
    }
}

// ---------------------------------------------------------------------------
extern "C" void kernel_launch(void* const* d_in, const int* in_sizes, int n_in,
                              void* d_out, int out_size)
{
    const float* x      = (const float*)d_in[0];
    const float* mask_h = (const float*)d_in[1];
    const float* mask_w = (const float*)d_in[2];
    const float* Wq = (const float*)d_in[3];
    const float* bq = (const float*)d_in[4];
    const float* Wk = (const float*)d_in[5];
    const float* bk = (const float*)d_in[6];
    const float* Wv = (const float*)d_in[7];
    const float* bv = (const float*)d_in[8];
    const float* Wl = (const float*)d_in[9];
    const float* bl = (const float*)d_in[10];
    const float* Wo = (const float*)d_in[11];
    const float* bo = (const float*)d_in[12];
    float* out = (float*)d_out;

    float *v, *lepe;
    __nv_bfloat16 *qwh, *qwl, *qhh, *qhl, *kwh, *kwl, *khh, *khl;
    __nv_bfloat16 *vwh, *vwl, *v1h, *v1l, *ahi, *alo, *whi, *wlo;
    cudaGetSymbolAddress((void**)&v,    g_v);
    cudaGetSymbolAddress((void**)&lepe, g_lepe);
    cudaGetSymbolAddress((void**)&qwh,  g_qwh);
    cudaGetSymbolAddress((void**)&qwl,  g_qwl);
    cudaGetSymbolAddress((void**)&qhh,  g_qhh);
    cudaGetSymbolAddress((void**)&qhl,  g_qhl);
    cudaGetSymbolAddress((void**)&kwh,  g_kwh);
    cudaGetSymbolAddress((void**)&kwl,  g_kwl);
    cudaGetSymbolAddress((void**)&khh,  g_khh);
    cudaGetSymbolAddress((void**)&khl,  g_khl);
    cudaGetSymbolAddress((void**)&vwh,  g_vwh);
    cudaGetSymbolAddress((void**)&vwl,  g_vwl);
    cudaGetSymbolAddress((void**)&v1h,  g_v1h);
    cudaGetSymbolAddress((void**)&v1l,  g_v1l);
    cudaGetSymbolAddress((void**)&ahi,  g_ahi);
    cudaGetSymbolAddress((void**)&alo,  g_alo);
    cudaGetSymbolAddress((void**)&whi,  g_whi);
    cudaGetSymbolAddress((void**)&wlo,  g_wlo);

    static int smem_set = 0;
    if (!smem_set) {
        cudaFuncSetAttribute(gemm_qkv,
                             cudaFuncAttributeMaxDynamicSharedMemorySize,
                             GEMM_SMEM);
        cudaFuncSetAttribute(gemm_out,
                             cudaFuncAttributeMaxDynamicSharedMemorySize,
                             GEMM_SMEM);
        smem_set = 1;
    }

    const float scaling = 0.17677669529663687f;  // 32^-0.5

    // 1) Splits in one launch.
    split_all<<<8448, 256>>>(x, Wq, Wk, Wv, Wo, ahi, alo, whi, wlo);

    // 2) QKV projection -> head-blocked layouts.
    gemm_qkv<<<dim3(1, 256, 3), 512, GEMM_SMEM>>>(
        ahi, alo, whi, wlo, bq, bk, bv,
        qwh, qwl, qhh, qhl, kwh, kwl, khh, khl, vwh, vwl, v, scaling);

    // 3) LePE on fp32 v (NHWC).
    lepe_kernel<<<ELEMS / 4 / 256, 256>>>(v, Wl, bl, lepe);

    // 4) Width-axis attention (W-layout tiles) -> v1 (H-layout).
    attn3<false><<<4096, 128>>>(qwh, qwl, kwh, kwl, vwh, vwl,
                                mask_w, nullptr, v1h, v1l);

    // 5) Height-axis attention (H-layout tiles) + LePE -> row-major a.
    attn3<true><<<4096, 128>>>(qhh, qhl, khh, khl, v1h, v1l,
                               mask_h, lepe, ahi, alo);

    // 6) Output projection.
    gemm_out<<<dim3(1, 256, 1), 512, GEMM_SMEM>>>(
        ahi, alo, whi + 3 * 65536, wlo + 3 * 65536, bo, out);
}

// round 11
// speedup vs baseline: 1.4124x; 1.4124x over previous
#include <cuda_runtime.h>
#include <cuda_bf16.h>
#include <cstdint>

// Problem constants: B=8, H=64, W=64, C=256, NUM_HEADS=8, KEY_DIM=32
#define M_TOT   32768
#define C_DIM   256
#define ELEMS   (M_TOT * C_DIM)   // 8388608

// ---------------- scratch (device globals; no allocation allowed) ----------
__device__ __align__(16) float g_v[ELEMS];
__device__ __align__(16) float g_lepe[ELEMS];

__device__ __align__(16) __nv_bfloat16 g_qhi[ELEMS];
__device__ __align__(16) __nv_bfloat16 g_qlo[ELEMS];
__device__ __align__(16) __nv_bfloat16 g_khi[ELEMS];
__device__ __align__(16) __nv_bfloat16 g_klo[ELEMS];
__device__ __align__(16) __nv_bfloat16 g_vhi[ELEMS];
__device__ __align__(16) __nv_bfloat16 g_vlo[ELEMS];
__device__ __align__(16) __nv_bfloat16 g_v1hi[ELEMS];
__device__ __align__(16) __nv_bfloat16 g_v1lo[ELEMS];
__device__ __align__(16) __nv_bfloat16 g_ahi[ELEMS];
__device__ __align__(16) __nv_bfloat16 g_alo[ELEMS];
__device__ __align__(16) __nv_bfloat16 g_whi[4 * 65536];
__device__ __align__(16) __nv_bfloat16 g_wlo[4 * 65536];

// ---------------- helpers ---------------------------------------------------
__device__ __forceinline__ uint32_t smem_u32(const void* p) {
    uint32_t a;
    asm("{ .reg .u64 t; cvta.to.shared.u64 t, %1; cvt.u32.u64 %0, t; }"
        : "=r"(a) : "l"(p));
    return a;
}

__device__ __forceinline__ void cpa16(uint32_t dst, const void* src) {
    asm volatile("cp.async.ca.shared.global [%0], [%1], 16;"
                 :: "r"(dst), "l"(src));
}

__device__ __forceinline__ void mma16816(float* c, const uint32_t* a,
                                         uint32_t b0, uint32_t b1)
{
    asm volatile(
        "mma.sync.aligned.m16n8k16.row.col.f32.bf16.bf16.f32 "
        "{%0,%1,%2,%3}, {%4,%5,%6,%7}, {%8,%9}, {%0,%1,%2,%3};"
        : "+f"(c[0]), "+f"(c[1]), "+f"(c[2]), "+f"(c[3])
        : "r"(a[0]), "r"(a[1]), "r"(a[2]), "r"(a[3]), "r"(b0), "r"(b1));
}

__device__ __forceinline__ void ldm_x4(uint32_t* r, uint32_t addr) {
    asm volatile("ldmatrix.sync.aligned.m8n8.x4.shared.b16 {%0,%1,%2,%3}, [%4];"
        : "=r"(r[0]), "=r"(r[1]), "=r"(r[2]), "=r"(r[3]) : "r"(addr));
}

__device__ __forceinline__ void ldm_x2t(uint32_t* r, uint32_t addr) {
    asm volatile("ldmatrix.sync.aligned.m8n8.x2.trans.shared.b16 {%0,%1}, [%2];"
        : "=r"(r[0]), "=r"(r[1]) : "r"(addr));
}

// Split pair (x0 -> low 16, x1 -> high 16) into bf16 hi word; residual lo word.
__device__ __forceinline__ uint32_t packsplit(float x0, float x1, uint32_t& lo) {
    __nv_bfloat16 h0 = __float2bfloat16(x0), h1 = __float2bfloat16(x1);
    float r0 = x0 - __bfloat162float(h0);
    float r1 = x1 - __bfloat162float(h1);
    __nv_bfloat16 l0 = __float2bfloat16(r0), l1 = __float2bfloat16(r1);
    lo = (uint32_t)__bfloat16_as_ushort(l0) |
         ((uint32_t)__bfloat16_as_ushort(l1) << 16);
    return (uint32_t)__bfloat16_as_ushort(h0) |
           ((uint32_t)__bfloat16_as_ushort(h1) << 16);
}

// ---------------------------------------------------------------------------
// Merged split kernel: blocks [0, 8192) split x; blocks [8192, 8448) split W.
// ---------------------------------------------------------------------------
__global__ __launch_bounds__(256)
void split_all(const float* __restrict__ x,
               const float* __restrict__ W0, const float* __restrict__ W1,
               const float* __restrict__ W2, const float* __restrict__ W3,
               __nv_bfloat16* __restrict__ xhi, __nv_bfloat16* __restrict__ xlo,
               __nv_bfloat16* __restrict__ whi, __nv_bfloat16* __restrict__ wlo)
{
    if (blockIdx.x < 8192) {
        const int i = blockIdx.x * 256 + threadIdx.x;
        float4 v = ((const float4*)x)[i];
        uint32_t l0, l1;
        uint32_t h0 = packsplit(v.x, v.y, l0);
        uint32_t h1 = packsplit(v.z, v.w, l1);
        ((uint2*)xhi)[i] = make_uint2(h0, h1);
        ((uint2*)xlo)[i] = make_uint2(l0, l1);
    } else {
        const int wblk = blockIdx.x - 8192;
        const int w = wblk >> 6;
        const float* W = (w == 0) ? W0 : (w == 1) ? W1 : (w == 2) ? W2 : W3;
        const int i = (wblk & 63) * 256 + threadIdx.x;
        float4 v = ((const float4*)W)[i];
        uint32_t l0, l1;
        uint32_t h0 = packsplit(v.x, v.y, l0);
        uint32_t h1 = packsplit(v.z, v.w, l1);
        ((uint2*)whi)[w * 16384 + i] = make_uint2(h0, h1);
        ((uint2*)wlo)[w * 16384 + i] = make_uint2(l0, l1);
    }
}

// ---------------------------------------------------------------------------
// HMMA GEMM, fp32 emulation (hi/lo bf16, 3 products), cp.async double buffer.
// CTA tile 128x256 (full N), 512 threads = 16 warps (4m x 4n), warp tile 32x64.
// Epilogue: optionally write bf16 hi/lo split output and/or fp32 output.
// ---------------------------------------------------------------------------
#define A_TILE_B  10240        // 128 * 80
#define B_TILE_B  20480        // 256 * 80
#define STAGE_B   (2 * A_TILE_B + 2 * B_TILE_B)   // 61440
#define GEMM_SMEM (2 * STAGE_B)                   // 122880

__global__ __launch_bounds__(512)
void gemm_hmma(const __nv_bfloat16* __restrict__ Ahi,
               const __nv_bfloat16* __restrict__ Alo,
               const __nv_bfloat16* __restrict__ Whi,
               const __nv_bfloat16* __restrict__ Wlo,
               const float* __restrict__ bias0, const float* __restrict__ bias1,
               const float* __restrict__ bias2,
               __nv_bfloat16* __restrict__ h0, __nv_bfloat16* __restrict__ l0p,
               __nv_bfloat16* __restrict__ h1, __nv_bfloat16* __restrict__ l1p,
               __nv_bfloat16* __restrict__ h2, __nv_bfloat16* __restrict__ l2p,
               float* __restrict__ f2,     // fp32 out for z==2 (v)
               float* __restrict__ fout,   // if set: fp32-only output (out proj)
               float sc0, float sc1, float sc2)
{
    extern __shared__ __align__(16) char gsm[];

    const int z = blockIdx.z;
    const __nv_bfloat16* Bhi = Whi + z * 65536;
    const __nv_bfloat16* Blo = Wlo + z * 65536;
    const float* bias = (z == 0) ? bias0 : (z == 1) ? bias1 : bias2;
    const float scale = (z == 0) ? sc0   : (z == 1) ? sc1   : sc2;

    __nv_bfloat16 *ohi, *olo;
    float* of;
    if (fout) { of = fout; ohi = nullptr; olo = nullptr; }
    else {
        ohi = (z == 0) ? h0 : (z == 1) ? h1 : h2;
        olo = (z == 0) ? l0p : (z == 1) ? l1p : l2p;
        of  = (z == 2) ? f2 : nullptr;
    }

    const int tid  = threadIdx.x;
    const int lane = tid & 31;
    const int warp = tid >> 5;
    const int wm   = warp >> 2;
    const int wn   = warp & 3;
    const int m0   = blockIdx.y * 128;
    const int gid  = lane >> 2;
    const int tig  = lane & 3;

    float acc[2][8][4];
#pragma unroll
    for (int i = 0; i < 2; i++)
#pragma unroll
        for (int j = 0; j < 8; j++)
#pragma unroll
            for (int t = 0; t < 4; t++) acc[i][j][t] = 0.f;

    const uint4* gAh = (const uint4*)Ahi + (size_t)m0 * 32;
    const uint4* gAl = (const uint4*)Alo + (size_t)m0 * 32;
    const uint4* gBh = (const uint4*)Bhi;
    const uint4* gBl = (const uint4*)Blo;
    const uint32_t smem_base = smem_u32(gsm);

    auto issue = [&](int chunk, int stg) {
        const int kq4 = chunk * 4;
        const uint32_t sb = smem_base + stg * STAGE_B;
        {
            const int r = tid >> 2, q = tid & 3;
            const uint32_t off = (uint32_t)(r * 80 + q * 16);
            cpa16(sb + off,            gAh + (size_t)r * 32 + kq4 + q);
            cpa16(sb + A_TILE_B + off, gAl + (size_t)r * 32 + kq4 + q);
        }
#pragma unroll
        for (int rep = 0; rep < 2; rep++) {
            const int li = rep * 512 + tid;
            const int r = li >> 2, q = li & 3;
            const uint32_t off = (uint32_t)(r * 80 + q * 16);
            cpa16(sb + 2 * A_TILE_B + off,
                  gBh + (size_t)r * 32 + kq4 + q);
            cpa16(sb + 2 * A_TILE_B + B_TILE_B + off,
                  gBl + (size_t)r * 32 + kq4 + q);
        }
    };

    issue(0, 0);
    asm volatile("cp.async.commit_group;" ::: "memory");

    for (int c = 0; c < 8; c++) {
        if (c + 1 < 8) issue(c + 1, (c + 1) & 1);
        asm volatile("cp.async.commit_group;" ::: "memory");
        asm volatile("cp.async.wait_group 1;" ::: "memory");
        __syncthreads();

        const uint32_t sb  = smem_base + (c & 1) * STAGE_B;
        const uint32_t sAh = sb, sAl = sb + A_TILE_B;
        const uint32_t sBh = sb + 2 * A_TILE_B;
        const uint32_t sBl = sb + 2 * A_TILE_B + B_TILE_B;

#pragma unroll
        for (int ks = 0; ks < 2; ks++) {
            const int kb = ks * 16;
            uint32_t ah[2][4], al[2][4];
            const int arow = wm * 32 + (lane & 15);
            const int acol = kb + ((lane >> 4) << 3);
#pragma unroll
            for (int i = 0; i < 2; i++) {
                const uint32_t off = (uint32_t)((arow + i * 16) * 80 + acol * 2);
                ldm_x4(ah[i], sAh + off);
                ldm_x4(al[i], sAl + off);
            }
            const int brow0 = wn * 64 + ((lane >> 4) & 1) * 8 + (lane & 7);
            const int bcol  = kb + ((lane >> 3) & 1) * 8;
#pragma unroll
            for (int jp = 0; jp < 4; jp++) {
                uint32_t bh[4], bl[4];
                const uint32_t off = (uint32_t)((brow0 + jp * 16) * 80 + bcol * 2);
                ldm_x4(bh, sBh + off);
                ldm_x4(bl, sBl + off);
#pragma unroll
                for (int jj = 0; jj < 2; jj++) {
                    const int j = jp * 2 + jj;
#pragma unroll
                    for (int i = 0; i < 2; i++) {
                        mma16816(acc[i][j], ah[i], bh[jj * 2], bh[jj * 2 + 1]);
                        mma16816(acc[i][j], al[i], bh[jj * 2], bh[jj * 2 + 1]);
                        mma16816(acc[i][j], ah[i], bl[jj * 2], bl[jj * 2 + 1]);
                    }
                }
            }
        }
        __syncthreads();
    }

    // Epilogue
#pragma unroll
    for (int i = 0; i < 2; i++) {
        const int row = m0 + wm * 32 + i * 16 + gid;
#pragma unroll
        for (int j = 0; j < 8; j++) {
            const int col = wn * 64 + j * 8 + tig * 2;
            const float b0 = bias[col], b1 = bias[col + 1];
            const float x0 = (acc[i][j][0] + b0) * scale;
            const float x1 = (acc[i][j][1] + b1) * scale;
            const float y0 = (acc[i][j][2] + b0) * scale;
            const float y1 = (acc[i][j][3] + b1) * scale;
            const size_t o0 = (size_t)row * 256 + col;
            const size_t o1 = o0 + 8 * 256;
            if (ohi) {
                uint32_t lo;
                uint32_t hi = packsplit(x0, x1, lo);
                *(uint32_t*)(ohi + o0) = hi;
                *(uint32_t*)(olo + o0) = lo;
                hi = packsplit(y0, y1, lo);
                *(uint32_t*)(ohi + o1) = hi;
                *(uint32_t*)(olo + o1) = lo;
            }
            if (of) {
                *(float2*)(of + o0) = make_float2(x0, x1);
                *(float2*)(of + o1) = make_float2(y0, y1);
            }
        }
    }
}

// ---------------------------------------------------------------------------
// LePE: 5x5 depthwise conv, register-blocked 4 x-outputs per thread.
// ---------------------------------------------------------------------------
__global__ __launch_bounds__(256)
void lepe_kernel(const float* __restrict__ V,
                 const float* __restrict__ Wl,
                 const float* __restrict__ bl,
                 float* __restrict__ out)
{
    const int idx = blockIdx.x * 256 + threadIdx.x;
    const int c  = idx & 255;
    const int xg = (idx >> 8) & 15;
    const int y  = (idx >> 12) & 63;
    const int b  = idx >> 18;
    const int x0 = xg * 4;

    float w[5][5];
#pragma unroll
    for (int dy = 0; dy < 5; dy++)
#pragma unroll
        for (int dx = 0; dx < 5; dx++)
            w[dy][dx] = Wl[(dy * 5 + dx) * 256 + c];

    const float bias = bl[c];
    float acc[4] = {bias, bias, bias, bias};

#pragma unroll
    for (int dy = 0; dy < 5; dy++) {
        const int yy = y + dy - 2;
        if (yy < 0 || yy > 63) continue;
        const float* vrow = V + (size_t)(((b << 6) + yy) << 6) * 256 + c;
#pragma unroll
        for (int e = 0; e < 8; e++) {
            const int xx = x0 - 2 + e;
            if (xx < 0 || xx > 63) continue;
            const float val = vrow[(size_t)xx * 256];
#pragma unroll
            for (int u = 0; u < 4; u++) {
                const int dxi = e - u;
                if (dxi >= 0 && dxi < 5) acc[u] += val * w[dy][dxi];
            }
        }
    }

    float* orow = out + (size_t)((((b << 6) + y) << 6) + x0) * 256 + c;
#pragma unroll
    for (int u = 0; u < 4; u++) orow[(size_t)u * 256] = acc[u];
}

// ---------------------------------------------------------------------------
// HMMA axis attention: one (b, line, head) 64x64x32 problem per block.
// 128 threads = 4 warps; warp w owns query rows 16w..16w+15.
// QK^T and PV on tensor cores with bf16 hi/lo fp32 emulation.
// Staging via cp.async (independent 16B ops, single wait).
// FUSE: add LePE and write bf16 hi/lo for the output projection input.
// ---------------------------------------------------------------------------
template <bool FUSE>
__global__ __launch_bounds__(128)
void attn_hmma(const __nv_bfloat16* __restrict__ Qhi, const __nv_bfloat16* __restrict__ Qlo,
               const __nv_bfloat16* __restrict__ Khi, const __nv_bfloat16* __restrict__ Klo,
               const __nv_bfloat16* __restrict__ Vhi, const __nv_bfloat16* __restrict__ Vlo,
               const float* __restrict__ mask,
               const float* __restrict__ lepe,
               __nv_bfloat16* __restrict__ Ohi, __nv_bfloat16* __restrict__ Olo,
               int y_stride, int row_stride)
{
    __shared__ __align__(16) __nv_bfloat16 sQh[64][40];
    __shared__ __align__(16) __nv_bfloat16 sQl[64][40];
    __shared__ __align__(16) __nv_bfloat16 sKh[64][40];
    __shared__ __align__(16) __nv_bfloat16 sKl[64][40];
    __shared__ __align__(16) __nv_bfloat16 sVh[64][40];
    __shared__ __align__(16) __nv_bfloat16 sVl[64][40];

    const int n = blockIdx.x;
    const int y = blockIdx.y;
    const int b = blockIdx.z;
    const int tid  = threadIdx.x;
    const int lane = tid & 31;
    const int w    = tid >> 5;
    const int gid  = lane >> 2;
    const int tig  = lane & 3;

    const size_t base = (size_t)b * (64 * 64 * 256) + (size_t)y * y_stride + n * 32;

    // Stage Q/K/V hi/lo tiles via cp.async (12 independent 16B ops/thread).
#pragma unroll
    for (int i = tid; i < 256; i += 128) {
        const int r = i >> 2, c8 = (i & 3) * 8;
        const size_t g = base + (size_t)r * row_stride + c8;
        cpa16(smem_u32(&sQh[r][c8]), Qhi + g);
        cpa16(smem_u32(&sQl[r][c8]), Qlo + g);
        cpa16(smem_u32(&sKh[r][c8]), Khi + g);
        cpa16(smem_u32(&sKl[r][c8]), Klo + g);
        cpa16(smem_u32(&sVh[r][c8]), Vhi + g);
        cpa16(smem_u32(&sVl[r][c8]), Vlo + g);
    }
    asm volatile("cp.async.commit_group;" ::: "memory");
    asm volatile("cp.async.wait_group 0;" ::: "memory");
    __syncthreads();

    // Q fragments: m16k16 x 2 k-chunks.
    uint32_t qh[2][4], ql[2][4];
    {
        const int arow = 16 * w + (lane & 15);
        const int acol = (lane >> 4) << 3;
#pragma unroll
        for (int kc = 0; kc < 2; kc++) {
            ldm_x4(qh[kc], smem_u32(&sQh[arow][kc * 16 + acol]));
            ldm_x4(ql[kc], smem_u32(&sQl[arow][kc * 16 + acol]));
        }
    }

    // S = Q K^T (+ emulation), 8 n8-tiles.
    float sacc[8][4];
#pragma unroll
    for (int j = 0; j < 8; j++)
#pragma unroll
        for (int t = 0; t < 4; t++) sacc[j][t] = 0.f;

    {
        const int krow = ((lane >> 4) & 1) * 8 + (lane & 7);
        const int kcol = ((lane >> 3) & 1) * 8;
#pragma unroll
        for (int kc = 0; kc < 2; kc++)
#pragma unroll
            for (int jp = 0; jp < 4; jp++) {
                uint32_t kh[4], kl[4];
                ldm_x4(kh, smem_u32(&sKh[16 * jp + krow][kc * 16 + kcol]));
                ldm_x4(kl, smem_u32(&sKl[16 * jp + krow][kc * 16 + kcol]));
#pragma unroll
                for (int jj = 0; jj < 2; jj++) {
                    const int j = jp * 2 + jj;
                    mma16816(sacc[j], qh[kc], kh[jj * 2], kh[jj * 2 + 1]);
                    mma16816(sacc[j], ql[kc], kh[jj * 2], kh[jj * 2 + 1]);
                    mma16816(sacc[j], qh[kc], kl[jj * 2], kl[jj * 2 + 1]);
                }
            }
    }

    // Mask add + softmax on fragments (rows r0=16w+gid, r1=r0+8).
    const int r0 = 16 * w + gid;
    const int r1 = r0 + 8;
    const float* mbase = mask + (size_t)n * 4096;
    float mx0 = -1e30f, mx1 = -1e30f;
#pragma unroll
    for (int j = 0; j < 8; j++) {
        const float2 m0 = *(const float2*)(mbase + r0 * 64 + j * 8 + tig * 2);
        const float2 m1 = *(const float2*)(mbase + r1 * 64 + j * 8 + tig * 2);
        sacc[j][0] += m0.x; sacc[j][1] += m0.y;
        sacc[j][2] += m1.x; sacc[j][3] += m1.y;
        mx0 = fmaxf(mx0, fmaxf(sacc[j][0], sacc[j][1]));
        mx1 = fmaxf(mx1, fmaxf(sacc[j][2], sacc[j][3]));
    }
    mx0 = fmaxf(mx0, __shfl_xor_sync(0xffffffffu, mx0, 1));
    mx0 = fmaxf(mx0, __shfl_xor_sync(0xffffffffu, mx0, 2));
    mx1 = fmaxf(mx1, __shfl_xor_sync(0xffffffffu, mx1, 1));
    mx1 = fmaxf(mx1, __shfl_xor_sync(0xffffffffu, mx1, 2));

    float sum0 = 0.f, sum1 = 0.f;
#pragma unroll
    for (int j = 0; j < 8; j++) {
        sacc[j][0] = __expf(sacc[j][0] - mx0);
        sacc[j][1] = __expf(sacc[j][1] - mx0);
        sacc[j][2] = __expf(sacc[j][2] - mx1);
        sacc[j][3] = __expf(sacc[j][3] - mx1);
        sum0 += sacc[j][0] + sacc[j][1];
        sum1 += sacc[j][2] + sacc[j][3];
    }
    sum0 += __shfl_xor_sync(0xffffffffu, sum0, 1);
    sum0 += __shfl_xor_sync(0xffffffffu, sum0, 2);
    sum1 += __shfl_xor_sync(0xffffffffu, sum1, 1);
    sum1 += __shfl_xor_sync(0xffffffffu, sum1, 2);
    const float inv0 = 1.f / sum0;
    const float inv1 = 1.f / sum1;

    // Repack P (unnormalized) into A-fragments, hi/lo bf16.
    uint32_t ph[4][4], pl[4][4];
#pragma unroll
    for (int kc = 0; kc < 4; kc++) {
        const int t0 = 2 * kc, t1 = 2 * kc + 1;
        ph[kc][0] = packsplit(sacc[t0][0], sacc[t0][1], pl[kc][0]);
        ph[kc][1] = packsplit(sacc[t0][2], sacc[t0][3], pl[kc][1]);
        ph[kc][2] = packsplit(sacc[t1][0], sacc[t1][1], pl[kc][2]);
        ph[kc][3] = packsplit(sacc[t1][2], sacc[t1][3], pl[kc][3]);
    }

    // O = P V (+ emulation): 4 d8-tiles, 4 k-chunks of 16.
    float oacc[4][4];
#pragma unroll
    for (int jd = 0; jd < 4; jd++)
#pragma unroll
        for (int t = 0; t < 4; t++) oacc[jd][t] = 0.f;

    {
        const int vrow = lane & 15;
#pragma unroll
        for (int kc = 0; kc < 4; kc++)
#pragma unroll
            for (int jd = 0; jd < 4; jd++) {
                uint32_t vh[2], vl[2];
                ldm_x2t(vh, smem_u32(&sVh[16 * kc + vrow][jd * 8]));
                ldm_x2t(vl, smem_u32(&sVl[16 * kc + vrow][jd * 8]));
                mma16816(oacc[jd], ph[kc], vh[0], vh[1]);
                mma16816(oacc[jd], pl[kc], vh[0], vh[1]);
                mma16816(oacc[jd], ph[kc], vl[0], vl[1]);
            }
    }

    // Epilogue: normalize, optionally add LePE, split to bf16 hi/lo.
#pragma unroll
    for (int jd = 0; jd < 4; jd++) {
        float x0 = oacc[jd][0] * inv0, x1 = oacc[jd][1] * inv0;
        float y0 = oacc[jd][2] * inv1, y1 = oacc[jd][3] * inv1;
        const size_t o0 = base + (size_t)r0 * row_stride + jd * 8 + tig * 2;
        const size_t o1 = base + (size_t)r1 * row_stride + jd * 8 + tig * 2;
        if (FUSE) {
            const float2 lp0 = *(const float2*)(lepe + o0);
            const float2 lp1 = *(const float2*)(lepe + o1);
            x0 += lp0.x; x1 += lp0.y;
            y0 += lp1.x; y1 += lp1.y;
        }
        uint32_t lo;
        uint32_t hi = packsplit(x0, x1, lo);
        *(uint32_t*)(Ohi + o0) = hi;
        *(uint32_t*)(Olo + o0) = lo;
        hi = packsplit(y0, y1, lo);
        *(uint32_t*)(Ohi + o1) = hi;
        *(uint32_t*)(Olo + o1) = lo;
    }
}

// ---------------------------------------------------------------------------
extern "C" void kernel_launch(void* const* d_in, const int* in_sizes, int n_in,
                              void* d_out, int out_size)
{
    const float* x      = (const float*)d_in[0];
    const float* mask_h = (const float*)d_in[1];
    const float* mask_w = (const float*)d_in[2];
    const float* Wq = (const float*)d_in[3];
    const float* bq = (const float*)d_in[4];
    const float* Wk = (const float*)d_in[5];
    const float* bk = (const float*)d_in[6];
    const float* Wv = (const float*)d_in[7];
    const float* bv = (const float*)d_in[8];
    const float* Wl = (const float*)d_in[9];
    const float* bl = (const float*)d_in[10];
    const float* Wo = (const float*)d_in[11];
    const float* bo = (const float*)d_in[12];
    float* out = (float*)d_out;

    float *v, *lepe;
    __nv_bfloat16 *qhi, *qlo, *khi, *klo, *vhi, *vlo, *v1hi, *v1lo;
    __nv_bfloat16 *ahi, *alo, *whi, *wlo;
    cudaGetSymbolAddress((void**)&v,    g_v);
    cudaGetSymbolAddress((void**)&lepe, g_lepe);
    cudaGetSymbolAddress((void**)&qhi,  g_qhi);
    cudaGetSymbolAddress((void**)&qlo,  g_qlo);
    cudaGetSymbolAddress((void**)&khi,  g_khi);
    cudaGetSymbolAddress((void**)&klo,  g_klo);
    cudaGetSymbolAddress((void**)&vhi,  g_vhi);
    cudaGetSymbolAddress((void**)&vlo,  g_vlo);
    cudaGetSymbolAddress((void**)&v1hi, g_v1hi);
    cudaGetSymbolAddress((void**)&v1lo, g_v1lo);
    cudaGetSymbolAddress((void**)&ahi,  g_ahi);
    cudaGetSymbolAddress((void**)&alo,  g_alo);
    cudaGetSymbolAddress((void**)&whi,  g_whi);
    cudaGetSymbolAddress((void**)&wlo,  g_wlo);

    static int smem_set = 0;
    if (!smem_set) {
        cudaFuncSetAttribute(gemm_hmma,
                             cudaFuncAttributeMaxDynamicSharedMemorySize,
                             GEMM_SMEM);
        smem_set = 1;
    }

    const float scaling = 0.17677669529663687f;  // 32^-0.5

    // 1) All splits in one launch.
    split_all<<<8448, 256>>>(x, Wq, Wk, Wv, Wo, ahi, alo, whi, wlo);

    // 2) Fused QKV projection: emits q/k/v bf16 hi/lo; v also fp32 (for LePE).
    gemm_hmma<<<dim3(1, 256, 3), 512, GEMM_SMEM>>>(
        ahi, alo, whi, wlo, bq, bk, bv,
        qhi, qlo, khi, klo, vhi, vlo, v, nullptr,
        1.0f, scaling, 1.0f);

    // 3) LePE.
    lepe_kernel<<<ELEMS / 4 / 256, 256>>>(v, Wl, bl, lepe);

    dim3 attn_grid(8, 64, 8);
    // 4) Width-axis attention -> v1 (bf16 hi/lo).
    attn_hmma<false><<<attn_grid, 128>>>(qhi, qlo, khi, klo, vhi, vlo,
                                         mask_w, nullptr, v1hi, v1lo,
                                         /*y_stride=*/64 * 256, /*row_stride=*/256);
    // 5) Height-axis attention + LePE add + hi/lo split -> out-proj input.
    attn_hmma<true><<<attn_grid, 128>>>(qhi, qlo, khi, klo, v1hi, v1lo,
                                        mask_h, lepe, ahi, alo,
                                        /*y_stride=*/256, /*row_stride=*/64 * 256);

    // 6) Output projection (fp32 out).
    gemm_hmma<<<dim3(1, 256, 1), 512, GEMM_SMEM>>>(
        ahi, alo, whi + 3 * 65536, wlo + 3 * 65536, bo, bo, bo,
        nullptr, nullptr, nullptr, nullptr, nullptr, nullptr, nullptr, out,
        1.0f, 1.0f, 1.0f);
}

// round 12
// speedup vs baseline: 1.4789x; 1.0471x over previous
#include <cuda_runtime.h>
#include <cuda_bf16.h>
#include <cstdint>

// Problem constants: B=8, H=64, W=64, C=256, NUM_HEADS=8, KEY_DIM=32
#define M_TOT   32768
#define C_DIM   256
#define ELEMS   (M_TOT * C_DIM)   // 8388608

// ---------------- scratch (device globals; no allocation allowed) ----------
__device__ __align__(16) float g_v[ELEMS];
__device__ __align__(16) float g_lepe[ELEMS];

__device__ __align__(16) __nv_bfloat16 g_qhi[ELEMS];
__device__ __align__(16) __nv_bfloat16 g_qlo[ELEMS];
__device__ __align__(16) __nv_bfloat16 g_khi[ELEMS];
__device__ __align__(16) __nv_bfloat16 g_klo[ELEMS];
__device__ __align__(16) __nv_bfloat16 g_vhi[ELEMS];
__device__ __align__(16) __nv_bfloat16 g_vlo[ELEMS];
__device__ __align__(16) __nv_bfloat16 g_v1hi[ELEMS];
__device__ __align__(16) __nv_bfloat16 g_v1lo[ELEMS];
__device__ __align__(16) __nv_bfloat16 g_ahi[ELEMS];
__device__ __align__(16) __nv_bfloat16 g_alo[ELEMS];
__device__ __align__(16) __nv_bfloat16 g_whi[4 * 65536];
__device__ __align__(16) __nv_bfloat16 g_wlo[4 * 65536];

// ---------------- helpers ---------------------------------------------------
__device__ __forceinline__ uint32_t smem_u32(const void* p) {
    uint32_t a;
    asm("{ .reg .u64 t; cvta.to.shared.u64 t, %1; cvt.u32.u64 %0, t; }"
        : "=r"(a) : "l"(p));
    return a;
}

__device__ __forceinline__ void cpa16(uint32_t dst, const void* src) {
    asm volatile("cp.async.ca.shared.global [%0], [%1], 16;"
                 :: "r"(dst), "l"(src));
}

__device__ __forceinline__ void mma16816(float* c, const uint32_t* a,
                                         uint32_t b0, uint32_t b1)
{
    asm volatile(
        "mma.sync.aligned.m16n8k16.row.col.f32.bf16.bf16.f32 "
        "{%0,%1,%2,%3}, {%4,%5,%6,%7}, {%8,%9}, {%0,%1,%2,%3};"
        : "+f"(c[0]), "+f"(c[1]), "+f"(c[2]), "+f"(c[3])
        : "r"(a[0]), "r"(a[1]), "r"(a[2]), "r"(a[3]), "r"(b0), "r"(b1));
}

__device__ __forceinline__ void ldm_x4(uint32_t* r, uint32_t addr) {
    asm volatile("ldmatrix.sync.aligned.m8n8.x4.shared.b16 {%0,%1,%2,%3}, [%4];"
        : "=r"(r[0]), "=r"(r[1]), "=r"(r[2]), "=r"(r[3]) : "r"(addr));
}

__device__ __forceinline__ void ldm_x2t(uint32_t* r, uint32_t addr) {
    asm volatile("ldmatrix.sync.aligned.m8n8.x2.trans.shared.b16 {%0,%1}, [%2];"
        : "=r"(r[0]), "=r"(r[1]) : "r"(addr));
}

// Split pair (x0 -> low 16, x1 -> high 16) into bf16 hi word; residual lo word.
__device__ __forceinline__ uint32_t packsplit(float x0, float x1, uint32_t& lo) {
    __nv_bfloat16 h0 = __float2bfloat16(x0), h1 = __float2bfloat16(x1);
    float r0 = x0 - __bfloat162float(h0);
    float r1 = x1 - __bfloat162float(h1);
    __nv_bfloat16 l0 = __float2bfloat16(r0), l1 = __float2bfloat16(r1);
    lo = (uint32_t)__bfloat16_as_ushort(l0) |
         ((uint32_t)__bfloat16_as_ushort(l1) << 16);
    return (uint32_t)__bfloat16_as_ushort(h0) |
           ((uint32_t)__bfloat16_as_ushort(h1) << 16);
}

// ---------------------------------------------------------------------------
// Merged split kernel: blocks [0, 8192) split x; blocks [8192, 8448) split W.
// ---------------------------------------------------------------------------
__global__ __launch_bounds__(256)
void split_all(const float* __restrict__ x,
               const float* __restrict__ W0, const float* __restrict__ W1,
               const float* __restrict__ W2, const float* __restrict__ W3,
               __nv_bfloat16* __restrict__ xhi, __nv_bfloat16* __restrict__ xlo,
               __nv_bfloat16* __restrict__ whi, __nv_bfloat16* __restrict__ wlo)
{
    if (blockIdx.x < 8192) {
        const int i = blockIdx.x * 256 + threadIdx.x;
        float4 v = ((const float4*)x)[i];
        uint32_t l0, l1;
        uint32_t h0 = packsplit(v.x, v.y, l0);
        uint32_t h1 = packsplit(v.z, v.w, l1);
        ((uint2*)xhi)[i] = make_uint2(h0, h1);
        ((uint2*)xlo)[i] = make_uint2(l0, l1);
    } else {
        const int wblk = blockIdx.x - 8192;
        const int w = wblk >> 6;
        const float* W = (w == 0) ? W0 : (w == 1) ? W1 : (w == 2) ? W2 : W3;
        const int i = (wblk & 63) * 256 + threadIdx.x;
        float4 v = ((const float4*)W)[i];
        uint32_t l0, l1;
        uint32_t h0 = packsplit(v.x, v.y, l0);
        uint32_t h1 = packsplit(v.z, v.w, l1);
        ((uint2*)whi)[w * 16384 + i] = make_uint2(h0, h1);
        ((uint2*)wlo)[w * 16384 + i] = make_uint2(l0, l1);
    }
}

// ---------------------------------------------------------------------------
// HMMA GEMM, fp32 emulation (hi/lo bf16, 3 products), cp.async double buffer.
// CTA tile 128x256 (full N), 512 threads = 16 warps (4m x 4n), warp tile 32x64.
// ---------------------------------------------------------------------------
#define A_TILE_B  10240        // 128 * 80
#define B_TILE_B  20480        // 256 * 80
#define STAGE_B   (2 * A_TILE_B + 2 * B_TILE_B)   // 61440
#define GEMM_SMEM (2 * STAGE_B)                   // 122880

__global__ __launch_bounds__(512)
void gemm_hmma(const __nv_bfloat16* __restrict__ Ahi,
               const __nv_bfloat16* __restrict__ Alo,
               const __nv_bfloat16* __restrict__ Whi,
               const __nv_bfloat16* __restrict__ Wlo,
               const float* __restrict__ bias0, const float* __restrict__ bias1,
               const float* __restrict__ bias2,
               __nv_bfloat16* __restrict__ h0, __nv_bfloat16* __restrict__ l0p,
               __nv_bfloat16* __restrict__ h1, __nv_bfloat16* __restrict__ l1p,
               __nv_bfloat16* __restrict__ h2, __nv_bfloat16* __restrict__ l2p,
               float* __restrict__ f2,     // fp32 out for z==2 (v)
               float* __restrict__ fout,   // if set: fp32-only output (out proj)
               float sc0, float sc1, float sc2)
{
    extern __shared__ __align__(16) char gsm[];

    const int z = blockIdx.z;
    const __nv_bfloat16* Bhi = Whi + z * 65536;
    const __nv_bfloat16* Blo = Wlo + z * 65536;
    const float* bias = (z == 0) ? bias0 : (z == 1) ? bias1 : bias2;
    const float scale = (z == 0) ? sc0   : (z == 1) ? sc1   : sc2;

    __nv_bfloat16 *ohi, *olo;
    float* of;
    if (fout) { of = fout; ohi = nullptr; olo = nullptr; }
    else {
        ohi = (z == 0) ? h0 : (z == 1) ? h1 : h2;
        olo = (z == 0) ? l0p : (z == 1) ? l1p : l2p;
        of  = (z == 2) ? f2 : nullptr;
    }

    const int tid  = threadIdx.x;
    const int lane = tid & 31;
    const int warp = tid >> 5;
    const int wm   = warp >> 2;
    const int wn   = warp & 3;
    const int m0   = blockIdx.y * 128;
    const int gid  = lane >> 2;
    const int tig  = lane & 3;

    float acc[2][8][4];
#pragma unroll
    for (int i = 0; i < 2; i++)
#pragma unroll
        for (int j = 0; j < 8; j++)
#pragma unroll
            for (int t = 0; t < 4; t++) acc[i][j][t] = 0.f;

    const uint4* gAh = (const uint4*)Ahi + (size_t)m0 * 32;
    const uint4* gAl = (const uint4*)Alo + (size_t)m0 * 32;
    const uint4* gBh = (const uint4*)Bhi;
    const uint4* gBl = (const uint4*)Blo;
    const uint32_t smem_base = smem_u32(gsm);

    auto issue = [&](int chunk, int stg) {
        const int kq4 = chunk * 4;
        const uint32_t sb = smem_base + stg * STAGE_B;
        {
            const int r = tid >> 2, q = tid & 3;
            const uint32_t off = (uint32_t)(r * 80 + q * 16);
            cpa16(sb + off,            gAh + (size_t)r * 32 + kq4 + q);
            cpa16(sb + A_TILE_B + off, gAl + (size_t)r * 32 + kq4 + q);
        }
#pragma unroll
        for (int rep = 0; rep < 2; rep++) {
            const int li = rep * 512 + tid;
            const int r = li >> 2, q = li & 3;
            const uint32_t off = (uint32_t)(r * 80 + q * 16);
            cpa16(sb + 2 * A_TILE_B + off,
                  gBh + (size_t)r * 32 + kq4 + q);
            cpa16(sb + 2 * A_TILE_B + B_TILE_B + off,
                  gBl + (size_t)r * 32 + kq4 + q);
        }
    };

    issue(0, 0);
    asm volatile("cp.async.commit_group;" ::: "memory");

    for (int c = 0; c < 8; c++) {
        if (c + 1 < 8) issue(c + 1, (c + 1) & 1);
        asm volatile("cp.async.commit_group;" ::: "memory");
        asm volatile("cp.async.wait_group 1;" ::: "memory");
        __syncthreads();

        const uint32_t sb  = smem_base + (c & 1) * STAGE_B;
        const uint32_t sAh = sb, sAl = sb + A_TILE_B;
        const uint32_t sBh = sb + 2 * A_TILE_B;
        const uint32_t sBl = sb + 2 * A_TILE_B + B_TILE_B;

#pragma unroll
        for (int ks = 0; ks < 2; ks++) {
            const int kb = ks * 16;
            uint32_t ah[2][4], al[2][4];
            const int arow = wm * 32 + (lane & 15);
            const int acol = kb + ((lane >> 4) << 3);
#pragma unroll
            for (int i = 0; i < 2; i++) {
                const uint32_t off = (uint32_t)((arow + i * 16) * 80 + acol * 2);
                ldm_x4(ah[i], sAh + off);
                ldm_x4(al[i], sAl + off);
            }
            const int brow0 = wn * 64 + ((lane >> 4) & 1) * 8 + (lane & 7);
            const int bcol  = kb + ((lane >> 3) & 1) * 8;
#pragma unroll
            for (int jp = 0; jp < 4; jp++) {
                uint32_t bh[4], bl[4];
                const uint32_t off = (uint32_t)((brow0 + jp * 16) * 80 + bcol * 2);
                ldm_x4(bh, sBh + off);
                ldm_x4(bl, sBl + off);
#pragma unroll
                for (int jj = 0; jj < 2; jj++) {
                    const int j = jp * 2 + jj;
#pragma unroll
                    for (int i = 0; i < 2; i++) {
                        mma16816(acc[i][j], ah[i], bh[jj * 2], bh[jj * 2 + 1]);
                        mma16816(acc[i][j], al[i], bh[jj * 2], bh[jj * 2 + 1]);
                        mma16816(acc[i][j], ah[i], bl[jj * 2], bl[jj * 2 + 1]);
                    }
                }
            }
        }
        __syncthreads();
    }

    // Epilogue
#pragma unroll
    for (int i = 0; i < 2; i++) {
        const int row = m0 + wm * 32 + i * 16 + gid;
#pragma unroll
        for (int j = 0; j < 8; j++) {
            const int col = wn * 64 + j * 8 + tig * 2;
            const float b0 = bias[col], b1 = bias[col + 1];
            const float x0 = (acc[i][j][0] + b0) * scale;
            const float x1 = (acc[i][j][1] + b1) * scale;
            const float y0 = (acc[i][j][2] + b0) * scale;
            const float y1 = (acc[i][j][3] + b1) * scale;
            const size_t o0 = (size_t)row * 256 + col;
            const size_t o1 = o0 + 8 * 256;
            if (ohi) {
                uint32_t lo;
                uint32_t hi = packsplit(x0, x1, lo);
                *(uint32_t*)(ohi + o0) = hi;
                *(uint32_t*)(olo + o0) = lo;
                hi = packsplit(y0, y1, lo);
                *(uint32_t*)(ohi + o1) = hi;
                *(uint32_t*)(olo + o1) = lo;
            }
            if (of) {
                *(float2*)(of + o0) = make_float2(x0, x1);
                *(float2*)(of + o1) = make_float2(y0, y1);
            }
        }
    }
}

// ---------------------------------------------------------------------------
// LePE: 5x5 depthwise conv, register-blocked 4 x-outputs per thread.
// ---------------------------------------------------------------------------
__global__ __launch_bounds__(256)
void lepe_kernel(const float* __restrict__ V,
                 const float* __restrict__ Wl,
                 const float* __restrict__ bl,
                 float* __restrict__ out)
{
    const int idx = blockIdx.x * 256 + threadIdx.x;
    const int c  = idx & 255;
    const int xg = (idx >> 8) & 15;
    const int y  = (idx >> 12) & 63;
    const int b  = idx >> 18;
    const int x0 = xg * 4;

    float w[5][5];
#pragma unroll
    for (int dy = 0; dy < 5; dy++)
#pragma unroll
        for (int dx = 0; dx < 5; dx++)
            w[dy][dx] = Wl[(dy * 5 + dx) * 256 + c];

    const float bias = bl[c];
    float acc[4] = {bias, bias, bias, bias};

#pragma unroll
    for (int dy = 0; dy < 5; dy++) {
        const int yy = y + dy - 2;
        if (yy < 0 || yy > 63) continue;
        const float* vrow = V + (size_t)(((b << 6) + yy) << 6) * 256 + c;
#pragma unroll
        for (int e = 0; e < 8; e++) {
            const int xx = x0 - 2 + e;
            if (xx < 0 || xx > 63) continue;
            const float val = vrow[(size_t)xx * 256];
#pragma unroll
            for (int u = 0; u < 4; u++) {
                const int dxi = e - u;
                if (dxi >= 0 && dxi < 5) acc[u] += val * w[dy][dxi];
            }
        }
    }

    float* orow = out + (size_t)((((b << 6) + y) << 6) + x0) * 256 + c;
#pragma unroll
    for (int u = 0; u < 4; u++) orow[(size_t)u * 256] = acc[u];
}

// ---------------------------------------------------------------------------
// HMMA axis attention, 2 heads per block (adjacent channels -> 128B rows).
// 256 threads = 2 warp-groups of 4; group wg handles head n = 2*blockIdx.x+wg.
// Tile rows: 64 bf16 (2 heads), smem row stride 144B (conflict-free ldmatrix).
// Staging via cp.async; fragment math identical to the proven single-head path.
// FUSE: add LePE and write bf16 hi/lo for the output projection input.
// ---------------------------------------------------------------------------
#define AT_ROW   144                   // bytes per smem row (64 elems + pad)
#define AT_TILE  (64 * AT_ROW)         // 9216 B per tensor tile
#define AT_SMEM  (6 * AT_TILE)         // 55296 B

template <bool FUSE>
__global__ __launch_bounds__(256)
void attn_hmma2(const __nv_bfloat16* __restrict__ Qhi, const __nv_bfloat16* __restrict__ Qlo,
                const __nv_bfloat16* __restrict__ Khi, const __nv_bfloat16* __restrict__ Klo,
                const __nv_bfloat16* __restrict__ Vhi, const __nv_bfloat16* __restrict__ Vlo,
                const float* __restrict__ mask,
                const float* __restrict__ lepe,
                __nv_bfloat16* __restrict__ Ohi, __nv_bfloat16* __restrict__ Olo,
                int y_stride, int row_stride)
{
    extern __shared__ __align__(16) char asm_[];
    const uint32_t sm = smem_u32(asm_);
    const uint32_t sQh = sm, sQl = sm + AT_TILE;
    const uint32_t sKh = sm + 2 * AT_TILE, sKl = sm + 3 * AT_TILE;
    const uint32_t sVh = sm + 4 * AT_TILE, sVl = sm + 5 * AT_TILE;

    const int np = blockIdx.x;            // head pair 0..3
    const int y  = blockIdx.y;
    const int b  = blockIdx.z;
    const int tid  = threadIdx.x;
    const int lane = tid & 31;
    const int wg   = tid >> 7;            // 0/1: which head
    const int w    = (tid >> 5) & 3;      // warp within group
    const int gid  = lane >> 2;
    const int tig  = lane & 3;
    const int n    = np * 2 + wg;
    const int hb   = wg * 64;             // head byte offset within smem row

    // base points at channel np*64 (two heads, 64 contiguous elems per row)
    const size_t base = (size_t)b * (64 * 64 * 256) + (size_t)y * y_stride
                        + np * 64;

    // Stage 6 tiles: 64 rows x 128B each, fully 128B-coalesced.
#pragma unroll
    for (int i = tid; i < 512; i += 256) {
        const int r = i >> 3, c8 = (i & 7) * 8;       // elem col 0..56
        const size_t g = base + (size_t)r * row_stride + c8;
        const uint32_t so = (uint32_t)(r * AT_ROW + c8 * 2);
        cpa16(sQh + so, Qhi + g);
        cpa16(sQl + so, Qlo + g);
        cpa16(sKh + so, Khi + g);
        cpa16(sKl + so, Klo + g);
        cpa16(sVh + so, Vhi + g);
        cpa16(sVl + so, Vlo + g);
    }
    asm volatile("cp.async.commit_group;" ::: "memory");
    asm volatile("cp.async.wait_group 0;" ::: "memory");
    __syncthreads();

    // Q fragments: m16k16 x 2 k-chunks (head-local columns).
    uint32_t qh[2][4], ql[2][4];
    {
        const int arow = 16 * w + (lane & 15);
        const int acol = (lane >> 4) << 3;
#pragma unroll
        for (int kc = 0; kc < 2; kc++) {
            const uint32_t off = (uint32_t)(arow * AT_ROW + hb
                                            + (kc * 16 + acol) * 2);
            ldm_x4(qh[kc], sQh + off);
            ldm_x4(ql[kc], sQl + off);
        }
    }

    // S = Q K^T (+ emulation), 8 n8-tiles.
    float sacc[8][4];
#pragma unroll
    for (int j = 0; j < 8; j++)
#pragma unroll
        for (int t = 0; t < 4; t++) sacc[j][t] = 0.f;

    {
        const int krow = ((lane >> 4) & 1) * 8 + (lane & 7);
        const int kcol = ((lane >> 3) & 1) * 8;
#pragma unroll
        for (int kc = 0; kc < 2; kc++)
#pragma unroll
            for (int jp = 0; jp < 4; jp++) {
                uint32_t kh[4], kl[4];
                const uint32_t off = (uint32_t)((16 * jp + krow) * AT_ROW + hb
                                                + (kc * 16 + kcol) * 2);
                ldm_x4(kh, sKh + off);
                ldm_x4(kl, sKl + off);
#pragma unroll
                for (int jj = 0; jj < 2; jj++) {
                    const int j = jp * 2 + jj;
                    mma16816(sacc[j], qh[kc], kh[jj * 2], kh[jj * 2 + 1]);
                    mma16816(sacc[j], ql[kc], kh[jj * 2], kh[jj * 2 + 1]);
                    mma16816(sacc[j], qh[kc], kl[jj * 2], kl[jj * 2 + 1]);
                }
            }
    }

    // Mask add + softmax on fragments (rows r0=16w+gid, r1=r0+8).
    const int r0 = 16 * w + gid;
    const int r1 = r0 + 8;
    const float* mbase = mask + (size_t)n * 4096;
    float mx0 = -1e30f, mx1 = -1e30f;
#pragma unroll
    for (int j = 0; j < 8; j++) {
        const float2 m0 = *(const float2*)(mbase + r0 * 64 + j * 8 + tig * 2);
        const float2 m1 = *(const float2*)(mbase + r1 * 64 + j * 8 + tig * 2);
        sacc[j][0] += m0.x; sacc[j][1] += m0.y;
        sacc[j][2] += m1.x; sacc[j][3] += m1.y;
        mx0 = fmaxf(mx0, fmaxf(sacc[j][0], sacc[j][1]));
        mx1 = fmaxf(mx1, fmaxf(sacc[j][2], sacc[j][3]));
    }
    mx0 = fmaxf(mx0, __shfl_xor_sync(0xffffffffu, mx0, 1));
    mx0 = fmaxf(mx0, __shfl_xor_sync(0xffffffffu, mx0, 2));
    mx1 = fmaxf(mx1, __shfl_xor_sync(0xffffffffu, mx1, 1));
    mx1 = fmaxf(mx1, __shfl_xor_sync(0xffffffffu, mx1, 2));

    float sum0 = 0.f, sum1 = 0.f;
#pragma unroll
    for (int j = 0; j < 8; j++) {
        sacc[j][0] = __expf(sacc[j][0] - mx0);
        sacc[j][1] = __expf(sacc[j][1] - mx0);
        sacc[j][2] = __expf(sacc[j][2] - mx1);
        sacc[j][3] = __expf(sacc[j][3] - mx1);
        sum0 += sacc[j][0] + sacc[j][1];
        sum1 += sacc[j][2] + sacc[j][3];
    }
    sum0 += __shfl_xor_sync(0xffffffffu, sum0, 1);
    sum0 += __shfl_xor_sync(0xffffffffu, sum0, 2);
    sum1 += __shfl_xor_sync(0xffffffffu, sum1, 1);
    sum1 += __shfl_xor_sync(0xffffffffu, sum1, 2);
    const float inv0 = 1.f / sum0;
    const float inv1 = 1.f / sum1;

    // Repack P (unnormalized) into A-fragments, hi/lo bf16.
    uint32_t ph[4][4], pl[4][4];
#pragma unroll
    for (int kc = 0; kc < 4; kc++) {
        const int t0 = 2 * kc, t1 = 2 * kc + 1;
        ph[kc][0] = packsplit(sacc[t0][0], sacc[t0][1], pl[kc][0]);
        ph[kc][1] = packsplit(sacc[t0][2], sacc[t0][3], pl[kc][1]);
        ph[kc][2] = packsplit(sacc[t1][0], sacc[t1][1], pl[kc][2]);
        ph[kc][3] = packsplit(sacc[t1][2], sacc[t1][3], pl[kc][3]);
    }

    // O = P V (+ emulation): 4 d8-tiles, 4 k-chunks of 16.
    float oacc[4][4];
#pragma unroll
    for (int jd = 0; jd < 4; jd++)
#pragma unroll
        for (int t = 0; t < 4; t++) oacc[jd][t] = 0.f;

    {
        const int vrow = lane & 15;
#pragma unroll
        for (int kc = 0; kc < 4; kc++)
#pragma unroll
            for (int jd = 0; jd < 4; jd++) {
                uint32_t vh[2], vl[2];
                const uint32_t off = (uint32_t)((16 * kc + vrow) * AT_ROW + hb
                                                + jd * 16);
                ldm_x2t(vh, sVh + off);
                ldm_x2t(vl, sVl + off);
                mma16816(oacc[jd], ph[kc], vh[0], vh[1]);
                mma16816(oacc[jd], pl[kc], vh[0], vh[1]);
                mma16816(oacc[jd], ph[kc], vl[0], vl[1]);
            }
    }

    // Epilogue: normalize, optionally add LePE, split to bf16 hi/lo.
#pragma unroll
    for (int jd = 0; jd < 4; jd++) {
        float x0 = oacc[jd][0] * inv0, x1 = oacc[jd][1] * inv0;
        float y0 = oacc[jd][2] * inv1, y1 = oacc[jd][3] * inv1;
        const int d = wg * 32 + jd * 8 + tig * 2;
        const size_t o0 = base + (size_t)r0 * row_stride + d;
        const size_t o1 = base + (size_t)r1 * row_stride + d;
        if (FUSE) {
            const float2 lp0 = *(const float2*)(lepe + o0);
            const float2 lp1 = *(const float2*)(lepe + o1);
            x0 += lp0.x; x1 += lp0.y;
            y0 += lp1.x; y1 += lp1.y;
        }
        uint32_t lo;
        uint32_t hi = packsplit(x0, x1, lo);
        *(uint32_t*)(Ohi + o0) = hi;
        *(uint32_t*)(Olo + o0) = lo;
        hi = packsplit(y0, y1, lo);
        *(uint32_t*)(Ohi + o1) = hi;
        *(uint32_t*)(Olo + o1) = lo;
    }
}

// ---------------------------------------------------------------------------
extern "C" void kernel_launch(void* const* d_in, const int* in_sizes, int n_in,
                              void* d_out, int out_size)
{
    const float* x      = (const float*)d_in[0];
    const float* mask_h = (const float*)d_in[1];
    const float* mask_w = (const float*)d_in[2];
    const float* Wq = (const float*)d_in[3];
    const float* bq = (const float*)d_in[4];
    const float* Wk = (const float*)d_in[5];
    const float* bk = (const float*)d_in[6];
    const float* Wv = (const float*)d_in[7];
    const float* bv = (const float*)d_in[8];
    const float* Wl = (const float*)d_in[9];
    const float* bl = (const float*)d_in[10];
    const float* Wo = (const float*)d_in[11];
    const float* bo = (const float*)d_in[12];
    float* out = (float*)d_out;

    float *v, *lepe;
    __nv_bfloat16 *qhi, *qlo, *khi, *klo, *vhi, *vlo, *v1hi, *v1lo;
    __nv_bfloat16 *ahi, *alo, *whi, *wlo;
    cudaGetSymbolAddress((void**)&v,    g_v);
    cudaGetSymbolAddress((void**)&lepe, g_lepe);
    cudaGetSymbolAddress((void**)&qhi,  g_qhi);
    cudaGetSymbolAddress((void**)&qlo,  g_qlo);
    cudaGetSymbolAddress((void**)&khi,  g_khi);
    cudaGetSymbolAddress((void**)&klo,  g_klo);
    cudaGetSymbolAddress((void**)&vhi,  g_vhi);
    cudaGetSymbolAddress((void**)&vlo,  g_vlo);
    cudaGetSymbolAddress((void**)&v1hi, g_v1hi);
    cudaGetSymbolAddress((void**)&v1lo, g_v1lo);
    cudaGetSymbolAddress((void**)&ahi,  g_ahi);
    cudaGetSymbolAddress((void**)&alo,  g_alo);
    cudaGetSymbolAddress((void**)&whi,  g_whi);
    cudaGetSymbolAddress((void**)&wlo,  g_wlo);

    static int smem_set = 0;
    if (!smem_set) {
        cudaFuncSetAttribute(gemm_hmma,
                             cudaFuncAttributeMaxDynamicSharedMemorySize,
                             GEMM_SMEM);
        cudaFuncSetAttribute(attn_hmma2<false>,
                             cudaFuncAttributeMaxDynamicSharedMemorySize,
                             AT_SMEM);
        cudaFuncSetAttribute(attn_hmma2<true>,
                             cudaFuncAttributeMaxDynamicSharedMemorySize,
                             AT_SMEM);
        smem_set = 1;
    }

    const float scaling = 0.17677669529663687f;  // 32^-0.5

    // 1) All splits in one launch.
    split_all<<<8448, 256>>>(x, Wq, Wk, Wv, Wo, ahi, alo, whi, wlo);

    // 2) Fused QKV projection: emits q/k/v bf16 hi/lo; v also fp32 (for LePE).
    gemm_hmma<<<dim3(1, 256, 3), 512, GEMM_SMEM>>>(
        ahi, alo, whi, wlo, bq, bk, bv,
        qhi, qlo, khi, klo, vhi, vlo, v, nullptr,
        1.0f, scaling, 1.0f);

    // 3) LePE.
    lepe_kernel<<<ELEMS / 4 / 256, 256>>>(v, Wl, bl, lepe);

    dim3 attn_grid(4, 64, 8);   // head pairs x line x batch
    // 4) Width-axis attention -> v1 (bf16 hi/lo).
    attn_hmma2<false><<<attn_grid, 256, AT_SMEM>>>(
        qhi, qlo, khi, klo, vhi, vlo, mask_w, nullptr, v1hi, v1lo,
        /*y_stride=*/64 * 256, /*row_stride=*/256);
    // 5) Height-axis attention + LePE add + hi/lo split -> out-proj input.
    attn_hmma2<true><<<attn_grid, 256, AT_SMEM>>>(
        qhi, qlo, khi, klo, v1hi, v1lo, mask_h, lepe, ahi, alo,
        /*y_stride=*/256, /*row_stride=*/64 * 256);

    // 6) Output projection (fp32 out).
    gemm_hmma<<<dim3(1, 256, 1), 512, GEMM_SMEM>>>(
        ahi, alo, whi + 3 * 65536, wlo + 3 * 65536, bo, bo, bo,
        nullptr, nullptr, nullptr, nullptr, nullptr, nullptr, nullptr, out,
        1.0f, 1.0f, 1.0f);
}

// round 13
// speedup vs baseline: 1.7084x; 1.1552x over previous
#include <cuda_runtime.h>
#include <cuda_bf16.h>
#include <cuda_fp16.h>
#include <cstdint>

// Problem constants: B=8, H=64, W=64, C=256, NUM_HEADS=8, KEY_DIM=32
#define M_TOT   32768
#define C_DIM   256
#define ELEMS   (M_TOT * C_DIM)   // 8388608

// ---------------- scratch (device globals; no allocation allowed) ----------
__device__ __align__(16) float g_v[ELEMS];
__device__ __align__(16) float g_lepe[ELEMS];

// GEMM-side (fp16 emulation): A hi/lo, W single fp16
__device__ __align__(16) __half g_xh[ELEMS];
__device__ __align__(16) __half g_xl[ELEMS];
__device__ __align__(16) __half g_ah[ELEMS];     // attn+lepe hi (out-proj A)
__device__ __align__(16) __half g_al[ELEMS];     // attn+lepe lo
__device__ __align__(16) __half g_wh[4 * 65536]; // Wq,Wk,Wv,Wo fp16

// Attention-side (bf16 emulation, proven path)
__device__ __align__(16) __nv_bfloat16 g_qhi[ELEMS];
__device__ __align__(16) __nv_bfloat16 g_qlo[ELEMS];
__device__ __align__(16) __nv_bfloat16 g_khi[ELEMS];
__device__ __align__(16) __nv_bfloat16 g_klo[ELEMS];
__device__ __align__(16) __nv_bfloat16 g_vhi[ELEMS];
__device__ __align__(16) __nv_bfloat16 g_vlo[ELEMS];
__device__ __align__(16) __nv_bfloat16 g_v1hi[ELEMS];
__device__ __align__(16) __nv_bfloat16 g_v1lo[ELEMS];

// ---------------- helpers ---------------------------------------------------
__device__ __forceinline__ uint32_t smem_u32(const void* p) {
    uint32_t a;
    asm("{ .reg .u64 t; cvta.to.shared.u64 t, %1; cvt.u32.u64 %0, t; }"
        : "=r"(a) : "l"(p));
    return a;
}

__device__ __forceinline__ void cpa16(uint32_t dst, const void* src) {
    asm volatile("cp.async.ca.shared.global [%0], [%1], 16;"
                 :: "r"(dst), "l"(src));
}

// bf16 MMA (attention path)
__device__ __forceinline__ void mma_bf16(float* c, const uint32_t* a,
                                         uint32_t b0, uint32_t b1)
{
    asm volatile(
        "mma.sync.aligned.m16n8k16.row.col.f32.bf16.bf16.f32 "
        "{%0,%1,%2,%3}, {%4,%5,%6,%7}, {%8,%9}, {%0,%1,%2,%3};"
        : "+f"(c[0]), "+f"(c[1]), "+f"(c[2]), "+f"(c[3])
        : "r"(a[0]), "r"(a[1]), "r"(a[2]), "r"(a[3]), "r"(b0), "r"(b1));
}

// fp16 MMA (GEMM path)
__device__ __forceinline__ void mma_f16(float* c, const uint32_t* a,
                                        uint32_t b0, uint32_t b1)
{
    asm volatile(
        "mma.sync.aligned.m16n8k16.row.col.f32.f16.f16.f32 "
        "{%0,%1,%2,%3}, {%4,%5,%6,%7}, {%8,%9}, {%0,%1,%2,%3};"
        : "+f"(c[0]), "+f"(c[1]), "+f"(c[2]), "+f"(c[3])
        : "r"(a[0]), "r"(a[1]), "r"(a[2]), "r"(a[3]), "r"(b0), "r"(b1));
}

__device__ __forceinline__ void ldm_x4(uint32_t* r, uint32_t addr) {
    asm volatile("ldmatrix.sync.aligned.m8n8.x4.shared.b16 {%0,%1,%2,%3}, [%4];"
        : "=r"(r[0]), "=r"(r[1]), "=r"(r[2]), "=r"(r[3]) : "r"(addr));
}

__device__ __forceinline__ void ldm_x2t(uint32_t* r, uint32_t addr) {
    asm volatile("ldmatrix.sync.aligned.m8n8.x2.trans.shared.b16 {%0,%1}, [%2];"
        : "=r"(r[0]), "=r"(r[1]) : "r"(addr));
}

// bf16 hi/lo split pack
__device__ __forceinline__ uint32_t packsplit(float x0, float x1, uint32_t& lo) {
    __nv_bfloat16 h0 = __float2bfloat16(x0), h1 = __float2bfloat16(x1);
    float r0 = x0 - __bfloat162float(h0);
    float r1 = x1 - __bfloat162float(h1);
    __nv_bfloat16 l0 = __float2bfloat16(r0), l1 = __float2bfloat16(r1);
    lo = (uint32_t)__bfloat16_as_ushort(l0) |
         ((uint32_t)__bfloat16_as_ushort(l1) << 16);
    return (uint32_t)__bfloat16_as_ushort(h0) |
           ((uint32_t)__bfloat16_as_ushort(h1) << 16);
}

// fp16 hi/lo split pack
__device__ __forceinline__ uint32_t packsplit_h(float x0, float x1, uint32_t& lo) {
    __half h0 = __float2half_rn(x0), h1 = __float2half_rn(x1);
    float r0 = x0 - __half2float(h0);
    float r1 = x1 - __half2float(h1);
    __half l0 = __float2half_rn(r0), l1 = __float2half_rn(r1);
    lo = (uint32_t)__half_as_ushort(l0) |
         ((uint32_t)__half_as_ushort(l1) << 16);
    return (uint32_t)__half_as_ushort(h0) |
           ((uint32_t)__half_as_ushort(h1) << 16);
}

// ---------------------------------------------------------------------------
// Merged split kernel: blocks [0, 8192) split x into fp16 hi/lo;
// blocks [8192, 8448) convert the four weight matrices to fp16.
// ---------------------------------------------------------------------------
__global__ __launch_bounds__(256)
void split_all(const float* __restrict__ x,
               const float* __restrict__ W0, const float* __restrict__ W1,
               const float* __restrict__ W2, const float* __restrict__ W3,
               __half* __restrict__ xh, __half* __restrict__ xl,
               __half* __restrict__ wh)
{
    if (blockIdx.x < 8192) {
        const int i = blockIdx.x * 256 + threadIdx.x;
        float4 v = ((const float4*)x)[i];
        uint32_t l0, l1;
        uint32_t h0 = packsplit_h(v.x, v.y, l0);
        uint32_t h1 = packsplit_h(v.z, v.w, l1);
        ((uint2*)xh)[i] = make_uint2(h0, h1);
        ((uint2*)xl)[i] = make_uint2(l0, l1);
    } else {
        const int wblk = blockIdx.x - 8192;
        const int w = wblk >> 6;
        const float* W = (w == 0) ? W0 : (w == 1) ? W1 : (w == 2) ? W2 : W3;
        const int i = (wblk & 63) * 256 + threadIdx.x;
        float4 v = ((const float4*)W)[i];
        const uint32_t p0 = (uint32_t)__half_as_ushort(__float2half_rn(v.x)) |
                            ((uint32_t)__half_as_ushort(__float2half_rn(v.y)) << 16);
        const uint32_t p1 = (uint32_t)__half_as_ushort(__float2half_rn(v.z)) |
                            ((uint32_t)__half_as_ushort(__float2half_rn(v.w)) << 16);
        ((uint2*)wh)[w * 16384 + i] = make_uint2(p0, p1);
    }
}

// ---------------------------------------------------------------------------
// fp16 HMMA GEMM, 2-product fp32 emulation: out = (Ah+Al) @ Bh^T exactly in A,
// W rounded to fp16 once (rel err ~1.4e-4).
// CTA tile 128x256 (full N), 512 threads = 16 warps (4m x 4n), warp tile 32x64.
// ---------------------------------------------------------------------------
#define A_TILE_B  10240        // 128 * 80
#define B_TILE_B  20480        // 256 * 80
#define STAGE_B   (2 * A_TILE_B + B_TILE_B)       // 40960
#define GEMM_SMEM (2 * STAGE_B)                   // 81920

__device__ __forceinline__
void gemm_main(float acc[2][8][4],
               const __half* __restrict__ Ah,
               const __half* __restrict__ Al,
               const __half* __restrict__ Bh,
               int m0, uint32_t smem_base)
{
    const int tid  = threadIdx.x;
    const int lane = tid & 31;
    const int warp = tid >> 5;
    const int wm   = warp >> 2;
    const int wn   = warp & 3;

    const uint4* gAh = (const uint4*)Ah + (size_t)m0 * 32;
    const uint4* gAl = (const uint4*)Al + (size_t)m0 * 32;
    const uint4* gBh = (const uint4*)Bh;

    auto issue = [&](int chunk, int stg) {
        const int kq4 = chunk * 4;
        const uint32_t sb = smem_base + stg * STAGE_B;
        {
            const int r = tid >> 2, q = tid & 3;
            const uint32_t off = (uint32_t)(r * 80 + q * 16);
            cpa16(sb + off,            gAh + (size_t)r * 32 + kq4 + q);
            cpa16(sb + A_TILE_B + off, gAl + (size_t)r * 32 + kq4 + q);
        }
#pragma unroll
        for (int rep = 0; rep < 2; rep++) {
            const int li = rep * 512 + tid;
            const int r = li >> 2, q = li & 3;
            const uint32_t off = (uint32_t)(r * 80 + q * 16);
            cpa16(sb + 2 * A_TILE_B + off,
                  gBh + (size_t)r * 32 + kq4 + q);
        }
    };

    issue(0, 0);
    asm volatile("cp.async.commit_group;" ::: "memory");

    for (int c = 0; c < 8; c++) {
        if (c + 1 < 8) issue(c + 1, (c + 1) & 1);
        asm volatile("cp.async.commit_group;" ::: "memory");
        asm volatile("cp.async.wait_group 1;" ::: "memory");
        __syncthreads();

        const uint32_t sb  = smem_base + (c & 1) * STAGE_B;
        const uint32_t sAh = sb, sAl = sb + A_TILE_B;
        const uint32_t sBh = sb + 2 * A_TILE_B;

#pragma unroll
        for (int ks = 0; ks < 2; ks++) {
            const int kb = ks * 16;
            uint32_t ah[2][4], al[2][4];
            const int arow = wm * 32 + (lane & 15);
            const int acol = kb + ((lane >> 4) << 3);
#pragma unroll
            for (int i = 0; i < 2; i++) {
                const uint32_t off = (uint32_t)((arow + i * 16) * 80 + acol * 2);
                ldm_x4(ah[i], sAh + off);
                ldm_x4(al[i], sAl + off);
            }
            const int brow0 = wn * 64 + ((lane >> 4) & 1) * 8 + (lane & 7);
            const int bcol  = kb + ((lane >> 3) & 1) * 8;
#pragma unroll
            for (int jp = 0; jp < 4; jp++) {
                uint32_t bh[4];
                const uint32_t off = (uint32_t)((brow0 + jp * 16) * 80 + bcol * 2);
                ldm_x4(bh, sBh + off);
#pragma unroll
                for (int jj = 0; jj < 2; jj++) {
                    const int j = jp * 2 + jj;
#pragma unroll
                    for (int i = 0; i < 2; i++) {
                        mma_f16(acc[i][j], ah[i], bh[jj * 2], bh[jj * 2 + 1]);
                        mma_f16(acc[i][j], al[i], bh[jj * 2], bh[jj * 2 + 1]);
                    }
                }
            }
        }
        __syncthreads();
    }
}

// ---------------------------------------------------------------------------
// QKV GEMM: grid.z selects q/k/v. Writes bf16 hi/lo (attention inputs);
// v additionally fp32 (LePE input).
// ---------------------------------------------------------------------------
__global__ __launch_bounds__(512)
void gemm_qkv(const __half* __restrict__ Ah, const __half* __restrict__ Al,
              const __half* __restrict__ Wh,
              const float* __restrict__ bq, const float* __restrict__ bk,
              const float* __restrict__ bv,
              __nv_bfloat16* __restrict__ qhi, __nv_bfloat16* __restrict__ qlo,
              __nv_bfloat16* __restrict__ khi, __nv_bfloat16* __restrict__ klo,
              __nv_bfloat16* __restrict__ vhi, __nv_bfloat16* __restrict__ vlo,
              float* __restrict__ vf, float kscale)
{
    extern __shared__ __align__(16) char gsm[];
    const int z = blockIdx.z;
    const int m0 = blockIdx.y * 128;

    float acc[2][8][4];
#pragma unroll
    for (int i = 0; i < 2; i++)
#pragma unroll
        for (int j = 0; j < 8; j++)
#pragma unroll
            for (int t = 0; t < 4; t++) acc[i][j][t] = 0.f;

    gemm_main(acc, Ah, Al, Wh + z * 65536, m0, smem_u32(gsm));

    const float* bias = (z == 0) ? bq : (z == 1) ? bk : bv;
    const float scale = (z == 1) ? kscale : 1.0f;
    __nv_bfloat16* ohi = (z == 0) ? qhi : (z == 1) ? khi : vhi;
    __nv_bfloat16* olo = (z == 0) ? qlo : (z == 1) ? klo : vlo;

    const int lane = threadIdx.x & 31;
    const int warp = threadIdx.x >> 5;
    const int wm = warp >> 2, wn = warp & 3;
    const int gid = lane >> 2, tig = lane & 3;

#pragma unroll
    for (int i = 0; i < 2; i++) {
        const int row = m0 + wm * 32 + i * 16 + gid;
#pragma unroll
        for (int j = 0; j < 8; j++) {
            const int col = wn * 64 + j * 8 + tig * 2;
            const float b0 = bias[col], b1 = bias[col + 1];
            const float x0 = (acc[i][j][0] + b0) * scale;
            const float x1 = (acc[i][j][1] + b1) * scale;
            const float y0 = (acc[i][j][2] + b0) * scale;
            const float y1 = (acc[i][j][3] + b1) * scale;
            const size_t o0 = (size_t)row * 256 + col;
            const size_t o1 = o0 + 8 * 256;
            uint32_t lo;
            uint32_t hi = packsplit(x0, x1, lo);
            *(uint32_t*)(ohi + o0) = hi;
            *(uint32_t*)(olo + o0) = lo;
            hi = packsplit(y0, y1, lo);
            *(uint32_t*)(ohi + o1) = hi;
            *(uint32_t*)(olo + o1) = lo;
            if (z == 2) {
                *(float2*)(vf + o0) = make_float2(x0, x1);
                *(float2*)(vf + o1) = make_float2(y0, y1);
            }
        }
    }
}

// ---------------------------------------------------------------------------
// Output projection GEMM: fp32 out.
// ---------------------------------------------------------------------------
__global__ __launch_bounds__(512)
void gemm_out(const __half* __restrict__ Ah, const __half* __restrict__ Al,
              const __half* __restrict__ Wh,
              const float* __restrict__ bias, float* __restrict__ out)
{
    extern __shared__ __align__(16) char gsm[];
    const int m0 = blockIdx.y * 128;

    float acc[2][8][4];
#pragma unroll
    for (int i = 0; i < 2; i++)
#pragma unroll
        for (int j = 0; j < 8; j++)
#pragma unroll
            for (int t = 0; t < 4; t++) acc[i][j][t] = 0.f;

    gemm_main(acc, Ah, Al, Wh, m0, smem_u32(gsm));

    const int lane = threadIdx.x & 31;
    const int warp = threadIdx.x >> 5;
    const int wm = warp >> 2, wn = warp & 3;
    const int gid = lane >> 2, tig = lane & 3;

#pragma unroll
    for (int i = 0; i < 2; i++) {
        const int row = m0 + wm * 32 + i * 16 + gid;
#pragma unroll
        for (int j = 0; j < 8; j++) {
            const int col = wn * 64 + j * 8 + tig * 2;
            const float b0 = bias[col], b1 = bias[col + 1];
            *(float2*)(out + (size_t)row * 256 + col) =
                make_float2(acc[i][j][0] + b0, acc[i][j][1] + b1);
            *(float2*)(out + (size_t)(row + 8) * 256 + col) =
                make_float2(acc[i][j][2] + b0, acc[i][j][3] + b1);
        }
    }
}

// ---------------------------------------------------------------------------
// LePE: 5x5 depthwise conv, register-blocked 4 x-outputs per thread.
// ---------------------------------------------------------------------------
__global__ __launch_bounds__(256)
void lepe_kernel(const float* __restrict__ V,
                 const float* __restrict__ Wl,
                 const float* __restrict__ bl,
                 float* __restrict__ out)
{
    const int idx = blockIdx.x * 256 + threadIdx.x;
    const int c  = idx & 255;
    const int xg = (idx >> 8) & 15;
    const int y  = (idx >> 12) & 63;
    const int b  = idx >> 18;
    const int x0 = xg * 4;

    float w[5][5];
#pragma unroll
    for (int dy = 0; dy < 5; dy++)
#pragma unroll
        for (int dx = 0; dx < 5; dx++)
            w[dy][dx] = Wl[(dy * 5 + dx) * 256 + c];

    const float bias = bl[c];
    float acc[4] = {bias, bias, bias, bias};

#pragma unroll
    for (int dy = 0; dy < 5; dy++) {
        const int yy = y + dy - 2;
        if (yy < 0 || yy > 63) continue;
        const float* vrow = V + (size_t)(((b << 6) + yy) << 6) * 256 + c;
#pragma unroll
        for (int e = 0; e < 8; e++) {
            const int xx = x0 - 2 + e;
            if (xx < 0 || xx > 63) continue;
            const float val = vrow[(size_t)xx * 256];
#pragma unroll
            for (int u = 0; u < 4; u++) {
                const int dxi = e - u;
                if (dxi >= 0 && dxi < 5) acc[u] += val * w[dy][dxi];
            }
        }
    }

    float* orow = out + (size_t)((((b << 6) + y) << 6) + x0) * 256 + c;
#pragma unroll
    for (int u = 0; u < 4; u++) orow[(size_t)u * 256] = acc[u];
}

// ---------------------------------------------------------------------------
// HMMA axis attention, 2 heads per block (R12 winner, bf16 3-product).
// FUSE=false: -> v1 bf16 hi/lo. FUSE=true: +LePE -> fp16 hi/lo (out-proj A).
// ---------------------------------------------------------------------------
#define AT_ROW   144
#define AT_TILE  (64 * AT_ROW)
#define AT_SMEM  (6 * AT_TILE)

template <bool FUSE>
__global__ __launch_bounds__(256)
void attn_hmma2(const __nv_bfloat16* __restrict__ Qhi, const __nv_bfloat16* __restrict__ Qlo,
                const __nv_bfloat16* __restrict__ Khi, const __nv_bfloat16* __restrict__ Klo,
                const __nv_bfloat16* __restrict__ Vhi, const __nv_bfloat16* __restrict__ Vlo,
                const float* __restrict__ mask,
                const float* __restrict__ lepe,
                __nv_bfloat16* __restrict__ Ohi, __nv_bfloat16* __restrict__ Olo,
                __half* __restrict__ HOhi, __half* __restrict__ HOlo,
                int y_stride, int row_stride)
{
    extern __shared__ __align__(16) char asm_[];
    const uint32_t sm = smem_u32(asm_);
    const uint32_t sQh = sm, sQl = sm + AT_TILE;
    const uint32_t sKh = sm + 2 * AT_TILE, sKl = sm + 3 * AT_TILE;
    const uint32_t sVh = sm + 4 * AT_TILE, sVl = sm + 5 * AT_TILE;

    const int np = blockIdx.x;
    const int y  = blockIdx.y;
    const int b  = blockIdx.z;
    const int tid  = threadIdx.x;
    const int lane = tid & 31;
    const int wg   = tid >> 7;
    const int w    = (tid >> 5) & 3;
    const int gid  = lane >> 2;
    const int tig  = lane & 3;
    const int n    = np * 2 + wg;
    const int hb   = wg * 64;

    const size_t base = (size_t)b * (64 * 64 * 256) + (size_t)y * y_stride
                        + np * 64;

#pragma unroll
    for (int i = tid; i < 512; i += 256) {
        const int r = i >> 3, c8 = (i & 7) * 8;
        const size_t g = base + (size_t)r * row_stride + c8;
        const uint32_t so = (uint32_t)(r * AT_ROW + c8 * 2);
        cpa16(sQh + so, Qhi + g);
        cpa16(sQl + so, Qlo + g);
        cpa16(sKh + so, Khi + g);
        cpa16(sKl + so, Klo + g);
        cpa16(sVh + so, Vhi + g);
        cpa16(sVl + so, Vlo + g);
    }
    asm volatile("cp.async.commit_group;" ::: "memory");
    asm volatile("cp.async.wait_group 0;" ::: "memory");
    __syncthreads();

    uint32_t qh[2][4], ql[2][4];
    {
        const int arow = 16 * w + (lane & 15);
        const int acol = (lane >> 4) << 3;
#pragma unroll
        for (int kc = 0; kc < 2; kc++) {
            const uint32_t off = (uint32_t)(arow * AT_ROW + hb
                                            + (kc * 16 + acol) * 2);
            ldm_x4(qh[kc], sQh + off);
            ldm_x4(ql[kc], sQl + off);
        }
    }

    float sacc[8][4];
#pragma unroll
    for (int j = 0; j < 8; j++)
#pragma unroll
        for (int t = 0; t < 4; t++) sacc[j][t] = 0.f;

    {
        const int krow = ((lane >> 4) & 1) * 8 + (lane & 7);
        const int kcol = ((lane >> 3) & 1) * 8;
#pragma unroll
        for (int kc = 0; kc < 2; kc++)
#pragma unroll
            for (int jp = 0; jp < 4; jp++) {
                uint32_t kh[4], kl[4];
                const uint32_t off = (uint32_t)((16 * jp + krow) * AT_ROW + hb
                                                + (kc * 16 + kcol) * 2);
                ldm_x4(kh, sKh + off);
                ldm_x4(kl, sKl + off);
#pragma unroll
                for (int jj = 0; jj < 2; jj++) {
                    const int j = jp * 2 + jj;
                    mma_bf16(sacc[j], qh[kc], kh[jj * 2], kh[jj * 2 + 1]);
                    mma_bf16(sacc[j], ql[kc], kh[jj * 2], kh[jj * 2 + 1]);
                    mma_bf16(sacc[j], qh[kc], kl[jj * 2], kl[jj * 2 + 1]);
                }
            }
    }

    const int r0 = 16 * w + gid;
    const int r1 = r0 + 8;
    const float* mbase = mask + (size_t)n * 4096;
    float mx0 = -1e30f, mx1 = -1e30f;
#pragma unroll
    for (int j = 0; j < 8; j++) {
        const float2 m0 = *(const float2*)(mbase + r0 * 64 + j * 8 + tig * 2);
        const float2 m1 = *(const float2*)(mbase + r1 * 64 + j * 8 + tig * 2);
        sacc[j][0] += m0.x; sacc[j][1] += m0.y;
        sacc[j][2] += m1.x; sacc[j][3] += m1.y;
        mx0 = fmaxf(mx0, fmaxf(sacc[j][0], sacc[j][1]));
        mx1 = fmaxf(mx1, fmaxf(sacc[j][2], sacc[j][3]));
    }
    mx0 = fmaxf(mx0, __shfl_xor_sync(0xffffffffu, mx0, 1));
    mx0 = fmaxf(mx0, __shfl_xor_sync(0xffffffffu, mx0, 2));
    mx1 = fmaxf(mx1, __shfl_xor_sync(0xffffffffu, mx1, 1));
    mx1 = fmaxf(mx1, __shfl_xor_sync(0xffffffffu, mx1, 2));

    float sum0 = 0.f, sum1 = 0.f;
#pragma unroll
    for (int j = 0; j < 8; j++) {
        sacc[j][0] = __expf(sacc[j][0] - mx0);
        sacc[j][1] = __expf(sacc[j][1] - mx0);
        sacc[j][2] = __expf(sacc[j][2] - mx1);
        sacc[j][3] = __expf(sacc[j][3] - mx1);
        sum0 += sacc[j][0] + sacc[j][1];
        sum1 += sacc[j][2] + sacc[j][3];
    }
    sum0 += __shfl_xor_sync(0xffffffffu, sum0, 1);
    sum0 += __shfl_xor_sync(0xffffffffu, sum0, 2);
    sum1 += __shfl_xor_sync(0xffffffffu, sum1, 1);
    sum1 += __shfl_xor_sync(0xffffffffu, sum1, 2);
    const float inv0 = 1.f / sum0;
    const float inv1 = 1.f / sum1;

    uint32_t ph[4][4], pl[4][4];
#pragma unroll
    for (int kc = 0; kc < 4; kc++) {
        const int t0 = 2 * kc, t1 = 2 * kc + 1;
        ph[kc][0] = packsplit(sacc[t0][0], sacc[t0][1], pl[kc][0]);
        ph[kc][1] = packsplit(sacc[t0][2], sacc[t0][3], pl[kc][1]);
        ph[kc][2] = packsplit(sacc[t1][0], sacc[t1][1], pl[kc][2]);
        ph[kc][3] = packsplit(sacc[t1][2], sacc[t1][3], pl[kc][3]);
    }

    float oacc[4][4];
#pragma unroll
    for (int jd = 0; jd < 4; jd++)
#pragma unroll
        for (int t = 0; t < 4; t++) oacc[jd][t] = 0.f;

    {
        const int vrow = lane & 15;
#pragma unroll
        for (int kc = 0; kc < 4; kc++)
#pragma unroll
            for (int jd = 0; jd < 4; jd++) {
                uint32_t vh[2], vl[2];
                const uint32_t off = (uint32_t)((16 * kc + vrow) * AT_ROW + hb
                                                + jd * 16);
                ldm_x2t(vh, sVh + off);
                ldm_x2t(vl, sVl + off);
                mma_bf16(oacc[jd], ph[kc], vh[0], vh[1]);
                mma_bf16(oacc[jd], pl[kc], vh[0], vh[1]);
                mma_bf16(oacc[jd], ph[kc], vl[0], vl[1]);
            }
    }

#pragma unroll
    for (int jd = 0; jd < 4; jd++) {
        float x0 = oacc[jd][0] * inv0, x1 = oacc[jd][1] * inv0;
        float y0 = oacc[jd][2] * inv1, y1 = oacc[jd][3] * inv1;
        const int d = wg * 32 + jd * 8 + tig * 2;
        const size_t o0 = base + (size_t)r0 * row_stride + d;
        const size_t o1 = base + (size_t)r1 * row_stride + d;
        if (FUSE) {
            const float2 lp0 = *(const float2*)(lepe + o0);
            const float2 lp1 = *(const float2*)(lepe + o1);
            x0 += lp0.x; x1 += lp0.y;
            y0 += lp1.x; y1 += lp1.y;
            uint32_t lo;
            uint32_t hi = packsplit_h(x0, x1, lo);
            *(uint32_t*)(HOhi + o0) = hi;
            *(uint32_t*)(HOlo + o0) = lo;
            hi = packsplit_h(y0, y1, lo);
            *(uint32_t*)(HOhi + o1) = hi;
            *(uint32_t*)(HOlo + o1) = lo;
        } else {
            uint32_t lo;
            uint32_t hi = packsplit(x0, x1, lo);
            *(uint32_t*)(Ohi + o0) = hi;
            *(uint32_t*)(Olo + o0) = lo;
            hi = packsplit(y0, y1, lo);
            *(uint32_t*)(Ohi + o1) = hi;
            *(uint32_t*)(Olo + o1) = lo;
        }
    }
}

// ---------------------------------------------------------------------------
extern "C" void kernel_launch(void* const* d_in, const int* in_sizes, int n_in,
                              void* d_out, int out_size)
{
    const float* x      = (const float*)d_in[0];
    const float* mask_h = (const float*)d_in[1];
    const float* mask_w = (const float*)d_in[2];
    const float* Wq = (const float*)d_in[3];
    const float* bq = (const float*)d_in[4];
    const float* Wk = (const float*)d_in[5];
    const float* bk = (const float*)d_in[6];
    const float* Wv = (const float*)d_in[7];
    const float* bv = (const float*)d_in[8];
    const float* Wl = (const float*)d_in[9];
    const float* bl = (const float*)d_in[10];
    const float* Wo = (const float*)d_in[11];
    const float* bo = (const float*)d_in[12];
    float* out = (float*)d_out;

    float *v, *lepe;
    __half *xh, *xl, *ah, *al, *wh;
    __nv_bfloat16 *qhi, *qlo, *khi, *klo, *vhi, *vlo, *v1hi, *v1lo;
    cudaGetSymbolAddress((void**)&v,    g_v);
    cudaGetSymbolAddress((void**)&lepe, g_lepe);
    cudaGetSymbolAddress((void**)&xh,   g_xh);
    cudaGetSymbolAddress((void**)&xl,   g_xl);
    cudaGetSymbolAddress((void**)&ah,   g_ah);
    cudaGetSymbolAddress((void**)&al,   g_al);
    cudaGetSymbolAddress((void**)&wh,   g_wh);
    cudaGetSymbolAddress((void**)&qhi,  g_qhi);
    cudaGetSymbolAddress((void**)&qlo,  g_qlo);
    cudaGetSymbolAddress((void**)&khi,  g_khi);
    cudaGetSymbolAddress((void**)&klo,  g_klo);
    cudaGetSymbolAddress((void**)&vhi,  g_vhi);
    cudaGetSymbolAddress((void**)&vlo,  g_vlo);
    cudaGetSymbolAddress((void**)&v1hi, g_v1hi);
    cudaGetSymbolAddress((void**)&v1lo, g_v1lo);

    static int smem_set = 0;
    if (!smem_set) {
        cudaFuncSetAttribute(gemm_qkv,
                             cudaFuncAttributeMaxDynamicSharedMemorySize,
                             GEMM_SMEM);
        cudaFuncSetAttribute(gemm_out,
                             cudaFuncAttributeMaxDynamicSharedMemorySize,
                             GEMM_SMEM);
        cudaFuncSetAttribute(attn_hmma2<false>,
                             cudaFuncAttributeMaxDynamicSharedMemorySize,
                             AT_SMEM);
        cudaFuncSetAttribute(attn_hmma2<true>,
                             cudaFuncAttributeMaxDynamicSharedMemorySize,
                             AT_SMEM);
        smem_set = 1;
    }

    const float scaling = 0.17677669529663687f;  // 32^-0.5

    // 1) Splits (x -> fp16 hi/lo; W -> fp16).
    split_all<<<8448, 256>>>(x, Wq, Wk, Wv, Wo, xh, xl, wh);

    // 2) QKV projection (fp16 2-product) -> bf16 hi/lo q/k/v, fp32 v.
    gemm_qkv<<<dim3(1, 256, 3), 512, GEMM_SMEM>>>(
        xh, xl, wh, bq, bk, bv,
        qhi, qlo, khi, klo, vhi, vlo, v, scaling);

    // 3) LePE.
    lepe_kernel<<<ELEMS / 4 / 256, 256>>>(v, Wl, bl, lepe);

    dim3 attn_grid(4, 64, 8);
    // 4) Width-axis attention -> v1 (bf16 hi/lo).
    attn_hmma2<false><<<attn_grid, 256, AT_SMEM>>>(
        qhi, qlo, khi, klo, vhi, vlo, mask_w, nullptr,
        v1hi, v1lo, nullptr, nullptr,
        /*y_stride=*/64 * 256, /*row_stride=*/256);
    // 5) Height-axis attention + LePE -> fp16 hi/lo (out-proj A input).
    attn_hmma2<true><<<attn_grid, 256, AT_SMEM>>>(
        qhi, qlo, khi, klo, v1hi, v1lo, mask_h, lepe,
        nullptr, nullptr, ah, al,
        /*y_stride=*/256, /*row_stride=*/64 * 256);

    // 6) Output projection (fp16 2-product, fp32 out).
    gemm_out<<<dim3(1, 256, 1), 512, GEMM_SMEM>>>(
        ah, al, wh + 3 * 65536, bo, out);
}

// round 14
// speedup vs baseline: 2.0523x; 1.2013x over previous
#include <cuda_runtime.h>
#include <cuda_fp16.h>
#include <cstdint>

// Problem constants: B=8, H=64, W=64, C=256, NUM_HEADS=8, KEY_DIM=32
#define M_TOT   32768
#define C_DIM   256
#define ELEMS   (M_TOT * C_DIM)   // 8388608

// ---------------- scratch (device globals; no allocation allowed) ----------
__device__ __align__(16) float g_v[ELEMS];      // v fp32 (LePE input)
__device__ __align__(16) float g_lepe[ELEMS];

__device__ __align__(16) __half g_xh[ELEMS];    // x hi (GEMM A)
__device__ __align__(16) __half g_xl[ELEMS];    // x lo
__device__ __align__(16) __half g_ah[ELEMS];    // attn+lepe hi (out-proj A)
__device__ __align__(16) __half g_al[ELEMS];    // attn+lepe lo
__device__ __align__(16) __half g_wh[4 * 65536];// Wq,Wk,Wv,Wo fp16

__device__ __align__(16) __half g_qh[ELEMS];    // q hi
__device__ __align__(16) __half g_ql[ELEMS];    // q lo
__device__ __align__(16) __half g_k[ELEMS];     // k (scaled) fp16
__device__ __align__(16) __half g_vh[ELEMS];    // v fp16
__device__ __align__(16) __half g_v1[ELEMS];    // v1 fp16

// ---------------- helpers ---------------------------------------------------
__device__ __forceinline__ uint32_t smem_u32(const void* p) {
    uint32_t a;
    asm("{ .reg .u64 t; cvta.to.shared.u64 t, %1; cvt.u32.u64 %0, t; }"
        : "=r"(a) : "l"(p));
    return a;
}

__device__ __forceinline__ void cpa16(uint32_t dst, const void* src) {
    asm volatile("cp.async.ca.shared.global [%0], [%1], 16;"
                 :: "r"(dst), "l"(src));
}

__device__ __forceinline__ void mma_f16(float* c, const uint32_t* a,
                                        uint32_t b0, uint32_t b1)
{
    asm volatile(
        "mma.sync.aligned.m16n8k16.row.col.f32.f16.f16.f32 "
        "{%0,%1,%2,%3}, {%4,%5,%6,%7}, {%8,%9}, {%0,%1,%2,%3};"
        : "+f"(c[0]), "+f"(c[1]), "+f"(c[2]), "+f"(c[3])
        : "r"(a[0]), "r"(a[1]), "r"(a[2]), "r"(a[3]), "r"(b0), "r"(b1));
}

__device__ __forceinline__ void ldm_x4(uint32_t* r, uint32_t addr) {
    asm volatile("ldmatrix.sync.aligned.m8n8.x4.shared.b16 {%0,%1,%2,%3}, [%4];"
        : "=r"(r[0]), "=r"(r[1]), "=r"(r[2]), "=r"(r[3]) : "r"(addr));
}

__device__ __forceinline__ void ldm_x2t(uint32_t* r, uint32_t addr) {
    asm volatile("ldmatrix.sync.aligned.m8n8.x2.trans.shared.b16 {%0,%1}, [%2];"
        : "=r"(r[0]), "=r"(r[1]) : "r"(addr));
}

// fp16 hi/lo split pack
__device__ __forceinline__ uint32_t packsplit_h(float x0, float x1, uint32_t& lo) {
    __half h0 = __float2half_rn(x0), h1 = __float2half_rn(x1);
    float r0 = x0 - __half2float(h0);
    float r1 = x1 - __half2float(h1);
    __half l0 = __float2half_rn(r0), l1 = __float2half_rn(r1);
    lo = (uint32_t)__half_as_ushort(l0) |
         ((uint32_t)__half_as_ushort(l1) << 16);
    return (uint32_t)__half_as_ushort(h0) |
           ((uint32_t)__half_as_ushort(h1) << 16);
}

__device__ __forceinline__ uint32_t pack_h(float x0, float x1) {
    return (uint32_t)__half_as_ushort(__float2half_rn(x0)) |
           ((uint32_t)__half_as_ushort(__float2half_rn(x1)) << 16);
}

// ---------------------------------------------------------------------------
// Merged split kernel: blocks [0, 8192) split x into fp16 hi/lo;
// blocks [8192, 8448) convert the four weight matrices to fp16.
// ---------------------------------------------------------------------------
__global__ __launch_bounds__(256)
void split_all(const float* __restrict__ x,
               const float* __restrict__ W0, const float* __restrict__ W1,
               const float* __restrict__ W2, const float* __restrict__ W3,
               __half* __restrict__ xh, __half* __restrict__ xl,
               __half* __restrict__ wh)
{
    if (blockIdx.x < 8192) {
        const int i = blockIdx.x * 256 + threadIdx.x;
        float4 v = ((const float4*)x)[i];
        uint32_t l0, l1;
        uint32_t h0 = packsplit_h(v.x, v.y, l0);
        uint32_t h1 = packsplit_h(v.z, v.w, l1);
        ((uint2*)xh)[i] = make_uint2(h0, h1);
        ((uint2*)xl)[i] = make_uint2(l0, l1);
    } else {
        const int wblk = blockIdx.x - 8192;
        const int w = wblk >> 6;
        const float* W = (w == 0) ? W0 : (w == 1) ? W1 : (w == 2) ? W2 : W3;
        const int i = (wblk & 63) * 256 + threadIdx.x;
        float4 v = ((const float4*)W)[i];
        ((uint2*)wh)[w * 16384 + i] = make_uint2(pack_h(v.x, v.y),
                                                 pack_h(v.z, v.w));
    }
}

// ---------------------------------------------------------------------------
// fp16 HMMA GEMM, 2-product emulation (A = hi+lo exact, W fp16 once-rounded).
// CTA tile 128x256 (full N), 512 threads = 16 warps (4m x 4n), warp tile 32x64.
// ---------------------------------------------------------------------------
#define A_TILE_B  10240        // 128 * 80
#define B_TILE_B  20480        // 256 * 80
#define STAGE_B   (2 * A_TILE_B + B_TILE_B)       // 40960
#define GEMM_SMEM (2 * STAGE_B)                   // 81920

__device__ __forceinline__
void gemm_main(float acc[2][8][4],
               const __half* __restrict__ Ah,
               const __half* __restrict__ Al,
               const __half* __restrict__ Bh,
               int m0, uint32_t smem_base)
{
    const int tid  = threadIdx.x;
    const int lane = tid & 31;
    const int warp = tid >> 5;
    const int wm   = warp >> 2;
    const int wn   = warp & 3;

    const uint4* gAh = (const uint4*)Ah + (size_t)m0 * 32;
    const uint4* gAl = (const uint4*)Al + (size_t)m0 * 32;
    const uint4* gBh = (const uint4*)Bh;

    auto issue = [&](int chunk, int stg) {
        const int kq4 = chunk * 4;
        const uint32_t sb = smem_base + stg * STAGE_B;
        {
            const int r = tid >> 2, q = tid & 3;
            const uint32_t off = (uint32_t)(r * 80 + q * 16);
            cpa16(sb + off,            gAh + (size_t)r * 32 + kq4 + q);
            cpa16(sb + A_TILE_B + off, gAl + (size_t)r * 32 + kq4 + q);
        }
#pragma unroll
        for (int rep = 0; rep < 2; rep++) {
            const int li = rep * 512 + tid;
            const int r = li >> 2, q = li & 3;
            const uint32_t off = (uint32_t)(r * 80 + q * 16);
            cpa16(sb + 2 * A_TILE_B + off,
                  gBh + (size_t)r * 32 + kq4 + q);
        }
    };

    issue(0, 0);
    asm volatile("cp.async.commit_group;" ::: "memory");

    for (int c = 0; c < 8; c++) {
        if (c + 1 < 8) issue(c + 1, (c + 1) & 1);
        asm volatile("cp.async.commit_group;" ::: "memory");
        asm volatile("cp.async.wait_group 1;" ::: "memory");
        __syncthreads();

        const uint32_t sb  = smem_base + (c & 1) * STAGE_B;
        const uint32_t sAh = sb, sAl = sb + A_TILE_B;
        const uint32_t sBh = sb + 2 * A_TILE_B;

#pragma unroll
        for (int ks = 0; ks < 2; ks++) {
            const int kb = ks * 16;
            uint32_t ah[2][4], al[2][4];
            const int arow = wm * 32 + (lane & 15);
            const int acol = kb + ((lane >> 4) << 3);
#pragma unroll
            for (int i = 0; i < 2; i++) {
                const uint32_t off = (uint32_t)((arow + i * 16) * 80 + acol * 2);
                ldm_x4(ah[i], sAh + off);
                ldm_x4(al[i], sAl + off);
            }
            const int brow0 = wn * 64 + ((lane >> 4) & 1) * 8 + (lane & 7);
            const int bcol  = kb + ((lane >> 3) & 1) * 8;
#pragma unroll
            for (int jp = 0; jp < 4; jp++) {
                uint32_t bh[4];
                const uint32_t off = (uint32_t)((brow0 + jp * 16) * 80 + bcol * 2);
                ldm_x4(bh, sBh + off);
#pragma unroll
                for (int jj = 0; jj < 2; jj++) {
                    const int j = jp * 2 + jj;
#pragma unroll
                    for (int i = 0; i < 2; i++) {
                        mma_f16(acc[i][j], ah[i], bh[jj * 2], bh[jj * 2 + 1]);
                        mma_f16(acc[i][j], al[i], bh[jj * 2], bh[jj * 2 + 1]);
                    }
                }
            }
        }
        __syncthreads();
    }
}

// ---------------------------------------------------------------------------
// QKV GEMM: grid.z selects q/k/v.
// q -> fp16 hi/lo; k -> fp16 single (scaled); v -> fp16 single + fp32.
// ---------------------------------------------------------------------------
__global__ __launch_bounds__(512)
void gemm_qkv(const __half* __restrict__ Ah, const __half* __restrict__ Al,
              const __half* __restrict__ Wh,
              const float* __restrict__ bq, const float* __restrict__ bk,
              const float* __restrict__ bv,
              __half* __restrict__ qh, __half* __restrict__ ql,
              __half* __restrict__ kk, __half* __restrict__ vv,
              float* __restrict__ vf, float kscale)
{
    extern __shared__ __align__(16) char gsm[];
    const int z = blockIdx.z;
    const int m0 = blockIdx.y * 128;

    float acc[2][8][4];
#pragma unroll
    for (int i = 0; i < 2; i++)
#pragma unroll
        for (int j = 0; j < 8; j++)
#pragma unroll
            for (int t = 0; t < 4; t++) acc[i][j][t] = 0.f;

    gemm_main(acc, Ah, Al, Wh + z * 65536, m0, smem_u32(gsm));

    const float* bias = (z == 0) ? bq : (z == 1) ? bk : bv;
    const float scale = (z == 1) ? kscale : 1.0f;

    const int lane = threadIdx.x & 31;
    const int warp = threadIdx.x >> 5;
    const int wm = warp >> 2, wn = warp & 3;
    const int gid = lane >> 2, tig = lane & 3;

#pragma unroll
    for (int i = 0; i < 2; i++) {
        const int row = m0 + wm * 32 + i * 16 + gid;
#pragma unroll
        for (int j = 0; j < 8; j++) {
            const int col = wn * 64 + j * 8 + tig * 2;
            const float b0 = bias[col], b1 = bias[col + 1];
            const float x0 = (acc[i][j][0] + b0) * scale;
            const float x1 = (acc[i][j][1] + b1) * scale;
            const float y0 = (acc[i][j][2] + b0) * scale;
            const float y1 = (acc[i][j][3] + b1) * scale;
            const size_t o0 = (size_t)row * 256 + col;
            const size_t o1 = o0 + 8 * 256;
            if (z == 0) {
                uint32_t lo;
                uint32_t hi = packsplit_h(x0, x1, lo);
                *(uint32_t*)(qh + o0) = hi;
                *(uint32_t*)(ql + o0) = lo;
                hi = packsplit_h(y0, y1, lo);
                *(uint32_t*)(qh + o1) = hi;
                *(uint32_t*)(ql + o1) = lo;
            } else if (z == 1) {
                *(uint32_t*)(kk + o0) = pack_h(x0, x1);
                *(uint32_t*)(kk + o1) = pack_h(y0, y1);
            } else {
                *(uint32_t*)(vv + o0) = pack_h(x0, x1);
                *(uint32_t*)(vv + o1) = pack_h(y0, y1);
                *(float2*)(vf + o0) = make_float2(x0, x1);
                *(float2*)(vf + o1) = make_float2(y0, y1);
            }
        }
    }
}

// ---------------------------------------------------------------------------
// Output projection GEMM: fp32 out.
// ---------------------------------------------------------------------------
__global__ __launch_bounds__(512)
void gemm_out(const __half* __restrict__ Ah, const __half* __restrict__ Al,
              const __half* __restrict__ Wh,
              const float* __restrict__ bias, float* __restrict__ out)
{
    extern __shared__ __align__(16) char gsm[];
    const int m0 = blockIdx.y * 128;

    float acc[2][8][4];
#pragma unroll
    for (int i = 0; i < 2; i++)
#pragma unroll
        for (int j = 0; j < 8; j++)
#pragma unroll
            for (int t = 0; t < 4; t++) acc[i][j][t] = 0.f;

    gemm_main(acc, Ah, Al, Wh, m0, smem_u32(gsm));

    const int lane = threadIdx.x & 31;
    const int warp = threadIdx.x >> 5;
    const int wm = warp >> 2, wn = warp & 3;
    const int gid = lane >> 2, tig = lane & 3;

#pragma unroll
    for (int i = 0; i < 2; i++) {
        const int row = m0 + wm * 32 + i * 16 + gid;
#pragma unroll
        for (int j = 0; j < 8; j++) {
            const int col = wn * 64 + j * 8 + tig * 2;
            const float b0 = bias[col], b1 = bias[col + 1];
            *(float2*)(out + (size_t)row * 256 + col) =
                make_float2(acc[i][j][0] + b0, acc[i][j][1] + b1);
            *(float2*)(out + (size_t)(row + 8) * 256 + col) =
                make_float2(acc[i][j][2] + b0, acc[i][j][3] + b1);
        }
    }
}

// ---------------------------------------------------------------------------
// LePE: 5x5 depthwise conv, register-blocked 4 x-outputs per thread.
// ---------------------------------------------------------------------------
__global__ __launch_bounds__(256)
void lepe_kernel(const float* __restrict__ V,
                 const float* __restrict__ Wl,
                 const float* __restrict__ bl,
                 float* __restrict__ out)
{
    const int idx = blockIdx.x * 256 + threadIdx.x;
    const int c  = idx & 255;
    const int xg = (idx >> 8) & 15;
    const int y  = (idx >> 12) & 63;
    const int b  = idx >> 18;
    const int x0 = xg * 4;

    float w[5][5];
#pragma unroll
    for (int dy = 0; dy < 5; dy++)
#pragma unroll
        for (int dx = 0; dx < 5; dx++)
            w[dy][dx] = Wl[(dy * 5 + dx) * 256 + c];

    const float bias = bl[c];
    float acc[4] = {bias, bias, bias, bias};

#pragma unroll
    for (int dy = 0; dy < 5; dy++) {
        const int yy = y + dy - 2;
        if (yy < 0 || yy > 63) continue;
        const float* vrow = V + (size_t)(((b << 6) + yy) << 6) * 256 + c;
#pragma unroll
        for (int e = 0; e < 8; e++) {
            const int xx = x0 - 2 + e;
            if (xx < 0 || xx > 63) continue;
            const float val = vrow[(size_t)xx * 256];
#pragma unroll
            for (int u = 0; u < 4; u++) {
                const int dxi = e - u;
                if (dxi >= 0 && dxi < 5) acc[u] += val * w[dy][dxi];
            }
        }
    }

    float* orow = out + (size_t)((((b << 6) + y) << 6) + x0) * 256 + c;
#pragma unroll
    for (int u = 0; u < 4; u++) orow[(size_t)u * 256] = acc[u];
}

// ---------------------------------------------------------------------------
// fp16 HMMA axis attention, 2 heads per block.
// Q = hi/lo fp16 (exact); K, V = single fp16. 2 MMAs per group.
// FUSE=false: out -> v1 single fp16.
// FUSE=true : +LePE -> fp16 hi/lo (out-projection A input).
// ---------------------------------------------------------------------------
#define AT_ROW   144
#define AT_TILE  (64 * AT_ROW)
#define AT_SMEM  (4 * AT_TILE)        // Qh, Ql, K, V

template <bool FUSE>
__global__ __launch_bounds__(256)
void attn_f16(const __half* __restrict__ Qh, const __half* __restrict__ Ql,
              const __half* __restrict__ K, const __half* __restrict__ V,
              const float* __restrict__ mask,
              const float* __restrict__ lepe,
              __half* __restrict__ O,                       // FUSE=false
              __half* __restrict__ OHhi, __half* __restrict__ OHlo, // FUSE=true
              int y_stride, int row_stride)
{
    extern __shared__ __align__(16) char asm_[];
    const uint32_t sm = smem_u32(asm_);
    const uint32_t sQh = sm, sQl = sm + AT_TILE;
    const uint32_t sK  = sm + 2 * AT_TILE, sV = sm + 3 * AT_TILE;

    const int np = blockIdx.x;
    const int y  = blockIdx.y;
    const int b  = blockIdx.z;
    const int tid  = threadIdx.x;
    const int lane = tid & 31;
    const int wg   = tid >> 7;
    const int w    = (tid >> 5) & 3;
    const int gid  = lane >> 2;
    const int tig  = lane & 3;
    const int n    = np * 2 + wg;
    const int hb   = wg * 64;

    const size_t base = (size_t)b * (64 * 64 * 256) + (size_t)y * y_stride
                        + np * 64;

#pragma unroll
    for (int i = tid; i < 512; i += 256) {
        const int r = i >> 3, c8 = (i & 7) * 8;
        const size_t g = base + (size_t)r * row_stride + c8;
        const uint32_t so = (uint32_t)(r * AT_ROW + c8 * 2);
        cpa16(sQh + so, Qh + g);
        cpa16(sQl + so, Ql + g);
        cpa16(sK  + so, K  + g);
        cpa16(sV  + so, V  + g);
    }
    asm volatile("cp.async.commit_group;" ::: "memory");
    asm volatile("cp.async.wait_group 0;" ::: "memory");
    __syncthreads();

    uint32_t qh[2][4], ql[2][4];
    {
        const int arow = 16 * w + (lane & 15);
        const int acol = (lane >> 4) << 3;
#pragma unroll
        for (int kc = 0; kc < 2; kc++) {
            const uint32_t off = (uint32_t)(arow * AT_ROW + hb
                                            + (kc * 16 + acol) * 2);
            ldm_x4(qh[kc], sQh + off);
            ldm_x4(ql[kc], sQl + off);
        }
    }

    float sacc[8][4];
#pragma unroll
    for (int j = 0; j < 8; j++)
#pragma unroll
        for (int t = 0; t < 4; t++) sacc[j][t] = 0.f;

    {
        const int krow = ((lane >> 4) & 1) * 8 + (lane & 7);
        const int kcol = ((lane >> 3) & 1) * 8;
#pragma unroll
        for (int kc = 0; kc < 2; kc++)
#pragma unroll
            for (int jp = 0; jp < 4; jp++) {
                uint32_t kv[4];
                const uint32_t off = (uint32_t)((16 * jp + krow) * AT_ROW + hb
                                                + (kc * 16 + kcol) * 2);
                ldm_x4(kv, sK + off);
#pragma unroll
                for (int jj = 0; jj < 2; jj++) {
                    const int j = jp * 2 + jj;
                    mma_f16(sacc[j], qh[kc], kv[jj * 2], kv[jj * 2 + 1]);
                    mma_f16(sacc[j], ql[kc], kv[jj * 2], kv[jj * 2 + 1]);
                }
            }
    }

    const int r0 = 16 * w + gid;
    const int r1 = r0 + 8;
    const float* mbase = mask + (size_t)n * 4096;
    float mx0 = -1e30f, mx1 = -1e30f;
#pragma unroll
    for (int j = 0; j < 8; j++) {
        const float2 m0 = *(const float2*)(mbase + r0 * 64 + j * 8 + tig * 2);
        const float2 m1 = *(const float2*)(mbase + r1 * 64 + j * 8 + tig * 2);
        sacc[j][0] += m0.x; sacc[j][1] += m0.y;
        sacc[j][2] += m1.x; sacc[j][3] += m1.y;
        mx0 = fmaxf(mx0, fmaxf(sacc[j][0], sacc[j][1]));
        mx1 = fmaxf(mx1, fmaxf(sacc[j][2], sacc[j][3]));
    }
    mx0 = fmaxf(mx0, __shfl_xor_sync(0xffffffffu, mx0, 1));
    mx0 = fmaxf(mx0, __shfl_xor_sync(0xffffffffu, mx0, 2));
    mx1 = fmaxf(mx1, __shfl_xor_sync(0xffffffffu, mx1, 1));
    mx1 = fmaxf(mx1, __shfl_xor_sync(0xffffffffu, mx1, 2));

    float sum0 = 0.f, sum1 = 0.f;
#pragma unroll
    for (int j = 0; j < 8; j++) {
        sacc[j][0] = __expf(sacc[j][0] - mx0);
        sacc[j][1] = __expf(sacc[j][1] - mx0);
        sacc[j][2] = __expf(sacc[j][2] - mx1);
        sacc[j][3] = __expf(sacc[j][3] - mx1);
        sum0 += sacc[j][0] + sacc[j][1];
        sum1 += sacc[j][2] + sacc[j][3];
    }
    sum0 += __shfl_xor_sync(0xffffffffu, sum0, 1);
    sum0 += __shfl_xor_sync(0xffffffffu, sum0, 2);
    sum1 += __shfl_xor_sync(0xffffffffu, sum1, 1);
    sum1 += __shfl_xor_sync(0xffffffffu, sum1, 2);
    const float inv0 = 1.f / sum0;
    const float inv1 = 1.f / sum1;

    // Repack P (unnormalized, in (0,1]) into fp16 hi/lo A-fragments.
    uint32_t ph[4][4], pl[4][4];
#pragma unroll
    for (int kc = 0; kc < 4; kc++) {
        const int t0 = 2 * kc, t1 = 2 * kc + 1;
        ph[kc][0] = packsplit_h(sacc[t0][0], sacc[t0][1], pl[kc][0]);
        ph[kc][1] = packsplit_h(sacc[t0][2], sacc[t0][3], pl[kc][1]);
        ph[kc][2] = packsplit_h(sacc[t1][0], sacc[t1][1], pl[kc][2]);
        ph[kc][3] = packsplit_h(sacc[t1][2], sacc[t1][3], pl[kc][3]);
    }

    float oacc[4][4];
#pragma unroll
    for (int jd = 0; jd < 4; jd++)
#pragma unroll
        for (int t = 0; t < 4; t++) oacc[jd][t] = 0.f;

    {
        const int vrow = lane & 15;
#pragma unroll
        for (int kc = 0; kc < 4; kc++)
#pragma unroll
            for (int jd = 0; jd < 4; jd++) {
                uint32_t vv[2];
                const uint32_t off = (uint32_t)((16 * kc + vrow) * AT_ROW + hb
                                                + jd * 16);
                ldm_x2t(vv, sV + off);
                mma_f16(oacc[jd], ph[kc], vv[0], vv[1]);
                mma_f16(oacc[jd], pl[kc], vv[0], vv[1]);
            }
    }

#pragma unroll
    for (int jd = 0; jd < 4; jd++) {
        float x0 = oacc[jd][0] * inv0, x1 = oacc[jd][1] * inv0;
        float y0 = oacc[jd][2] * inv1, y1 = oacc[jd][3] * inv1;
        const int d = wg * 32 + jd * 8 + tig * 2;
        const size_t o0 = base + (size_t)r0 * row_stride + d;
        const size_t o1 = base + (size_t)r1 * row_stride + d;
        if (FUSE) {
            const float2 lp0 = *(const float2*)(lepe + o0);
            const float2 lp1 = *(const float2*)(lepe + o1);
            x0 += lp0.x; x1 += lp0.y;
            y0 += lp1.x; y1 += lp1.y;
            uint32_t lo;
            uint32_t hi = packsplit_h(x0, x1, lo);
            *(uint32_t*)(OHhi + o0) = hi;
            *(uint32_t*)(OHlo + o0) = lo;
            hi = packsplit_h(y0, y1, lo);
            *(uint32_t*)(OHhi + o1) = hi;
            *(uint32_t*)(OHlo + o1) = lo;
        } else {
            *(uint32_t*)(O + o0) = pack_h(x0, x1);
            *(uint32_t*)(O + o1) = pack_h(y0, y1);
        }
    }
}

// ---------------------------------------------------------------------------
extern "C" void kernel_launch(void* const* d_in, const int* in_sizes, int n_in,
                              void* d_out, int out_size)
{
    const float* x      = (const float*)d_in[0];
    const float* mask_h = (const float*)d_in[1];
    const float* mask_w = (const float*)d_in[2];
    const float* Wq = (const float*)d_in[3];
    const float* bq = (const float*)d_in[4];
    const float* Wk = (const float*)d_in[5];
    const float* bk = (const float*)d_in[6];
    const float* Wv = (const float*)d_in[7];
    const float* bv = (const float*)d_in[8];
    const float* Wl = (const float*)d_in[9];
    const float* bl = (const float*)d_in[10];
    const float* Wo = (const float*)d_in[11];
    const float* bo = (const float*)d_in[12];
    float* out = (float*)d_out;

    float *v, *lepe;
    __half *xh, *xl, *ah, *al, *wh, *qh, *ql, *kk, *vv, *v1;
    cudaGetSymbolAddress((void**)&v,    g_v);
    cudaGetSymbolAddress((void**)&lepe, g_lepe);
    cudaGetSymbolAddress((void**)&xh,   g_xh);
    cudaGetSymbolAddress((void**)&xl,   g_xl);
    cudaGetSymbolAddress((void**)&ah,   g_ah);
    cudaGetSymbolAddress((void**)&al,   g_al);
    cudaGetSymbolAddress((void**)&wh,   g_wh);
    cudaGetSymbolAddress((void**)&qh,   g_qh);
    cudaGetSymbolAddress((void**)&ql,   g_ql);
    cudaGetSymbolAddress((void**)&kk,   g_k);
    cudaGetSymbolAddress((void**)&vv,   g_vh);
    cudaGetSymbolAddress((void**)&v1,   g_v1);

    static int smem_set = 0;
    if (!smem_set) {
        cudaFuncSetAttribute(gemm_qkv,
                             cudaFuncAttributeMaxDynamicSharedMemorySize,
                             GEMM_SMEM);
        cudaFuncSetAttribute(gemm_out,
                             cudaFuncAttributeMaxDynamicSharedMemorySize,
                             GEMM_SMEM);
        cudaFuncSetAttribute(attn_f16<false>,
                             cudaFuncAttributeMaxDynamicSharedMemorySize,
                             AT_SMEM);
        cudaFuncSetAttribute(attn_f16<true>,
                             cudaFuncAttributeMaxDynamicSharedMemorySize,
                             AT_SMEM);
        smem_set = 1;
    }

    const float scaling = 0.17677669529663687f;  // 32^-0.5

    // 1) Splits (x -> fp16 hi/lo; W -> fp16).
    split_all<<<8448, 256>>>(x, Wq, Wk, Wv, Wo, xh, xl, wh);

    // 2) QKV projection: q fp16 hi/lo; k, v fp16; v fp32 for LePE.
    gemm_qkv<<<dim3(1, 256, 3), 512, GEMM_SMEM>>>(
        xh, xl, wh, bq, bk, bv, qh, ql, kk, vv, v, scaling);

    // 3) LePE.
    lepe_kernel<<<ELEMS / 4 / 256, 256>>>(v, Wl, bl, lepe);

    dim3 attn_grid(4, 64, 8);
    // 4) Width-axis attention -> v1 (fp16).
    attn_f16<false><<<attn_grid, 256, AT_SMEM>>>(
        qh, ql, kk, vv, mask_w, nullptr, v1, nullptr, nullptr,
        /*y_stride=*/64 * 256, /*row_stride=*/256);
    // 5) Height-axis attention (V = v1) + LePE -> fp16 hi/lo out-proj input.
    attn_f16<true><<<attn_grid, 256, AT_SMEM>>>(
        qh, ql, kk, v1, mask_h, lepe, nullptr, ah, al,
        /*y_stride=*/256, /*row_stride=*/64 * 256);

    // 6) Output projection (fp32 out).
    gemm_out<<<dim3(1, 256, 1), 512, GEMM_SMEM>>>(
        ah, al, wh + 3 * 65536, bo, out);
}

// round 15
// speedup vs baseline: 2.6211x; 1.2772x over previous
#include <cuda_runtime.h>
#include <cuda_fp16.h>
#include <cstdint>

// Problem constants: B=8, H=64, W=64, C=256, NUM_HEADS=8, KEY_DIM=32
#define M_TOT   32768
#define C_DIM   256
#define ELEMS   (M_TOT * C_DIM)   // 8388608

// ---------------- scratch (device globals; no allocation allowed) ----------
__device__ __align__(16) float g_v[ELEMS];      // v fp32 (LePE input)
__device__ __align__(16) float g_lepe[ELEMS];

__device__ __align__(16) __half g_xh[ELEMS];    // x fp16 (GEMM A)
__device__ __align__(16) __half g_ah[ELEMS];    // attn+lepe fp16 (out-proj A)
__device__ __align__(16) __half g_wh[4 * 65536];// Wq,Wk,Wv,Wo fp16

__device__ __align__(16) __half g_qh[ELEMS];    // q hi
__device__ __align__(16) __half g_ql[ELEMS];    // q lo
__device__ __align__(16) __half g_k[ELEMS];     // k (scaled) fp16
__device__ __align__(16) __half g_vh[ELEMS];    // v fp16
__device__ __align__(16) __half g_v1[ELEMS];    // v1 fp16

// ---------------- helpers ---------------------------------------------------
__device__ __forceinline__ uint32_t smem_u32(const void* p) {
    uint32_t a;
    asm("{ .reg .u64 t; cvta.to.shared.u64 t, %1; cvt.u32.u64 %0, t; }"
        : "=r"(a) : "l"(p));
    return a;
}

__device__ __forceinline__ void cpa16(uint32_t dst, const void* src) {
    asm volatile("cp.async.ca.shared.global [%0], [%1], 16;"
                 :: "r"(dst), "l"(src));
}

__device__ __forceinline__ void mma_f16(float* c, const uint32_t* a,
                                        uint32_t b0, uint32_t b1)
{
    asm volatile(
        "mma.sync.aligned.m16n8k16.row.col.f32.f16.f16.f32 "
        "{%0,%1,%2,%3}, {%4,%5,%6,%7}, {%8,%9}, {%0,%1,%2,%3};"
        : "+f"(c[0]), "+f"(c[1]), "+f"(c[2]), "+f"(c[3])
        : "r"(a[0]), "r"(a[1]), "r"(a[2]), "r"(a[3]), "r"(b0), "r"(b1));
}

__device__ __forceinline__ void ldm_x4(uint32_t* r, uint32_t addr) {
    asm volatile("ldmatrix.sync.aligned.m8n8.x4.shared.b16 {%0,%1,%2,%3}, [%4];"
        : "=r"(r[0]), "=r"(r[1]), "=r"(r[2]), "=r"(r[3]) : "r"(addr));
}

__device__ __forceinline__ void ldm_x2t(uint32_t* r, uint32_t addr) {
    asm volatile("ldmatrix.sync.aligned.m8n8.x2.trans.shared.b16 {%0,%1}, [%2];"
        : "=r"(r[0]), "=r"(r[1]) : "r"(addr));
}

// fp16 hi/lo split pack
__device__ __forceinline__ uint32_t packsplit_h(float x0, float x1, uint32_t& lo) {
    __half h0 = __float2half_rn(x0), h1 = __float2half_rn(x1);
    float r0 = x0 - __half2float(h0);
    float r1 = x1 - __half2float(h1);
    __half l0 = __float2half_rn(r0), l1 = __float2half_rn(r1);
    lo = (uint32_t)__half_as_ushort(l0) |
         ((uint32_t)__half_as_ushort(l1) << 16);
    return (uint32_t)__half_as_ushort(h0) |
           ((uint32_t)__half_as_ushort(h1) << 16);
}

__device__ __forceinline__ uint32_t pack_h(float x0, float x1) {
    return (uint32_t)__half_as_ushort(__float2half_rn(x0)) |
           ((uint32_t)__half_as_ushort(__float2half_rn(x1)) << 16);
}

// ---------------------------------------------------------------------------
// Merged split kernel: blocks [0, 8192) convert x to fp16;
// blocks [8192, 8448) convert the four weight matrices to fp16.
// ---------------------------------------------------------------------------
__global__ __launch_bounds__(256)
void split_all(const float* __restrict__ x,
               const float* __restrict__ W0, const float* __restrict__ W1,
               const float* __restrict__ W2, const float* __restrict__ W3,
               __half* __restrict__ xh, __half* __restrict__ wh)
{
    if (blockIdx.x < 8192) {
        const int i = blockIdx.x * 256 + threadIdx.x;
        float4 v = ((const float4*)x)[i];
        ((uint2*)xh)[i] = make_uint2(pack_h(v.x, v.y), pack_h(v.z, v.w));
    } else {
        const int wblk = blockIdx.x - 8192;
        const int w = wblk >> 6;
        const float* W = (w == 0) ? W0 : (w == 1) ? W1 : (w == 2) ? W2 : W3;
        const int i = (wblk & 63) * 256 + threadIdx.x;
        float4 v = ((const float4*)W)[i];
        ((uint2*)wh)[w * 16384 + i] = make_uint2(pack_h(v.x, v.y),
                                                 pack_h(v.z, v.w));
    }
}

// ---------------------------------------------------------------------------
// Plain fp16 HMMA GEMM (single product, fp32 accumulate).
// CTA tile 128x256 (full N), 512 threads = 16 warps (4m x 4n), warp tile 32x64.
// ---------------------------------------------------------------------------
#define A_TILE_B  10240        // 128 * 80
#define B_TILE_B  20480        // 256 * 80
#define STAGE_B   (A_TILE_B + B_TILE_B)           // 30720
#define GEMM_SMEM (2 * STAGE_B)                   // 61440

__device__ __forceinline__
void gemm_main(float acc[2][8][4],
               const __half* __restrict__ Ah,
               const __half* __restrict__ Bh,
               int m0, uint32_t smem_base)
{
    const int tid  = threadIdx.x;
    const int lane = tid & 31;
    const int warp = tid >> 5;
    const int wm   = warp >> 2;
    const int wn   = warp & 3;

    const uint4* gAh = (const uint4*)Ah + (size_t)m0 * 32;
    const uint4* gBh = (const uint4*)Bh;

    auto issue = [&](int chunk, int stg) {
        const int kq4 = chunk * 4;
        const uint32_t sb = smem_base + stg * STAGE_B;
        {
            const int r = tid >> 2, q = tid & 3;
            const uint32_t off = (uint32_t)(r * 80 + q * 16);
            cpa16(sb + off, gAh + (size_t)r * 32 + kq4 + q);
        }
#pragma unroll
        for (int rep = 0; rep < 2; rep++) {
            const int li = rep * 512 + tid;
            const int r = li >> 2, q = li & 3;
            const uint32_t off = (uint32_t)(r * 80 + q * 16);
            cpa16(sb + A_TILE_B + off, gBh + (size_t)r * 32 + kq4 + q);
        }
    };

    issue(0, 0);
    asm volatile("cp.async.commit_group;" ::: "memory");

    for (int c = 0; c < 8; c++) {
        if (c + 1 < 8) issue(c + 1, (c + 1) & 1);
        asm volatile("cp.async.commit_group;" ::: "memory");
        asm volatile("cp.async.wait_group 1;" ::: "memory");
        __syncthreads();

        const uint32_t sb  = smem_base + (c & 1) * STAGE_B;
        const uint32_t sAh = sb;
        const uint32_t sBh = sb + A_TILE_B;

#pragma unroll
        for (int ks = 0; ks < 2; ks++) {
            const int kb = ks * 16;
            uint32_t ah[2][4];
            const int arow = wm * 32 + (lane & 15);
            const int acol = kb + ((lane >> 4) << 3);
#pragma unroll
            for (int i = 0; i < 2; i++) {
                const uint32_t off = (uint32_t)((arow + i * 16) * 80 + acol * 2);
                ldm_x4(ah[i], sAh + off);
            }
            const int brow0 = wn * 64 + ((lane >> 4) & 1) * 8 + (lane & 7);
            const int bcol  = kb + ((lane >> 3) & 1) * 8;
#pragma unroll
            for (int jp = 0; jp < 4; jp++) {
                uint32_t bh[4];
                const uint32_t off = (uint32_t)((brow0 + jp * 16) * 80 + bcol * 2);
                ldm_x4(bh, sBh + off);
#pragma unroll
                for (int jj = 0; jj < 2; jj++) {
                    const int j = jp * 2 + jj;
#pragma unroll
                    for (int i = 0; i < 2; i++)
                        mma_f16(acc[i][j], ah[i], bh[jj * 2], bh[jj * 2 + 1]);
                }
            }
        }
        __syncthreads();
    }
}

// ---------------------------------------------------------------------------
// QKV GEMM: grid.z selects q/k/v.
// q -> fp16 hi/lo; k -> fp16 single (scaled); v -> fp16 single + fp32.
// ---------------------------------------------------------------------------
__global__ __launch_bounds__(512)
void gemm_qkv(const __half* __restrict__ Ah, const __half* __restrict__ Wh,
              const float* __restrict__ bq, const float* __restrict__ bk,
              const float* __restrict__ bv,
              __half* __restrict__ qh, __half* __restrict__ ql,
              __half* __restrict__ kk, __half* __restrict__ vv,
              float* __restrict__ vf, float kscale)
{
    extern __shared__ __align__(16) char gsm[];
    const int z = blockIdx.z;
    const int m0 = blockIdx.y * 128;

    float acc[2][8][4];
#pragma unroll
    for (int i = 0; i < 2; i++)
#pragma unroll
        for (int j = 0; j < 8; j++)
#pragma unroll
            for (int t = 0; t < 4; t++) acc[i][j][t] = 0.f;

    gemm_main(acc, Ah, Wh + z * 65536, m0, smem_u32(gsm));

    const float* bias = (z == 0) ? bq : (z == 1) ? bk : bv;
    const float scale = (z == 1) ? kscale : 1.0f;

    const int lane = threadIdx.x & 31;
    const int warp = threadIdx.x >> 5;
    const int wm = warp >> 2, wn = warp & 3;
    const int gid = lane >> 2, tig = lane & 3;

#pragma unroll
    for (int i = 0; i < 2; i++) {
        const int row = m0 + wm * 32 + i * 16 + gid;
#pragma unroll
        for (int j = 0; j < 8; j++) {
            const int col = wn * 64 + j * 8 + tig * 2;
            const float b0 = bias[col], b1 = bias[col + 1];
            const float x0 = (acc[i][j][0] + b0) * scale;
            const float x1 = (acc[i][j][1] + b1) * scale;
            const float y0 = (acc[i][j][2] + b0) * scale;
            const float y1 = (acc[i][j][3] + b1) * scale;
            const size_t o0 = (size_t)row * 256 + col;
            const size_t o1 = o0 + 8 * 256;
            if (z == 0) {
                uint32_t lo;
                uint32_t hi = packsplit_h(x0, x1, lo);
                *(uint32_t*)(qh + o0) = hi;
                *(uint32_t*)(ql + o0) = lo;
                hi = packsplit_h(y0, y1, lo);
                *(uint32_t*)(qh + o1) = hi;
                *(uint32_t*)(ql + o1) = lo;
            } else if (z == 1) {
                *(uint32_t*)(kk + o0) = pack_h(x0, x1);
                *(uint32_t*)(kk + o1) = pack_h(y0, y1);
            } else {
                *(uint32_t*)(vv + o0) = pack_h(x0, x1);
                *(uint32_t*)(vv + o1) = pack_h(y0, y1);
                *(float2*)(vf + o0) = make_float2(x0, x1);
                *(float2*)(vf + o1) = make_float2(y0, y1);
            }
        }
    }
}

// ---------------------------------------------------------------------------
// Output projection GEMM: fp32 out.
// ---------------------------------------------------------------------------
__global__ __launch_bounds__(512)
void gemm_out(const __half* __restrict__ Ah, const __half* __restrict__ Wh,
              const float* __restrict__ bias, float* __restrict__ out)
{
    extern __shared__ __align__(16) char gsm[];
    const int m0 = blockIdx.y * 128;

    float acc[2][8][4];
#pragma unroll
    for (int i = 0; i < 2; i++)
#pragma unroll
        for (int j = 0; j < 8; j++)
#pragma unroll
            for (int t = 0; t < 4; t++) acc[i][j][t] = 0.f;

    gemm_main(acc, Ah, Wh, m0, smem_u32(gsm));

    const int lane = threadIdx.x & 31;
    const int warp = threadIdx.x >> 5;
    const int wm = warp >> 2, wn = warp & 3;
    const int gid = lane >> 2, tig = lane & 3;

#pragma unroll
    for (int i = 0; i < 2; i++) {
        const int row = m0 + wm * 32 + i * 16 + gid;
#pragma unroll
        for (int j = 0; j < 8; j++) {
            const int col = wn * 64 + j * 8 + tig * 2;
            const float b0 = bias[col], b1 = bias[col + 1];
            *(float2*)(out + (size_t)row * 256 + col) =
                make_float2(acc[i][j][0] + b0, acc[i][j][1] + b1);
            *(float2*)(out + (size_t)(row + 8) * 256 + col) =
                make_float2(acc[i][j][2] + b0, acc[i][j][3] + b1);
        }
    }
}

// ---------------------------------------------------------------------------
// LePE: 5x5 depthwise conv, register-blocked 4 x-outputs per thread.
// ---------------------------------------------------------------------------
__global__ __launch_bounds__(256)
void lepe_kernel(const float* __restrict__ V,
                 const float* __restrict__ Wl,
                 const float* __restrict__ bl,
                 float* __restrict__ out)
{
    const int idx = blockIdx.x * 256 + threadIdx.x;
    const int c  = idx & 255;
    const int xg = (idx >> 8) & 15;
    const int y  = (idx >> 12) & 63;
    const int b  = idx >> 18;
    const int x0 = xg * 4;

    float w[5][5];
#pragma unroll
    for (int dy = 0; dy < 5; dy++)
#pragma unroll
        for (int dx = 0; dx < 5; dx++)
            w[dy][dx] = Wl[(dy * 5 + dx) * 256 + c];

    const float bias = bl[c];
    float acc[4] = {bias, bias, bias, bias};

#pragma unroll
    for (int dy = 0; dy < 5; dy++) {
        const int yy = y + dy - 2;
        if (yy < 0 || yy > 63) continue;
        const float* vrow = V + (size_t)(((b << 6) + yy) << 6) * 256 + c;
#pragma unroll
        for (int e = 0; e < 8; e++) {
            const int xx = x0 - 2 + e;
            if (xx < 0 || xx > 63) continue;
            const float val = vrow[(size_t)xx * 256];
#pragma unroll
            for (int u = 0; u < 4; u++) {
                const int dxi = e - u;
                if (dxi >= 0 && dxi < 5) acc[u] += val * w[dy][dxi];
            }
        }
    }

    float* orow = out + (size_t)((((b << 6) + y) << 6) + x0) * 256 + c;
#pragma unroll
    for (int u = 0; u < 4; u++) orow[(size_t)u * 256] = acc[u];
}

// ---------------------------------------------------------------------------
// fp16 HMMA axis attention, 2 heads per block.
// Q = hi/lo fp16 (exact); K, V = single fp16.
// FUSE=false: out -> v1 single fp16.
// FUSE=true : +LePE -> single fp16 (out-projection A input).
// ---------------------------------------------------------------------------
#define AT_ROW   144
#define AT_TILE  (64 * AT_ROW)
#define AT_SMEM  (4 * AT_TILE)        // Qh, Ql, K, V

template <bool FUSE>
__global__ __launch_bounds__(256)
void attn_f16(const __half* __restrict__ Qh, const __half* __restrict__ Ql,
              const __half* __restrict__ K, const __half* __restrict__ V,
              const float* __restrict__ mask,
              const float* __restrict__ lepe,
              __half* __restrict__ O,
              int y_stride, int row_stride)
{
    extern __shared__ __align__(16) char asm_[];
    const uint32_t sm = smem_u32(asm_);
    const uint32_t sQh = sm, sQl = sm + AT_TILE;
    const uint32_t sK  = sm + 2 * AT_TILE, sV = sm + 3 * AT_TILE;

    const int np = blockIdx.x;
    const int y  = blockIdx.y;
    const int b  = blockIdx.z;
    const int tid  = threadIdx.x;
    const int lane = tid & 31;
    const int wg   = tid >> 7;
    const int w    = (tid >> 5) & 3;
    const int gid  = lane >> 2;
    const int tig  = lane & 3;
    const int n    = np * 2 + wg;
    const int hb   = wg * 64;

    const size_t base = (size_t)b * (64 * 64 * 256) + (size_t)y * y_stride
                        + np * 64;

#pragma unroll
    for (int i = tid; i < 512; i += 256) {
        const int r = i >> 3, c8 = (i & 7) * 8;
        const size_t g = base + (size_t)r * row_stride + c8;
        const uint32_t so = (uint32_t)(r * AT_ROW + c8 * 2);
        cpa16(sQh + so, Qh + g);
        cpa16(sQl + so, Ql + g);
        cpa16(sK  + so, K  + g);
        cpa16(sV  + so, V  + g);
    }
    asm volatile("cp.async.commit_group;" ::: "memory");
    asm volatile("cp.async.wait_group 0;" ::: "memory");
    __syncthreads();

    uint32_t qh[2][4], ql[2][4];
    {
        const int arow = 16 * w + (lane & 15);
        const int acol = (lane >> 4) << 3;
#pragma unroll
        for (int kc = 0; kc < 2; kc++) {
            const uint32_t off = (uint32_t)(arow * AT_ROW + hb
                                            + (kc * 16 + acol) * 2);
            ldm_x4(qh[kc], sQh + off);
            ldm_x4(ql[kc], sQl + off);
        }
    }

    float sacc[8][4];
#pragma unroll
    for (int j = 0; j < 8; j++)
#pragma unroll
        for (int t = 0; t < 4; t++) sacc[j][t] = 0.f;

    {
        const int krow = ((lane >> 4) & 1) * 8 + (lane & 7);
        const int kcol = ((lane >> 3) & 1) * 8;
#pragma unroll
        for (int kc = 0; kc < 2; kc++)
#pragma unroll
            for (int jp = 0; jp < 4; jp++) {
                uint32_t kv[4];
                const uint32_t off = (uint32_t)((16 * jp + krow) * AT_ROW + hb
                                                + (kc * 16 + kcol) * 2);
                ldm_x4(kv, sK + off);
#pragma unroll
                for (int jj = 0; jj < 2; jj++) {
                    const int j = jp * 2 + jj;
                    mma_f16(sacc[j], qh[kc], kv[jj * 2], kv[jj * 2 + 1]);
                    mma_f16(sacc[j], ql[kc], kv[jj * 2], kv[jj * 2 + 1]);
                }
            }
    }

    const int r0 = 16 * w + gid;
    const int r1 = r0 + 8;
    const float* mbase = mask + (size_t)n * 4096;
    float mx0 = -1e30f, mx1 = -1e30f;
#pragma unroll
    for (int j = 0; j < 8; j++) {
        const float2 m0 = *(const float2*)(mbase + r0 * 64 + j * 8 + tig * 2);
        const float2 m1 = *(const float2*)(mbase + r1 * 64 + j * 8 + tig * 2);
        sacc[j][0] += m0.x; sacc[j][1] += m0.y;
        sacc[j][2] += m1.x; sacc[j][3] += m1.y;
        mx0 = fmaxf(mx0, fmaxf(sacc[j][0], sacc[j][1]));
        mx1 = fmaxf(mx1, fmaxf(sacc[j][2], sacc[j][3]));
    }
    mx0 = fmaxf(mx0, __shfl_xor_sync(0xffffffffu, mx0, 1));
    mx0 = fmaxf(mx0, __shfl_xor_sync(0xffffffffu, mx0, 2));
    mx1 = fmaxf(mx1, __shfl_xor_sync(0xffffffffu, mx1, 1));
    mx1 = fmaxf(mx1, __shfl_xor_sync(0xffffffffu, mx1, 2));

    float sum0 = 0.f, sum1 = 0.f;
#pragma unroll
    for (int j = 0; j < 8; j++) {
        sacc[j][0] = __expf(sacc[j][0] - mx0);
        sacc[j][1] = __expf(sacc[j][1] - mx0);
        sacc[j][2] = __expf(sacc[j][2] - mx1);
        sacc[j][3] = __expf(sacc[j][3] - mx1);
        sum0 += sacc[j][0] + sacc[j][1];
        sum1 += sacc[j][2] + sacc[j][3];
    }
    sum0 += __shfl_xor_sync(0xffffffffu, sum0, 1);
    sum0 += __shfl_xor_sync(0xffffffffu, sum0, 2);
    sum1 += __shfl_xor_sync(0xffffffffu, sum1, 1);
    sum1 += __shfl_xor_sync(0xffffffffu, sum1, 2);
    const float inv0 = 1.f / sum0;
    const float inv1 = 1.f / sum1;

    // Repack P (unnormalized, in (0,1]) into fp16 hi/lo A-fragments.
    uint32_t ph[4][4], pl[4][4];
#pragma unroll
    for (int kc = 0; kc < 4; kc++) {
        const int t0 = 2 * kc, t1 = 2 * kc + 1;
        ph[kc][0] = packsplit_h(sacc[t0][0], sacc[t0][1], pl[kc][0]);
        ph[kc][1] = packsplit_h(sacc[t0][2], sacc[t0][3], pl[kc][1]);
        ph[kc][2] = packsplit_h(sacc[t1][0], sacc[t1][1], pl[kc][2]);
        ph[kc][3] = packsplit_h(sacc[t1][2], sacc[t1][3], pl[kc][3]);
    }

    float oacc[4][4];
#pragma unroll
    for (int jd = 0; jd < 4; jd++)
#pragma unroll
        for (int t = 0; t < 4; t++) oacc[jd][t] = 0.f;

    {
        const int vrow = lane & 15;
#pragma unroll
        for (int kc = 0; kc < 4; kc++)
#pragma unroll
            for (int jd = 0; jd < 4; jd++) {
                uint32_t vv[2];
                const uint32_t off = (uint32_t)((16 * kc + vrow) * AT_ROW + hb
                                                + jd * 16);
                ldm_x2t(vv, sV + off);
                mma_f16(oacc[jd], ph[kc], vv[0], vv[1]);
                mma_f16(oacc[jd], pl[kc], vv[0], vv[1]);
            }
    }

#pragma unroll
    for (int jd = 0; jd < 4; jd++) {
        float x0 = oacc[jd][0] * inv0, x1 = oacc[jd][1] * inv0;
        float y0 = oacc[jd][2] * inv1, y1 = oacc[jd][3] * inv1;
        const int d = wg * 32 + jd * 8 + tig * 2;
        const size_t o0 = base + (size_t)r0 * row_stride + d;
        const size_t o1 = base + (size_t)r1 * row_stride + d;
        if (FUSE) {
            const float2 lp0 = *(const float2*)(lepe + o0);
            const float2 lp1 = *(const float2*)(lepe + o1);
            x0 += lp0.x; x1 += lp0.y;
            y0 += lp1.x; y1 += lp1.y;
        }
        *(uint32_t*)(O + o0) = pack_h(x0, x1);
        *(uint32_t*)(O + o1) = pack_h(y0, y1);
    }
}

// ---------------------------------------------------------------------------
extern "C" void kernel_launch(void* const* d_in, const int* in_sizes, int n_in,
                              void* d_out, int out_size)
{
    const float* x      = (const float*)d_in[0];
    const float* mask_h = (const float*)d_in[1];
    const float* mask_w = (const float*)d_in[2];
    const float* Wq = (const float*)d_in[3];
    const float* bq = (const float*)d_in[4];
    const float* Wk = (const float*)d_in[5];
    const float* bk = (const float*)d_in[6];
    const float* Wv = (const float*)d_in[7];
    const float* bv = (const float*)d_in[8];
    const float* Wl = (const float*)d_in[9];
    const float* bl = (const float*)d_in[10];
    const float* Wo = (const float*)d_in[11];
    const float* bo = (const float*)d_in[12];
    float* out = (float*)d_out;

    float *v, *lepe;
    __half *xh, *ah, *wh, *qh, *ql, *kk, *vv, *v1;
    cudaGetSymbolAddress((void**)&v,    g_v);
    cudaGetSymbolAddress((void**)&lepe, g_lepe);
    cudaGetSymbolAddress((void**)&xh,   g_xh);
    cudaGetSymbolAddress((void**)&ah,   g_ah);
    cudaGetSymbolAddress((void**)&wh,   g_wh);
    cudaGetSymbolAddress((void**)&qh,   g_qh);
    cudaGetSymbolAddress((void**)&ql,   g_ql);
    cudaGetSymbolAddress((void**)&kk,   g_k);
    cudaGetSymbolAddress((void**)&vv,   g_vh);
    cudaGetSymbolAddress((void**)&v1,   g_v1);

    static int smem_set = 0;
    if (!smem_set) {
        cudaFuncSetAttribute(gemm_qkv,
                             cudaFuncAttributeMaxDynamicSharedMemorySize,
                             GEMM_SMEM);
        cudaFuncSetAttribute(gemm_out,
                             cudaFuncAttributeMaxDynamicSharedMemorySize,
                             GEMM_SMEM);
        cudaFuncSetAttribute(attn_f16<false>,
                             cudaFuncAttributeMaxDynamicSharedMemorySize,
                             AT_SMEM);
        cudaFuncSetAttribute(attn_f16<true>,
                             cudaFuncAttributeMaxDynamicSharedMemorySize,
                             AT_SMEM);
        smem_set = 1;
    }

    const float scaling = 0.17677669529663687f;  // 32^-0.5

    // 1) Conversions (x -> fp16; W -> fp16).
    split_all<<<8448, 256>>>(x, Wq, Wk, Wv, Wo, xh, wh);

    // 2) QKV projection: q fp16 hi/lo; k, v fp16; v fp32 for LePE.
    gemm_qkv<<<dim3(1, 256, 3), 512, GEMM_SMEM>>>(
        xh, wh, bq, bk, bv, qh, ql, kk, vv, v, scaling);

    // 3) LePE.
    lepe_kernel<<<ELEMS / 4 / 256, 256>>>(v, Wl, bl, lepe);

    dim3 attn_grid(4, 64, 8);
    // 4) Width-axis attention -> v1 (fp16).
    attn_f16<false><<<attn_grid, 256, AT_SMEM>>>(
        qh, ql, kk, vv, mask_w, nullptr, v1,
        /*y_stride=*/64 * 256, /*row_stride=*/256);
    // 5) Height-axis attention (V = v1) + LePE -> fp16 out-proj input.
    attn_f16<true><<<attn_grid, 256, AT_SMEM>>>(
        qh, ql, kk, v1, mask_h, lepe, ah,
        /*y_stride=*/256, /*row_stride=*/64 * 256);

    // 6) Output projection (fp32 out).
    gemm_out<<<dim3(1, 256, 1), 512, GEMM_SMEM>>>(
        ah, wh + 3 * 65536, bo, out);
}

// round 16
// speedup vs baseline: 2.7078x; 1.0331x over previous
#include <cuda_runtime.h>
#include <cuda_fp16.h>
#include <cstdint>

// Problem constants: B=8, H=64, W=64, C=256, NUM_HEADS=8, KEY_DIM=32
#define M_TOT   32768
#define C_DIM   256
#define ELEMS   (M_TOT * C_DIM)   // 8388608

// ---------------- scratch (device globals; no allocation allowed) ----------
__device__ __align__(16) float g_v[ELEMS];      // v fp32 (LePE input)
__device__ __align__(16) float g_lepe[ELEMS];

__device__ __align__(16) __half g_xh[ELEMS];    // x fp16 (GEMM A)
__device__ __align__(16) __half g_ah[ELEMS];    // attn+lepe fp16 (out-proj A)
__device__ __align__(16) __half g_wh[4 * 65536];// Wq,Wk,Wv,Wo fp16

__device__ __align__(16) __half g_qh[ELEMS];    // q hi
__device__ __align__(16) __half g_ql[ELEMS];    // q lo
__device__ __align__(16) __half g_k[ELEMS];     // k (scaled) fp16
__device__ __align__(16) __half g_vh[ELEMS];    // v fp16
__device__ __align__(16) __half g_v1[ELEMS];    // v1 fp16

// ---------------- helpers ---------------------------------------------------
__device__ __forceinline__ uint32_t smem_u32(const void* p) {
    uint32_t a;
    asm("{ .reg .u64 t; cvta.to.shared.u64 t, %1; cvt.u32.u64 %0, t; }"
        : "=r"(a) : "l"(p));
    return a;
}

__device__ __forceinline__ void cpa16(uint32_t dst, const void* src) {
    asm volatile("cp.async.ca.shared.global [%0], [%1], 16;"
                 :: "r"(dst), "l"(src));
}

__device__ __forceinline__ void mma_f16(float* c, const uint32_t* a,
                                        uint32_t b0, uint32_t b1)
{
    asm volatile(
        "mma.sync.aligned.m16n8k16.row.col.f32.f16.f16.f32 "
        "{%0,%1,%2,%3}, {%4,%5,%6,%7}, {%8,%9}, {%0,%1,%2,%3};"
        : "+f"(c[0]), "+f"(c[1]), "+f"(c[2]), "+f"(c[3])
        : "r"(a[0]), "r"(a[1]), "r"(a[2]), "r"(a[3]), "r"(b0), "r"(b1));
}

__device__ __forceinline__ void ldm_x4(uint32_t* r, uint32_t addr) {
    asm volatile("ldmatrix.sync.aligned.m8n8.x4.shared.b16 {%0,%1,%2,%3}, [%4];"
        : "=r"(r[0]), "=r"(r[1]), "=r"(r[2]), "=r"(r[3]) : "r"(addr));
}

__device__ __forceinline__ void ldm_x2t(uint32_t* r, uint32_t addr) {
    asm volatile("ldmatrix.sync.aligned.m8n8.x2.trans.shared.b16 {%0,%1}, [%2];"
        : "=r"(r[0]), "=r"(r[1]) : "r"(addr));
}

// fp16 hi/lo split pack
__device__ __forceinline__ uint32_t packsplit_h(float x0, float x1, uint32_t& lo) {
    __half h0 = __float2half_rn(x0), h1 = __float2half_rn(x1);
    float r0 = x0 - __half2float(h0);
    float r1 = x1 - __half2float(h1);
    __half l0 = __float2half_rn(r0), l1 = __float2half_rn(r1);
    lo = (uint32_t)__half_as_ushort(l0) |
         ((uint32_t)__half_as_ushort(l1) << 16);
    return (uint32_t)__half_as_ushort(h0) |
           ((uint32_t)__half_as_ushort(h1) << 16);
}

__device__ __forceinline__ uint32_t pack_h(float x0, float x1) {
    return (uint32_t)__half_as_ushort(__float2half_rn(x0)) |
           ((uint32_t)__half_as_ushort(__float2half_rn(x1)) << 16);
}

// ---------------------------------------------------------------------------
// Merged split kernel: blocks [0, 8192) convert x to fp16;
// blocks [8192, 8448) convert the four weight matrices to fp16.
// ---------------------------------------------------------------------------
__global__ __launch_bounds__(256)
void split_all(const float* __restrict__ x,
               const float* __restrict__ W0, const float* __restrict__ W1,
               const float* __restrict__ W2, const float* __restrict__ W3,
               __half* __restrict__ xh, __half* __restrict__ wh)
{
    if (blockIdx.x < 8192) {
        const int i = blockIdx.x * 256 + threadIdx.x;
        float4 v = ((const float4*)x)[i];
        ((uint2*)xh)[i] = make_uint2(pack_h(v.x, v.y), pack_h(v.z, v.w));
    } else {
        const int wblk = blockIdx.x - 8192;
        const int w = wblk >> 6;
        const float* W = (w == 0) ? W0 : (w == 1) ? W1 : (w == 2) ? W2 : W3;
        const int i = (wblk & 63) * 256 + threadIdx.x;
        float4 v = ((const float4*)W)[i];
        ((uint2*)wh)[w * 16384 + i] = make_uint2(pack_h(v.x, v.y),
                                                 pack_h(v.z, v.w));
    }
}

// ---------------------------------------------------------------------------
// Plain fp16 HMMA GEMM (single product, fp32 accumulate).
// CTA tile 128x256 (full N), 512 threads = 16 warps (4m x 4n), warp tile 32x64.
// ---------------------------------------------------------------------------
#define A_TILE_B  10240        // 128 * 80
#define B_TILE_B  20480        // 256 * 80
#define STAGE_B   (A_TILE_B + B_TILE_B)           // 30720
#define GEMM_SMEM (2 * STAGE_B)                   // 61440

__device__ __forceinline__
void gemm_main(float acc[2][8][4],
               const __half* __restrict__ Ah,
               const __half* __restrict__ Bh,
               int m0, uint32_t smem_base)
{
    const int tid  = threadIdx.x;
    const int lane = tid & 31;
    const int warp = tid >> 5;
    const int wm   = warp >> 2;
    const int wn   = warp & 3;

    const uint4* gAh = (const uint4*)Ah + (size_t)m0 * 32;
    const uint4* gBh = (const uint4*)Bh;

    auto issue = [&](int chunk, int stg) {
        const int kq4 = chunk * 4;
        const uint32_t sb = smem_base + stg * STAGE_B;
        {
            const int r = tid >> 2, q = tid & 3;
            const uint32_t off = (uint32_t)(r * 80 + q * 16);
            cpa16(sb + off, gAh + (size_t)r * 32 + kq4 + q);
        }
#pragma unroll
        for (int rep = 0; rep < 2; rep++) {
            const int li = rep * 512 + tid;
            const int r = li >> 2, q = li & 3;
            const uint32_t off = (uint32_t)(r * 80 + q * 16);
            cpa16(sb + A_TILE_B + off, gBh + (size_t)r * 32 + kq4 + q);
        }
    };

    issue(0, 0);
    asm volatile("cp.async.commit_group;" ::: "memory");

    for (int c = 0; c < 8; c++) {
        if (c + 1 < 8) issue(c + 1, (c + 1) & 1);
        asm volatile("cp.async.commit_group;" ::: "memory");
        asm volatile("cp.async.wait_group 1;" ::: "memory");
        __syncthreads();

        const uint32_t sb  = smem_base + (c & 1) * STAGE_B;
        const uint32_t sAh = sb;
        const uint32_t sBh = sb + A_TILE_B;

#pragma unroll
        for (int ks = 0; ks < 2; ks++) {
            const int kb = ks * 16;
            uint32_t ah[2][4];
            const int arow = wm * 32 + (lane & 15);
            const int acol = kb + ((lane >> 4) << 3);
#pragma unroll
            for (int i = 0; i < 2; i++) {
                const uint32_t off = (uint32_t)((arow + i * 16) * 80 + acol * 2);
                ldm_x4(ah[i], sAh + off);
            }
            const int brow0 = wn * 64 + ((lane >> 4) & 1) * 8 + (lane & 7);
            const int bcol  = kb + ((lane >> 3) & 1) * 8;
#pragma unroll
            for (int jp = 0; jp < 4; jp++) {
                uint32_t bh[4];
                const uint32_t off = (uint32_t)((brow0 + jp * 16) * 80 + bcol * 2);
                ldm_x4(bh, sBh + off);
#pragma unroll
                for (int jj = 0; jj < 2; jj++) {
                    const int j = jp * 2 + jj;
#pragma unroll
                    for (int i = 0; i < 2; i++)
                        mma_f16(acc[i][j], ah[i], bh[jj * 2], bh[jj * 2 + 1]);
                }
            }
        }
        __syncthreads();
    }
}

// ---------------------------------------------------------------------------
// QKV GEMM: grid.z selects q/k/v.
// q -> fp16 hi/lo; k -> fp16 single (scaled); v -> fp16 single + fp32.
// ---------------------------------------------------------------------------
__global__ __launch_bounds__(512)
void gemm_qkv(const __half* __restrict__ Ah, const __half* __restrict__ Wh,
              const float* __restrict__ bq, const float* __restrict__ bk,
              const float* __restrict__ bv,
              __half* __restrict__ qh, __half* __restrict__ ql,
              __half* __restrict__ kk, __half* __restrict__ vv,
              float* __restrict__ vf, float kscale)
{
    extern __shared__ __align__(16) char gsm[];
    const int z = blockIdx.z;
    const int m0 = blockIdx.y * 128;

    float acc[2][8][4];
#pragma unroll
    for (int i = 0; i < 2; i++)
#pragma unroll
        for (int j = 0; j < 8; j++)
#pragma unroll
            for (int t = 0; t < 4; t++) acc[i][j][t] = 0.f;

    gemm_main(acc, Ah, Wh + z * 65536, m0, smem_u32(gsm));

    const float* bias = (z == 0) ? bq : (z == 1) ? bk : bv;
    const float scale = (z == 1) ? kscale : 1.0f;

    const int lane = threadIdx.x & 31;
    const int warp = threadIdx.x >> 5;
    const int wm = warp >> 2, wn = warp & 3;
    const int gid = lane >> 2, tig = lane & 3;

#pragma unroll
    for (int i = 0; i < 2; i++) {
        const int row = m0 + wm * 32 + i * 16 + gid;
#pragma unroll
        for (int j = 0; j < 8; j++) {
            const int col = wn * 64 + j * 8 + tig * 2;
            const float b0 = bias[col], b1 = bias[col + 1];
            const float x0 = (acc[i][j][0] + b0) * scale;
            const float x1 = (acc[i][j][1] + b1) * scale;
            const float y0 = (acc[i][j][2] + b0) * scale;
            const float y1 = (acc[i][j][3] + b1) * scale;
            const size_t o0 = (size_t)row * 256 + col;
            const size_t o1 = o0 + 8 * 256;
            if (z == 0) {
                uint32_t lo;
                uint32_t hi = packsplit_h(x0, x1, lo);
                *(uint32_t*)(qh + o0) = hi;
                *(uint32_t*)(ql + o0) = lo;
                hi = packsplit_h(y0, y1, lo);
                *(uint32_t*)(qh + o1) = hi;
                *(uint32_t*)(ql + o1) = lo;
            } else if (z == 1) {
                *(uint32_t*)(kk + o0) = pack_h(x0, x1);
                *(uint32_t*)(kk + o1) = pack_h(y0, y1);
            } else {
                *(uint32_t*)(vv + o0) = pack_h(x0, x1);
                *(uint32_t*)(vv + o1) = pack_h(y0, y1);
                *(float2*)(vf + o0) = make_float2(x0, x1);
                *(float2*)(vf + o1) = make_float2(y0, y1);
            }
        }
    }
}

// ---------------------------------------------------------------------------
// Output projection GEMM: fp32 out.
// ---------------------------------------------------------------------------
__global__ __launch_bounds__(512)
void gemm_out(const __half* __restrict__ Ah, const __half* __restrict__ Wh,
              const float* __restrict__ bias, float* __restrict__ out)
{
    extern __shared__ __align__(16) char gsm[];
    const int m0 = blockIdx.y * 128;

    float acc[2][8][4];
#pragma unroll
    for (int i = 0; i < 2; i++)
#pragma unroll
        for (int j = 0; j < 8; j++)
#pragma unroll
            for (int t = 0; t < 4; t++) acc[i][j][t] = 0.f;

    gemm_main(acc, Ah, Wh, m0, smem_u32(gsm));

    const int lane = threadIdx.x & 31;
    const int warp = threadIdx.x >> 5;
    const int wm = warp >> 2, wn = warp & 3;
    const int gid = lane >> 2, tig = lane & 3;

#pragma unroll
    for (int i = 0; i < 2; i++) {
        const int row = m0 + wm * 32 + i * 16 + gid;
#pragma unroll
        for (int j = 0; j < 8; j++) {
            const int col = wn * 64 + j * 8 + tig * 2;
            const float b0 = bias[col], b1 = bias[col + 1];
            *(float2*)(out + (size_t)row * 256 + col) =
                make_float2(acc[i][j][0] + b0, acc[i][j][1] + b1);
            *(float2*)(out + (size_t)(row + 8) * 256 + col) =
                make_float2(acc[i][j][2] + b0, acc[i][j][3] + b1);
        }
    }
}

// ---------------------------------------------------------------------------
// LePE: 5x5 depthwise conv, register-blocked 4x (x) by 2x (y) per thread.
// 48 loads for 8 outputs (6 loads/output vs 10 before).
// ---------------------------------------------------------------------------
__global__ __launch_bounds__(256)
void lepe_kernel(const float* __restrict__ V,
                 const float* __restrict__ Wl,
                 const float* __restrict__ bl,
                 float* __restrict__ out)
{
    const int idx = blockIdx.x * 256 + threadIdx.x;   // over ELEMS/8
    const int c  = idx & 255;
    const int xg = (idx >> 8) & 15;
    const int yg = (idx >> 12) & 31;
    const int b  = idx >> 17;
    const int x0 = xg * 4;
    const int y0 = yg * 2;

    float w[5][5];
#pragma unroll
    for (int dy = 0; dy < 5; dy++)
#pragma unroll
        for (int dx = 0; dx < 5; dx++)
            w[dy][dx] = Wl[(dy * 5 + dx) * 256 + c];

    const float bias = bl[c];
    float acc[2][4];
#pragma unroll
    for (int uy = 0; uy < 2; uy++)
#pragma unroll
        for (int ux = 0; ux < 4; ux++) acc[uy][ux] = bias;

#pragma unroll
    for (int ry = 0; ry < 6; ry++) {
        const int yy = y0 + ry - 2;
        if (yy < 0 || yy > 63) continue;
        const float* vrow = V + (size_t)(((b << 6) + yy) << 6) * 256 + c;
#pragma unroll
        for (int e = 0; e < 8; e++) {
            const int xx = x0 - 2 + e;
            if (xx < 0 || xx > 63) continue;
            const float val = vrow[(size_t)xx * 256];
#pragma unroll
            for (int uy = 0; uy < 2; uy++) {
                const int dyi = ry - uy;
                if (dyi < 0 || dyi > 4) continue;
#pragma unroll
                for (int ux = 0; ux < 4; ux++) {
                    const int dxi = e - ux;
                    if (dxi >= 0 && dxi < 5) acc[uy][ux] += val * w[dyi][dxi];
                }
            }
        }
    }

#pragma unroll
    for (int uy = 0; uy < 2; uy++) {
        float* orow = out + (size_t)((((b << 6) + y0 + uy) << 6) + x0) * 256 + c;
#pragma unroll
        for (int ux = 0; ux < 4; ux++) orow[(size_t)ux * 256] = acc[uy][ux];
    }
}

// ---------------------------------------------------------------------------
// fp16 HMMA axis attention, 2 heads per block.
// Q = hi/lo fp16 (exact); K, V, P = single fp16.
// FUSE=false: out -> v1 single fp16.
// FUSE=true : +LePE -> single fp16 (out-projection A input).
// ---------------------------------------------------------------------------
#define AT_ROW   144
#define AT_TILE  (64 * AT_ROW)
#define AT_SMEM  (4 * AT_TILE)        // Qh, Ql, K, V

template <bool FUSE>
__global__ __launch_bounds__(256)
void attn_f16(const __half* __restrict__ Qh, const __half* __restrict__ Ql,
              const __half* __restrict__ K, const __half* __restrict__ V,
              const float* __restrict__ mask,
              const float* __restrict__ lepe,
              __half* __restrict__ O,
              int y_stride, int row_stride)
{
    extern __shared__ __align__(16) char asm_[];
    const uint32_t sm = smem_u32(asm_);
    const uint32_t sQh = sm, sQl = sm + AT_TILE;
    const uint32_t sK  = sm + 2 * AT_TILE, sV = sm + 3 * AT_TILE;

    const int np = blockIdx.x;
    const int y  = blockIdx.y;
    const int b  = blockIdx.z;
    const int tid  = threadIdx.x;
    const int lane = tid & 31;
    const int wg   = tid >> 7;
    const int w    = (tid >> 5) & 3;
    const int gid  = lane >> 2;
    const int tig  = lane & 3;
    const int n    = np * 2 + wg;
    const int hb   = wg * 64;

    const size_t base = (size_t)b * (64 * 64 * 256) + (size_t)y * y_stride
                        + np * 64;

#pragma unroll
    for (int i = tid; i < 512; i += 256) {
        const int r = i >> 3, c8 = (i & 7) * 8;
        const size_t g = base + (size_t)r * row_stride + c8;
        const uint32_t so = (uint32_t)(r * AT_ROW + c8 * 2);
        cpa16(sQh + so, Qh + g);
        cpa16(sQl + so, Ql + g);
        cpa16(sK  + so, K  + g);
        cpa16(sV  + so, V  + g);
    }
    asm volatile("cp.async.commit_group;" ::: "memory");
    asm volatile("cp.async.wait_group 0;" ::: "memory");
    __syncthreads();

    uint32_t qh[2][4], ql[2][4];
    {
        const int arow = 16 * w + (lane & 15);
        const int acol = (lane >> 4) << 3;
#pragma unroll
        for (int kc = 0; kc < 2; kc++) {
            const uint32_t off = (uint32_t)(arow * AT_ROW + hb
                                            + (kc * 16 + acol) * 2);
            ldm_x4(qh[kc], sQh + off);
            ldm_x4(ql[kc], sQl + off);
        }
    }

    float sacc[8][4];
#pragma unroll
    for (int j = 0; j < 8; j++)
#pragma unroll
        for (int t = 0; t < 4; t++) sacc[j][t] = 0.f;

    {
        const int krow = ((lane >> 4) & 1) * 8 + (lane & 7);
        const int kcol = ((lane >> 3) & 1) * 8;
#pragma unroll
        for (int kc = 0; kc < 2; kc++)
#pragma unroll
            for (int jp = 0; jp < 4; jp++) {
                uint32_t kv[4];
                const uint32_t off = (uint32_t)((16 * jp + krow) * AT_ROW + hb
                                                + (kc * 16 + kcol) * 2);
                ldm_x4(kv, sK + off);
#pragma unroll
                for (int jj = 0; jj < 2; jj++) {
                    const int j = jp * 2 + jj;
                    mma_f16(sacc[j], qh[kc], kv[jj * 2], kv[jj * 2 + 1]);
                    mma_f16(sacc[j], ql[kc], kv[jj * 2], kv[jj * 2 + 1]);
                }
            }
    }

    const int r0 = 16 * w + gid;
    const int r1 = r0 + 8;
    const float* mbase = mask + (size_t)n * 4096;
    float mx0 = -1e30f, mx1 = -1e30f;
#pragma unroll
    for (int j = 0; j < 8; j++) {
        const float2 m0 = *(const float2*)(mbase + r0 * 64 + j * 8 + tig * 2);
        const float2 m1 = *(const float2*)(mbase + r1 * 64 + j * 8 + tig * 2);
        sacc[j][0] += m0.x; sacc[j][1] += m0.y;
        sacc[j][2] += m1.x; sacc[j][3] += m1.y;
        mx0 = fmaxf(mx0, fmaxf(sacc[j][0], sacc[j][1]));
        mx1 = fmaxf(mx1, fmaxf(sacc[j][2], sacc[j][3]));
    }
    mx0 = fmaxf(mx0, __shfl_xor_sync(0xffffffffu, mx0, 1));
    mx0 = fmaxf(mx0, __shfl_xor_sync(0xffffffffu, mx0, 2));
    mx1 = fmaxf(mx1, __shfl_xor_sync(0xffffffffu, mx1, 1));
    mx1 = fmaxf(mx1, __shfl_xor_sync(0xffffffffu, mx1, 2));

    float sum0 = 0.f, sum1 = 0.f;
#pragma unroll
    for (int j = 0; j < 8; j++) {
        sacc[j][0] = __expf(sacc[j][0] - mx0);
        sacc[j][1] = __expf(sacc[j][1] - mx0);
        sacc[j][2] = __expf(sacc[j][2] - mx1);
        sacc[j][3] = __expf(sacc[j][3] - mx1);
        sum0 += sacc[j][0] + sacc[j][1];
        sum1 += sacc[j][2] + sacc[j][3];
    }
    sum0 += __shfl_xor_sync(0xffffffffu, sum0, 1);
    sum0 += __shfl_xor_sync(0xffffffffu, sum0, 2);
    sum1 += __shfl_xor_sync(0xffffffffu, sum1, 1);
    sum1 += __shfl_xor_sync(0xffffffffu, sum1, 2);
    const float inv0 = 1.f / sum0;
    const float inv1 = 1.f / sum1;

    // Repack P (unnormalized, in (0,1]) into single-fp16 A-fragments.
    uint32_t ph[4][4];
#pragma unroll
    for (int kc = 0; kc < 4; kc++) {
        const int t0 = 2 * kc, t1 = 2 * kc + 1;
        ph[kc][0] = pack_h(sacc[t0][0], sacc[t0][1]);
        ph[kc][1] = pack_h(sacc[t0][2], sacc[t0][3]);
        ph[kc][2] = pack_h(sacc[t1][0], sacc[t1][1]);
        ph[kc][3] = pack_h(sacc[t1][2], sacc[t1][3]);
    }

    float oacc[4][4];
#pragma unroll
    for (int jd = 0; jd < 4; jd++)
#pragma unroll
        for (int t = 0; t < 4; t++) oacc[jd][t] = 0.f;

    {
        const int vrow = lane & 15;
#pragma unroll
        for (int kc = 0; kc < 4; kc++)
#pragma unroll
            for (int jd = 0; jd < 4; jd++) {
                uint32_t vv[2];
                const uint32_t off = (uint32_t)((16 * kc + vrow) * AT_ROW + hb
                                                + jd * 16);
                ldm_x2t(vv, sV + off);
                mma_f16(oacc[jd], ph[kc], vv[0], vv[1]);
            }
    }

#pragma unroll
    for (int jd = 0; jd < 4; jd++) {
        float x0 = oacc[jd][0] * inv0, x1 = oacc[jd][1] * inv0;
        float y0 = oacc[jd][2] * inv1, y1 = oacc[jd][3] * inv1;
        const int d = wg * 32 + jd * 8 + tig * 2;
        const size_t o0 = base + (size_t)r0 * row_stride + d;
        const size_t o1 = base + (size_t)r1 * row_stride + d;
        if (FUSE) {
            const float2 lp0 = *(const float2*)(lepe + o0);
            const float2 lp1 = *(const float2*)(lepe + o1);
            x0 += lp0.x; x1 += lp0.y;
            y0 += lp1.x; y1 += lp1.y;
        }
        *(uint32_t*)(O + o0) = pack_h(x0, x1);
        *(uint32_t*)(O + o1) = pack_h(y0, y1);
    }
}

// ---------------------------------------------------------------------------
extern "C" void kernel_launch(void* const* d_in, const int* in_sizes, int n_in,
                              void* d_out, int out_size)
{
    const float* x      = (const float*)d_in[0];
    const float* mask_h = (const float*)d_in[1];
    const float* mask_w = (const float*)d_in[2];
    const float* Wq = (const float*)d_in[3];
    const float* bq = (const float*)d_in[4];
    const float* Wk = (const float*)d_in[5];
    const float* bk = (const float*)d_in[6];
    const float* Wv = (const float*)d_in[7];
    const float* bv = (const float*)d_in[8];
    const float* Wl = (const float*)d_in[9];
    const float* bl = (const float*)d_in[10];
    const float* Wo = (const float*)d_in[11];
    const float* bo = (const float*)d_in[12];
    float* out = (float*)d_out;

    float *v, *lepe;
    __half *xh, *ah, *wh, *qh, *ql, *kk, *vv, *v1;
    cudaGetSymbolAddress((void**)&v,    g_v);
    cudaGetSymbolAddress((void**)&lepe, g_lepe);
    cudaGetSymbolAddress((void**)&xh,   g_xh);
    cudaGetSymbolAddress((void**)&ah,   g_ah);
    cudaGetSymbolAddress((void**)&wh,   g_wh);
    cudaGetSymbolAddress((void**)&qh,   g_qh);
    cudaGetSymbolAddress((void**)&ql,   g_ql);
    cudaGetSymbolAddress((void**)&kk,   g_k);
    cudaGetSymbolAddress((void**)&vv,   g_vh);
    cudaGetSymbolAddress((void**)&v1,   g_v1);

    static int smem_set = 0;
    if (!smem_set) {
        cudaFuncSetAttribute(gemm_qkv,
                             cudaFuncAttributeMaxDynamicSharedMemorySize,
                             GEMM_SMEM);
        cudaFuncSetAttribute(gemm_out,
                             cudaFuncAttributeMaxDynamicSharedMemorySize,
                             GEMM_SMEM);
        cudaFuncSetAttribute(attn_f16<false>,
                             cudaFuncAttributeMaxDynamicSharedMemorySize,
                             AT_SMEM);
        cudaFuncSetAttribute(attn_f16<true>,
                             cudaFuncAttributeMaxDynamicSharedMemorySize,
                             AT_SMEM);
        smem_set = 1;
    }

    const float scaling = 0.17677669529663687f;  // 32^-0.5

    // 1) Conversions (x -> fp16; W -> fp16).
    split_all<<<8448, 256>>>(x, Wq, Wk, Wv, Wo, xh, wh);

    // 2) QKV projection: q fp16 hi/lo; k, v fp16; v fp32 for LePE.
    gemm_qkv<<<dim3(1, 256, 3), 512, GEMM_SMEM>>>(
        xh, wh, bq, bk, bv, qh, ql, kk, vv, v, scaling);

    // 3) LePE (4x2 register blocking).
    lepe_kernel<<<ELEMS / 8 / 256, 256>>>(v, Wl, bl, lepe);

    dim3 attn_grid(4, 64, 8);
    // 4) Width-axis attention -> v1 (fp16).
    attn_f16<false><<<attn_grid, 256, AT_SMEM>>>(
        qh, ql, kk, vv, mask_w, nullptr, v1,
        /*y_stride=*/64 * 256, /*row_stride=*/256);
    // 5) Height-axis attention (V = v1) + LePE -> fp16 out-proj input.
    attn_f16<true><<<attn_grid, 256, AT_SMEM>>>(
        qh, ql, kk, v1, mask_h, lepe, ah,
        /*y_stride=*/256, /*row_stride=*/64 * 256);

    // 6) Output projection (fp32 out).
    gemm_out<<<dim3(1, 256, 1), 512, GEMM_SMEM>>>(
        ah, wh + 3 * 65536, bo, out);
}

// round 17
// speedup vs baseline: 2.7866x; 1.0291x over previous
#include <cuda_runtime.h>
#include <cuda_fp16.h>
#include <cstdint>

// Problem constants: B=8, H=64, W=64, C=256, NUM_HEADS=8, KEY_DIM=32
#define M_TOT   32768
#define C_DIM   256
#define ELEMS   (M_TOT * C_DIM)   // 8388608

// ---------------- scratch (device globals; no allocation allowed) ----------
__device__ __align__(16) __half g_lepe[ELEMS];  // LePE output (fp16)

__device__ __align__(16) __half g_xh[ELEMS];    // x fp16 (GEMM A)
__device__ __align__(16) __half g_ah[ELEMS];    // attn+lepe fp16 (out-proj A)
__device__ __align__(16) __half g_wh[4 * 65536];// Wq,Wk,Wv,Wo fp16

__device__ __align__(16) __half g_qh[ELEMS];    // q hi
__device__ __align__(16) __half g_ql[ELEMS];    // q lo
__device__ __align__(16) __half g_k[ELEMS];     // k (scaled) fp16
__device__ __align__(16) __half g_vh[ELEMS];    // v fp16
__device__ __align__(16) __half g_v1[ELEMS];    // v1 fp16

// ---------------- helpers ---------------------------------------------------
__device__ __forceinline__ uint32_t smem_u32(const void* p) {
    uint32_t a;
    asm("{ .reg .u64 t; cvta.to.shared.u64 t, %1; cvt.u32.u64 %0, t; }"
        : "=r"(a) : "l"(p));
    return a;
}

__device__ __forceinline__ void cpa16(uint32_t dst, const void* src) {
    asm volatile("cp.async.ca.shared.global [%0], [%1], 16;"
                 :: "r"(dst), "l"(src));
}

__device__ __forceinline__ void mma_f16(float* c, const uint32_t* a,
                                        uint32_t b0, uint32_t b1)
{
    asm volatile(
        "mma.sync.aligned.m16n8k16.row.col.f32.f16.f16.f32 "
        "{%0,%1,%2,%3}, {%4,%5,%6,%7}, {%8,%9}, {%0,%1,%2,%3};"
        : "+f"(c[0]), "+f"(c[1]), "+f"(c[2]), "+f"(c[3])
        : "r"(a[0]), "r"(a[1]), "r"(a[2]), "r"(a[3]), "r"(b0), "r"(b1));
}

__device__ __forceinline__ void ldm_x4(uint32_t* r, uint32_t addr) {
    asm volatile("ldmatrix.sync.aligned.m8n8.x4.shared.b16 {%0,%1,%2,%3}, [%4];"
        : "=r"(r[0]), "=r"(r[1]), "=r"(r[2]), "=r"(r[3]) : "r"(addr));
}

__device__ __forceinline__ void ldm_x2t(uint32_t* r, uint32_t addr) {
    asm volatile("ldmatrix.sync.aligned.m8n8.x2.trans.shared.b16 {%0,%1}, [%2];"
        : "=r"(r[0]), "=r"(r[1]) : "r"(addr));
}

// fp16 hi/lo split pack
__device__ __forceinline__ uint32_t packsplit_h(float x0, float x1, uint32_t& lo) {
    __half h0 = __float2half_rn(x0), h1 = __float2half_rn(x1);
    float r0 = x0 - __half2float(h0);
    float r1 = x1 - __half2float(h1);
    __half l0 = __float2half_rn(r0), l1 = __float2half_rn(r1);
    lo = (uint32_t)__half_as_ushort(l0) |
         ((uint32_t)__half_as_ushort(l1) << 16);
    return (uint32_t)__half_as_ushort(h0) |
           ((uint32_t)__half_as_ushort(h1) << 16);
}

__device__ __forceinline__ uint32_t pack_h(float x0, float x1) {
    return (uint32_t)__half_as_ushort(__float2half_rn(x0)) |
           ((uint32_t)__half_as_ushort(__float2half_rn(x1)) << 16);
}

// ---------------------------------------------------------------------------
// Merged split kernel: blocks [0, 8192) convert x to fp16;
// blocks [8192, 8448) convert the four weight matrices to fp16.
// ---------------------------------------------------------------------------
__global__ __launch_bounds__(256)
void split_all(const float* __restrict__ x,
               const float* __restrict__ W0, const float* __restrict__ W1,
               const float* __restrict__ W2, const float* __restrict__ W3,
               __half* __restrict__ xh, __half* __restrict__ wh)
{
    if (blockIdx.x < 8192) {
        const int i = blockIdx.x * 256 + threadIdx.x;
        float4 v = ((const float4*)x)[i];
        ((uint2*)xh)[i] = make_uint2(pack_h(v.x, v.y), pack_h(v.z, v.w));
    } else {
        const int wblk = blockIdx.x - 8192;
        const int w = wblk >> 6;
        const float* W = (w == 0) ? W0 : (w == 1) ? W1 : (w == 2) ? W2 : W3;
        const int i = (wblk & 63) * 256 + threadIdx.x;
        float4 v = ((const float4*)W)[i];
        ((uint2*)wh)[w * 16384 + i] = make_uint2(pack_h(v.x, v.y),
                                                 pack_h(v.z, v.w));
    }
}

// ---------------------------------------------------------------------------
// Plain fp16 HMMA GEMM (single product, fp32 accumulate).
// CTA tile 128x256 (full N), 512 threads = 16 warps (4m x 4n), warp tile 32x64.
// ---------------------------------------------------------------------------
#define A_TILE_B  10240        // 128 * 80
#define B_TILE_B  20480        // 256 * 80
#define STAGE_B   (A_TILE_B + B_TILE_B)           // 30720
#define GEMM_SMEM (2 * STAGE_B)                   // 61440

__device__ __forceinline__
void gemm_main(float acc[2][8][4],
               const __half* __restrict__ Ah,
               const __half* __restrict__ Bh,
               int m0, uint32_t smem_base)
{
    const int tid  = threadIdx.x;
    const int lane = tid & 31;
    const int warp = tid >> 5;
    const int wm   = warp >> 2;
    const int wn   = warp & 3;

    const uint4* gAh = (const uint4*)Ah + (size_t)m0 * 32;
    const uint4* gBh = (const uint4*)Bh;

    auto issue = [&](int chunk, int stg) {
        const int kq4 = chunk * 4;
        const uint32_t sb = smem_base + stg * STAGE_B;
        {
            const int r = tid >> 2, q = tid & 3;
            const uint32_t off = (uint32_t)(r * 80 + q * 16);
            cpa16(sb + off, gAh + (size_t)r * 32 + kq4 + q);
        }
#pragma unroll
        for (int rep = 0; rep < 2; rep++) {
            const int li = rep * 512 + tid;
            const int r = li >> 2, q = li & 3;
            const uint32_t off = (uint32_t)(r * 80 + q * 16);
            cpa16(sb + A_TILE_B + off, gBh + (size_t)r * 32 + kq4 + q);
        }
    };

    issue(0, 0);
    asm volatile("cp.async.commit_group;" ::: "memory");

    for (int c = 0; c < 8; c++) {
        if (c + 1 < 8) issue(c + 1, (c + 1) & 1);
        asm volatile("cp.async.commit_group;" ::: "memory");
        asm volatile("cp.async.wait_group 1;" ::: "memory");
        __syncthreads();

        const uint32_t sb  = smem_base + (c & 1) * STAGE_B;
        const uint32_t sAh = sb;
        const uint32_t sBh = sb + A_TILE_B;

#pragma unroll
        for (int ks = 0; ks < 2; ks++) {
            const int kb = ks * 16;
            uint32_t ah[2][4];
            const int arow = wm * 32 + (lane & 15);
            const int acol = kb + ((lane >> 4) << 3);
#pragma unroll
            for (int i = 0; i < 2; i++) {
                const uint32_t off = (uint32_t)((arow + i * 16) * 80 + acol * 2);
                ldm_x4(ah[i], sAh + off);
            }
            const int brow0 = wn * 64 + ((lane >> 4) & 1) * 8 + (lane & 7);
            const int bcol  = kb + ((lane >> 3) & 1) * 8;
#pragma unroll
            for (int jp = 0; jp < 4; jp++) {
                uint32_t bh[4];
                const uint32_t off = (uint32_t)((brow0 + jp * 16) * 80 + bcol * 2);
                ldm_x4(bh, sBh + off);
#pragma unroll
                for (int jj = 0; jj < 2; jj++) {
                    const int j = jp * 2 + jj;
#pragma unroll
                    for (int i = 0; i < 2; i++)
                        mma_f16(acc[i][j], ah[i], bh[jj * 2], bh[jj * 2 + 1]);
                }
            }
        }
        __syncthreads();
    }
}

// ---------------------------------------------------------------------------
// QKV GEMM: grid.z selects q/k/v.
// q -> fp16 hi/lo; k -> fp16 single (scaled); v -> fp16 single.
// ---------------------------------------------------------------------------
__global__ __launch_bounds__(512)
void gemm_qkv(const __half* __restrict__ Ah, const __half* __restrict__ Wh,
              const float* __restrict__ bq, const float* __restrict__ bk,
              const float* __restrict__ bv,
              __half* __restrict__ qh, __half* __restrict__ ql,
              __half* __restrict__ kk, __half* __restrict__ vv,
              float kscale)
{
    extern __shared__ __align__(16) char gsm[];
    const int z = blockIdx.z;
    const int m0 = blockIdx.y * 128;

    float acc[2][8][4];
#pragma unroll
    for (int i = 0; i < 2; i++)
#pragma unroll
        for (int j = 0; j < 8; j++)
#pragma unroll
            for (int t = 0; t < 4; t++) acc[i][j][t] = 0.f;

    gemm_main(acc, Ah, Wh + z * 65536, m0, smem_u32(gsm));

    const float* bias = (z == 0) ? bq : (z == 1) ? bk : bv;
    const float scale = (z == 1) ? kscale : 1.0f;

    const int lane = threadIdx.x & 31;
    const int warp = threadIdx.x >> 5;
    const int wm = warp >> 2, wn = warp & 3;
    const int gid = lane >> 2, tig = lane & 3;

#pragma unroll
    for (int i = 0; i < 2; i++) {
        const int row = m0 + wm * 32 + i * 16 + gid;
#pragma unroll
        for (int j = 0; j < 8; j++) {
            const int col = wn * 64 + j * 8 + tig * 2;
            const float b0 = bias[col], b1 = bias[col + 1];
            const float x0 = (acc[i][j][0] + b0) * scale;
            const float x1 = (acc[i][j][1] + b1) * scale;
            const float y0 = (acc[i][j][2] + b0) * scale;
            const float y1 = (acc[i][j][3] + b1) * scale;
            const size_t o0 = (size_t)row * 256 + col;
            const size_t o1 = o0 + 8 * 256;
            if (z == 0) {
                uint32_t lo;
                uint32_t hi = packsplit_h(x0, x1, lo);
                *(uint32_t*)(qh + o0) = hi;
                *(uint32_t*)(ql + o0) = lo;
                hi = packsplit_h(y0, y1, lo);
                *(uint32_t*)(qh + o1) = hi;
                *(uint32_t*)(ql + o1) = lo;
            } else if (z == 1) {
                *(uint32_t*)(kk + o0) = pack_h(x0, x1);
                *(uint32_t*)(kk + o1) = pack_h(y0, y1);
            } else {
                *(uint32_t*)(vv + o0) = pack_h(x0, x1);
                *(uint32_t*)(vv + o1) = pack_h(y0, y1);
            }
        }
    }
}

// ---------------------------------------------------------------------------
// Output projection GEMM: fp32 out.
// ---------------------------------------------------------------------------
__global__ __launch_bounds__(512)
void gemm_out(const __half* __restrict__ Ah, const __half* __restrict__ Wh,
              const float* __restrict__ bias, float* __restrict__ out)
{
    extern __shared__ __align__(16) char gsm[];
    const int m0 = blockIdx.y * 128;

    float acc[2][8][4];
#pragma unroll
    for (int i = 0; i < 2; i++)
#pragma unroll
        for (int j = 0; j < 8; j++)
#pragma unroll
            for (int t = 0; t < 4; t++) acc[i][j][t] = 0.f;

    gemm_main(acc, Ah, Wh, m0, smem_u32(gsm));

    const int lane = threadIdx.x & 31;
    const int warp = threadIdx.x >> 5;
    const int wm = warp >> 2, wn = warp & 3;
    const int gid = lane >> 2, tig = lane & 3;

#pragma unroll
    for (int i = 0; i < 2; i++) {
        const int row = m0 + wm * 32 + i * 16 + gid;
#pragma unroll
        for (int j = 0; j < 8; j++) {
            const int col = wn * 64 + j * 8 + tig * 2;
            const float b0 = bias[col], b1 = bias[col + 1];
            *(float2*)(out + (size_t)row * 256 + col) =
                make_float2(acc[i][j][0] + b0, acc[i][j][1] + b1);
            *(float2*)(out + (size_t)(row + 8) * 256 + col) =
                make_float2(acc[i][j][2] + b0, acc[i][j][3] + b1);
        }
    }
}

// ---------------------------------------------------------------------------
// LePE: 5x5 depthwise conv on fp16 v, fp32 accumulate, fp16 out.
// Register-blocked 4x (x) by 2x (y) per thread.
// ---------------------------------------------------------------------------
__global__ __launch_bounds__(256)
void lepe_kernel(const __half* __restrict__ V,
                 const float* __restrict__ Wl,
                 const float* __restrict__ bl,
                 __half* __restrict__ out)
{
    const int idx = blockIdx.x * 256 + threadIdx.x;   // over ELEMS/8
    const int c  = idx & 255;
    const int xg = (idx >> 8) & 15;
    const int yg = (idx >> 12) & 31;
    const int b  = idx >> 17;
    const int x0 = xg * 4;
    const int y0 = yg * 2;

    float w[5][5];
#pragma unroll
    for (int dy = 0; dy < 5; dy++)
#pragma unroll
        for (int dx = 0; dx < 5; dx++)
            w[dy][dx] = Wl[(dy * 5 + dx) * 256 + c];

    const float bias = bl[c];
    float acc[2][4];
#pragma unroll
    for (int uy = 0; uy < 2; uy++)
#pragma unroll
        for (int ux = 0; ux < 4; ux++) acc[uy][ux] = bias;

#pragma unroll
    for (int ry = 0; ry < 6; ry++) {
        const int yy = y0 + ry - 2;
        if (yy < 0 || yy > 63) continue;
        const __half* vrow = V + (size_t)(((b << 6) + yy) << 6) * 256 + c;
#pragma unroll
        for (int e = 0; e < 8; e++) {
            const int xx = x0 - 2 + e;
            if (xx < 0 || xx > 63) continue;
            const float val = __half2float(vrow[(size_t)xx * 256]);
#pragma unroll
            for (int uy = 0; uy < 2; uy++) {
                const int dyi = ry - uy;
                if (dyi < 0 || dyi > 4) continue;
#pragma unroll
                for (int ux = 0; ux < 4; ux++) {
                    const int dxi = e - ux;
                    if (dxi >= 0 && dxi < 5) acc[uy][ux] += val * w[dyi][dxi];
                }
            }
        }
    }

#pragma unroll
    for (int uy = 0; uy < 2; uy++) {
        __half* orow = out + (size_t)((((b << 6) + y0 + uy) << 6) + x0) * 256 + c;
#pragma unroll
        for (int ux = 0; ux < 4; ux++)
            orow[(size_t)ux * 256] = __float2half_rn(acc[uy][ux]);
    }
}

// ---------------------------------------------------------------------------
// fp16 HMMA axis attention, 2 heads per block.
// Q = hi/lo fp16 (exact); K, V, P = single fp16.
// V staged in a separate cp.async group; its wait is deferred past softmax.
// FUSE=false: out -> v1 single fp16.
// FUSE=true : +LePE (fp16) -> single fp16 (out-projection A input).
// ---------------------------------------------------------------------------
#define AT_ROW   144
#define AT_TILE  (64 * AT_ROW)
#define AT_SMEM  (4 * AT_TILE)        // Qh, Ql, K, V

template <bool FUSE>
__global__ __launch_bounds__(256)
void attn_f16(const __half* __restrict__ Qh, const __half* __restrict__ Ql,
              const __half* __restrict__ K, const __half* __restrict__ V,
              const float* __restrict__ mask,
              const __half* __restrict__ lepe,
              __half* __restrict__ O,
              int y_stride, int row_stride)
{
    extern __shared__ __align__(16) char asm_[];
    const uint32_t sm = smem_u32(asm_);
    const uint32_t sQh = sm, sQl = sm + AT_TILE;
    const uint32_t sK  = sm + 2 * AT_TILE, sV = sm + 3 * AT_TILE;

    const int np = blockIdx.x;
    const int y  = blockIdx.y;
    const int b  = blockIdx.z;
    const int tid  = threadIdx.x;
    const int lane = tid & 31;
    const int wg   = tid >> 7;
    const int w    = (tid >> 5) & 3;
    const int gid  = lane >> 2;
    const int tig  = lane & 3;
    const int n    = np * 2 + wg;
    const int hb   = wg * 64;

    const size_t base = (size_t)b * (64 * 64 * 256) + (size_t)y * y_stride
                        + np * 64;

    // Group 0: Q hi/lo + K.  Group 1: V (wait deferred past softmax).
#pragma unroll
    for (int i = tid; i < 512; i += 256) {
        const int r = i >> 3, c8 = (i & 7) * 8;
        const size_t g = base + (size_t)r * row_stride + c8;
        const uint32_t so = (uint32_t)(r * AT_ROW + c8 * 2);
        cpa16(sQh + so, Qh + g);
        cpa16(sQl + so, Ql + g);
        cpa16(sK  + so, K  + g);
    }
    asm volatile("cp.async.commit_group;" ::: "memory");
#pragma unroll
    for (int i = tid; i < 512; i += 256) {
        const int r = i >> 3, c8 = (i & 7) * 8;
        const size_t g = base + (size_t)r * row_stride + c8;
        const uint32_t so = (uint32_t)(r * AT_ROW + c8 * 2);
        cpa16(sV + so, V + g);
    }
    asm volatile("cp.async.commit_group;" ::: "memory");
    asm volatile("cp.async.wait_group 1;" ::: "memory");
    __syncthreads();

    uint32_t qh[2][4], ql[2][4];
    {
        const int arow = 16 * w + (lane & 15);
        const int acol = (lane >> 4) << 3;
#pragma unroll
        for (int kc = 0; kc < 2; kc++) {
            const uint32_t off = (uint32_t)(arow * AT_ROW + hb
                                            + (kc * 16 + acol) * 2);
            ldm_x4(qh[kc], sQh + off);
            ldm_x4(ql[kc], sQl + off);
        }
    }

    float sacc[8][4];
#pragma unroll
    for (int j = 0; j < 8; j++)
#pragma unroll
        for (int t = 0; t < 4; t++) sacc[j][t] = 0.f;

    {
        const int krow = ((lane >> 4) & 1) * 8 + (lane & 7);
        const int kcol = ((lane >> 3) & 1) * 8;
#pragma unroll
        for (int kc = 0; kc < 2; kc++)
#pragma unroll
            for (int jp = 0; jp < 4; jp++) {
                uint32_t kv[4];
                const uint32_t off = (uint32_t)((16 * jp + krow) * AT_ROW + hb
                                                + (kc * 16 + kcol) * 2);
                ldm_x4(kv, sK + off);
#pragma unroll
                for (int jj = 0; jj < 2; jj++) {
                    const int j = jp * 2 + jj;
                    mma_f16(sacc[j], qh[kc], kv[jj * 2], kv[jj * 2 + 1]);
                    mma_f16(sacc[j], ql[kc], kv[jj * 2], kv[jj * 2 + 1]);
                }
            }
    }

    const int r0 = 16 * w + gid;
    const int r1 = r0 + 8;
    const float* mbase = mask + (size_t)n * 4096;
    float mx0 = -1e30f, mx1 = -1e30f;
#pragma unroll
    for (int j = 0; j < 8; j++) {
        const float2 m0 = *(const float2*)(mbase + r0 * 64 + j * 8 + tig * 2);
        const float2 m1 = *(const float2*)(mbase + r1 * 64 + j * 8 + tig * 2);
        sacc[j][0] += m0.x; sacc[j][1] += m0.y;
        sacc[j][2] += m1.x; sacc[j][3] += m1.y;
        mx0 = fmaxf(mx0, fmaxf(sacc[j][0], sacc[j][1]));
        mx1 = fmaxf(mx1, fmaxf(sacc[j][2], sacc[j][3]));
    }
    mx0 = fmaxf(mx0, __shfl_xor_sync(0xffffffffu, mx0, 1));
    mx0 = fmaxf(mx0, __shfl_xor_sync(0xffffffffu, mx0, 2));
    mx1 = fmaxf(mx1, __shfl_xor_sync(0xffffffffu, mx1, 1));
    mx1 = fmaxf(mx1, __shfl_xor_sync(0xffffffffu, mx1, 2));

    float sum0 = 0.f, sum1 = 0.f;
#pragma unroll
    for (int j = 0; j < 8; j++) {
        sacc[j][0] = __expf(sacc[j][0] - mx0);
        sacc[j][1] = __expf(sacc[j][1] - mx0);
        sacc[j][2] = __expf(sacc[j][2] - mx1);
        sacc[j][3] = __expf(sacc[j][3] - mx1);
        sum0 += sacc[j][0] + sacc[j][1];
        sum1 += sacc[j][2] + sacc[j][3];
    }
    sum0 += __shfl_xor_sync(0xffffffffu, sum0, 1);
    sum0 += __shfl_xor_sync(0xffffffffu, sum0, 2);
    sum1 += __shfl_xor_sync(0xffffffffu, sum1, 1);
    sum1 += __shfl_xor_sync(0xffffffffu, sum1, 2);
    const float inv0 = 1.f / sum0;
    const float inv1 = 1.f / sum1;

    // Repack P (unnormalized, in (0,1]) into single-fp16 A-fragments.
    uint32_t ph[4][4];
#pragma unroll
    for (int kc = 0; kc < 4; kc++) {
        const int t0 = 2 * kc, t1 = 2 * kc + 1;
        ph[kc][0] = pack_h(sacc[t0][0], sacc[t0][1]);
        ph[kc][1] = pack_h(sacc[t0][2], sacc[t0][3]);
        ph[kc][2] = pack_h(sacc[t1][0], sacc[t1][1]);
        ph[kc][3] = pack_h(sacc[t1][2], sacc[t1][3]);
    }

    // V must be resident now.
    asm volatile("cp.async.wait_group 0;" ::: "memory");
    __syncthreads();

    float oacc[4][4];
#pragma unroll
    for (int jd = 0; jd < 4; jd++)
#pragma unroll
        for (int t = 0; t < 4; t++) oacc[jd][t] = 0.f;

    {
        const int vrow = lane & 15;
#pragma unroll
        for (int kc = 0; kc < 4; kc++)
#pragma unroll
            for (int jd = 0; jd < 4; jd++) {
                uint32_t vv[2];
                const uint32_t off = (uint32_t)((16 * kc + vrow) * AT_ROW + hb
                                                + jd * 16);
                ldm_x2t(vv, sV + off);
                mma_f16(oacc[jd], ph[kc], vv[0], vv[1]);
            }
    }

#pragma unroll
    for (int jd = 0; jd < 4; jd++) {
        float x0 = oacc[jd][0] * inv0, x1 = oacc[jd][1] * inv0;
        float y0 = oacc[jd][2] * inv1, y1 = oacc[jd][3] * inv1;
        const int d = wg * 32 + jd * 8 + tig * 2;
        const size_t o0 = base + (size_t)r0 * row_stride + d;
        const size_t o1 = base + (size_t)r1 * row_stride + d;
        if (FUSE) {
            const __half2 lp0 = *(const __half2*)(lepe + o0);
            const __half2 lp1 = *(const __half2*)(lepe + o1);
            const float2 f0 = __half22float2(lp0);
            const float2 f1 = __half22float2(lp1);
            x0 += f0.x; x1 += f0.y;
            y0 += f1.x; y1 += f1.y;
        }
        *(uint32_t*)(O + o0) = pack_h(x0, x1);
        *(uint32_t*)(O + o1) = pack_h(y0, y1);
    }
}

// ---------------------------------------------------------------------------
extern "C" void kernel_launch(void* const* d_in, const int* in_sizes, int n_in,
                              void* d_out, int out_size)
{
    const float* x      = (const float*)d_in[0];
    const float* mask_h = (const float*)d_in[1];
    const float* mask_w = (const float*)d_in[2];
    const float* Wq = (const float*)d_in[3];
    const float* bq = (const float*)d_in[4];
    const float* Wk = (const float*)d_in[5];
    const float* bk = (const float*)d_in[6];
    const float* Wv = (const float*)d_in[7];
    const float* bv = (const float*)d_in[8];
    const float* Wl = (const float*)d_in[9];
    const float* bl = (const float*)d_in[10];
    const float* Wo = (const float*)d_in[11];
    const float* bo = (const float*)d_in[12];
    float* out = (float*)d_out;

    __half *lepe, *xh, *ah, *wh, *qh, *ql, *kk, *vv, *v1;
    cudaGetSymbolAddress((void**)&lepe, g_lepe);
    cudaGetSymbolAddress((void**)&xh,   g_xh);
    cudaGetSymbolAddress((void**)&ah,   g_ah);
    cudaGetSymbolAddress((void**)&wh,   g_wh);
    cudaGetSymbolAddress((void**)&qh,   g_qh);
    cudaGetSymbolAddress((void**)&ql,   g_ql);
    cudaGetSymbolAddress((void**)&kk,   g_k);
    cudaGetSymbolAddress((void**)&vv,   g_vh);
    cudaGetSymbolAddress((void**)&v1,   g_v1);

    static int smem_set = 0;
    if (!smem_set) {
        cudaFuncSetAttribute(gemm_qkv,
                             cudaFuncAttributeMaxDynamicSharedMemorySize,
                             GEMM_SMEM);
        cudaFuncSetAttribute(gemm_out,
                             cudaFuncAttributeMaxDynamicSharedMemorySize,
                             GEMM_SMEM);
        cudaFuncSetAttribute(attn_f16<false>,
                             cudaFuncAttributeMaxDynamicSharedMemorySize,
                             AT_SMEM);
        cudaFuncSetAttribute(attn_f16<true>,
                             cudaFuncAttributeMaxDynamicSharedMemorySize,
                             AT_SMEM);
        smem_set = 1;
    }

    const float scaling = 0.17677669529663687f;  // 32^-0.5

    // 1) Conversions (x -> fp16; W -> fp16).
    split_all<<<8448, 256>>>(x, Wq, Wk, Wv, Wo, xh, wh);

    // 2) QKV projection: q fp16 hi/lo; k, v fp16.
    gemm_qkv<<<dim3(1, 256, 3), 512, GEMM_SMEM>>>(
        xh, wh, bq, bk, bv, qh, ql, kk, vv, scaling);

    // 3) LePE on fp16 v.
    lepe_kernel<<<ELEMS / 8 / 256, 256>>>(vv, Wl, bl, lepe);

    dim3 attn_grid(4, 64, 8);
    // 4) Width-axis attention -> v1 (fp16).
    attn_f16<false><<<attn_grid, 256, AT_SMEM>>>(
        qh, ql, kk, vv, mask_w, nullptr, v1,
        /*y_stride=*/64 * 256, /*row_stride=*/256);
    // 5) Height-axis attention (V = v1) + LePE -> fp16 out-proj input.
    attn_f16<true><<<attn_grid, 256, AT_SMEM>>>(
        qh, ql, kk, v1, mask_h, lepe, ah,
        /*y_stride=*/256, /*row_stride=*/64 * 256);

    // 6) Output projection (fp32 out).
    gemm_out<<<dim3(1, 256, 1), 512, GEMM_SMEM>>>(
        ah, wh + 3 * 65536, bo, out);
}